// round 1
// baseline (speedup 1.0000x reference)
#include <cuda_runtime.h>
#include <math.h>

#define Bb    8
#define Cc    256
#define Ltot  4096
#define NC    4
#define DM    64
#define DS    16
#define DCONV 4
#define DI    128
#define Nseq  32            // NC * Bb
#define Mrow  (Nseq*Ltot)   // 131072
#define M2    (Bb*Ltot)     // 32768
#define OUTD  256

// ---------------- scratch (global, static) ----------------
__device__ float g_xn   [Nseq*Ltot*DM];    // normalized input, chunk layout [n][l][64]
__device__ float g_xin  [Nseq*Ltot*DI];    // in_proj first half
__device__ float g_z    [Nseq*Ltot*DI];    // in_proj second half (gate)
__device__ float g_xc   [Nseq*Ltot*DI];    // conv+silu output
__device__ float g_delta[Nseq*Ltot*DI];
__device__ float g_Bm   [Nseq*Ltot*DS];
__device__ float g_Cm   [Nseq*Ltot*DS];
__device__ float g_ys   [Nseq*Ltot*DI];    // scan output
__device__ float g_ym   [Nseq*Ltot*DM];    // after out_proj + residual
__device__ float g_x2   [Bb*Ltot*Cc];      // after LN2, [b][l][256]
__device__ float g_wx   [160*DI];          // fused xproj weights: [0:128]=W_delta, [128:160]=B/C rows

// ---------------- kernel 0: prep fused xproj weights ----------------
__global__ void k_prep(const float* __restrict__ dtw, const float* __restrict__ xpw) {
    int idx = blockIdx.x * blockDim.x + threadIdx.x;
    if (idx < 128 * 128) {
        int o = idx >> 7, k = idx & 127;
        float s = 0.f;
        #pragma unroll
        for (int r = 0; r < 4; r++) s += dtw[o * 4 + r] * xpw[r * 128 + k];
        g_wx[idx] = s;
    } else if (idx < 160 * 128) {
        int r = (idx >> 7) - 128;   // 0..31 -> xpw rows 4..35
        int k = idx & 127;
        g_wx[idx] = xpw[(4 + r) * 128 + k];
    }
}

// ---------------- kernel 1: LN over C + chunk rearrange ----------------
// one warp per (b,l) position
__global__ void k_ln1(const float* __restrict__ x, const float* __restrict__ g,
                      const float* __restrict__ bta) {
    int warp = (blockIdx.x * blockDim.x + threadIdx.x) >> 5;
    int lane = threadIdx.x & 31;
    int bb = warp >> 12, l = warp & 4095;
    const float* xp = x + (size_t)bb * Cc * Ltot + l;
    float v[8]; float s = 0.f, s2 = 0.f;
    #pragma unroll
    for (int k = 0; k < 8; k++) {
        float t = xp[(size_t)(lane + 32 * k) * Ltot];
        v[k] = t; s += t; s2 += t * t;
    }
    #pragma unroll
    for (int o = 16; o; o >>= 1) {
        s  += __shfl_xor_sync(0xffffffffu, s, o);
        s2 += __shfl_xor_sync(0xffffffffu, s2, o);
    }
    float mu = s * (1.f / 256.f);
    float var = s2 * (1.f / 256.f) - mu * mu;
    float rs = rsqrtf(var + 1e-5f);
    #pragma unroll
    for (int k = 0; k < 8; k++) {
        int c = lane + 32 * k;
        float xn = (v[k] - mu) * rs * g[c] + bta[c];
        int chunk = c >> 6, dm = c & 63;
        g_xn[((chunk * 8 + bb) * Ltot + l) * 64 + dm] = xn;
    }
}

// ---------------- kernel 2: in_proj GEMM (M=131072, N=256, K=64) ----------------
__global__ void k_inproj(const float* __restrict__ W) {  // W: 256 x 64
    __shared__ float sA[32][65];
    __shared__ float sB[32][65];
    int m0 = blockIdx.x * 64;
    int n0 = blockIdx.y * 64;
    int tid = threadIdx.x;
    int tx = tid & 15, ty = tid >> 4;
    float acc[4][4] = {};
    for (int k0 = 0; k0 < 64; k0 += 32) {
        #pragma unroll
        for (int i = 0; i < 8; i++) {
            int idx = i * 256 + tid;
            int m = idx >> 5, k = idx & 31;
            sA[k][m] = g_xn[(m0 + m) * 64 + k0 + k];
            sB[k][m] = W[(n0 + m) * 64 + k0 + k];
        }
        __syncthreads();
        #pragma unroll
        for (int k = 0; k < 32; k++) {
            float a[4], bv[4];
            #pragma unroll
            for (int i = 0; i < 4; i++) a[i] = sA[k][tx + 16 * i];
            #pragma unroll
            for (int j = 0; j < 4; j++) bv[j] = sB[k][ty + 16 * j];
            #pragma unroll
            for (int i = 0; i < 4; i++)
                #pragma unroll
                for (int j = 0; j < 4; j++) acc[i][j] += a[i] * bv[j];
        }
        __syncthreads();
    }
    #pragma unroll
    for (int i = 0; i < 4; i++) {
        int m = m0 + tx + 16 * i;
        #pragma unroll
        for (int j = 0; j < 4; j++) {
            int n = n0 + ty + 16 * j;
            if (n < 128) g_xin[m * 128 + n] = acc[i][j];
            else         g_z[m * 128 + n - 128] = acc[i][j];
        }
    }
}

// ---------------- kernel 3: depthwise causal conv + silu ----------------
__global__ void k_conv(const float* __restrict__ cw, const float* __restrict__ cb) {
    int idx = blockIdx.x * blockDim.x + threadIdx.x;   // over Nseq*Ltot*DI
    int d = idx & 127;
    int row = idx >> 7;
    int l = row & 4095;
    float s = cb[d];
    #pragma unroll
    for (int k = 0; k < 4; k++) {
        int ll = l - 3 + k;
        if (ll >= 0) s += cw[d * 4 + k] * g_xin[(row - 3 + k) * 128 + d];
    }
    float sig = 1.f / (1.f + __expf(-s));
    g_xc[idx] = s * sig;
}

// ---------------- kernel 4: fused x_proj + dt_proj GEMM (N=160, K=128) ----------------
__global__ void k_xproj(const float* __restrict__ dtb) {
    __shared__ float sA[32][65];
    __shared__ float sB[32][33];
    int m0 = blockIdx.x * 64;
    int n0 = blockIdx.y * 32;
    int tid = threadIdx.x;
    int tx = tid & 15, ty = tid >> 4;
    float acc[4][2] = {};
    for (int k0 = 0; k0 < 128; k0 += 32) {
        #pragma unroll
        for (int i = 0; i < 8; i++) {
            int idx = i * 256 + tid;
            int m = idx >> 5, k = idx & 31;
            sA[k][m] = g_xc[(m0 + m) * 128 + k0 + k];
        }
        #pragma unroll
        for (int i = 0; i < 4; i++) {
            int idx = i * 256 + tid;
            int n = idx >> 5, k = idx & 31;
            sB[k][n] = g_wx[(n0 + n) * 128 + k0 + k];
        }
        __syncthreads();
        #pragma unroll
        for (int k = 0; k < 32; k++) {
            float a[4], bv[2];
            #pragma unroll
            for (int i = 0; i < 4; i++) a[i] = sA[k][tx + 16 * i];
            #pragma unroll
            for (int j = 0; j < 2; j++) bv[j] = sB[k][ty + 16 * j];
            #pragma unroll
            for (int i = 0; i < 4; i++)
                #pragma unroll
                for (int j = 0; j < 2; j++) acc[i][j] += a[i] * bv[j];
        }
        __syncthreads();
    }
    #pragma unroll
    for (int i = 0; i < 4; i++) {
        int m = m0 + tx + 16 * i;
        #pragma unroll
        for (int j = 0; j < 2; j++) {
            int n = n0 + ty + 16 * j;
            float v = acc[i][j];
            if (n < 128) {
                float t = v + dtb[n];
                g_delta[m * 128 + n] = (t > 20.f) ? t : log1pf(expf(t));
            } else if (n < 144) {
                g_Bm[m * 16 + n - 128] = v;
            } else {
                g_Cm[m * 16 + n - 144] = v;
            }
        }
    }
}

// ---------------- kernel 5: sequential selective scan ----------------
// one 16-lane group per (n,d); lane = state index s
__global__ void k_scan(const float* __restrict__ Alog) {
    int tid = blockIdx.x * blockDim.x + threadIdx.x;
    int grp = tid >> 4;
    int s = tid & 15;
    int n = grp >> 7;
    int d = grp & 127;
    float a = -__expf(Alog[d * 16 + s]);
    const float* __restrict__ dptr = g_delta + n * Ltot * DI + d;
    const float* __restrict__ uptr = g_xc    + n * Ltot * DI + d;
    const float* __restrict__ bptr = g_Bm    + n * Ltot * DS + s;
    const float* __restrict__ cptr = g_Cm    + n * Ltot * DS + s;
    float* __restrict__ yptr = g_ys + n * Ltot * DI + d;
    float h = 0.f;
    // prefetch t=0
    float dt = __ldg(dptr), u = __ldg(uptr), Bt = __ldg(bptr), Ct = __ldg(cptr);
    #pragma unroll 4
    for (int t = 0; t < Ltot; ++t) {
        float dt1 = 0.f, u1 = 0.f, B1 = 0.f, C1 = 0.f;
        if (t + 1 < Ltot) {
            dt1 = __ldg(dptr + DI); u1 = __ldg(uptr + DI);
            B1 = __ldg(bptr + DS);  C1 = __ldg(cptr + DS);
        }
        float dA = __expf(dt * a);
        h = dA * h + (dt * Bt) * u;
        float y = h * Ct;
        y += __shfl_xor_sync(0xffffffffu, y, 8);
        y += __shfl_xor_sync(0xffffffffu, y, 4);
        y += __shfl_xor_sync(0xffffffffu, y, 2);
        y += __shfl_xor_sync(0xffffffffu, y, 1);
        if (s == 0) *yptr = y;
        dptr += DI; uptr += DI; bptr += DS; cptr += DS; yptr += DI;
        dt = dt1; u = u1; Bt = B1; Ct = C1;
    }
}

// ---------------- kernel 6: gate + out_proj GEMM + residual (N=64, K=128) ----------------
__global__ void k_outproj(const float* __restrict__ W,       // 64 x 128
                          const float* __restrict__ Dp,      // 128
                          const float* __restrict__ skip) {
    __shared__ float sA[32][65];
    __shared__ float sB[32][65];
    int m0 = blockIdx.x * 64;
    int tid = threadIdx.x;
    int tx = tid & 15, ty = tid >> 4;
    float acc[4][4] = {};
    for (int k0 = 0; k0 < 128; k0 += 32) {
        #pragma unroll
        for (int i = 0; i < 8; i++) {
            int idx = i * 256 + tid;
            int m = idx >> 5, k = idx & 31;
            int gi = (m0 + m) * 128 + k0 + k;
            float ys = g_ys[gi];
            float xc = g_xc[gi];
            float zz = g_z[gi];
            float sig = 1.f / (1.f + __expf(-zz));
            sA[k][m] = (ys + xc * Dp[k0 + k]) * (zz * sig);
            if (i < 4) {  // B tile 64 rows only needs first 2048 fills, but keep symmetric: guard
            }
            sB[k][m] = (m < 64) ? W[m * 128 + k0 + k] : 0.f;
        }
        __syncthreads();
        #pragma unroll
        for (int k = 0; k < 32; k++) {
            float a[4], bv[4];
            #pragma unroll
            for (int i = 0; i < 4; i++) a[i] = sA[k][tx + 16 * i];
            #pragma unroll
            for (int j = 0; j < 4; j++) bv[j] = sB[k][ty + 16 * j];
            #pragma unroll
            for (int i = 0; i < 4; i++)
                #pragma unroll
                for (int j = 0; j < 4; j++) acc[i][j] += a[i] * bv[j];
        }
        __syncthreads();
    }
    float sk = skip[0];
    #pragma unroll
    for (int i = 0; i < 4; i++) {
        int m = m0 + tx + 16 * i;
        #pragma unroll
        for (int j = 0; j < 4; j++) {
            int n = ty + 16 * j;
            g_ym[m * 64 + n] = acc[i][j] + sk * g_xn[m * 64 + n];
        }
    }
}

// ---------------- kernel 7: LN2 + chunk gather ----------------
__global__ void k_ln2(const float* __restrict__ g, const float* __restrict__ bta) {
    int warp = (blockIdx.x * blockDim.x + threadIdx.x) >> 5;
    int lane = threadIdx.x & 31;
    int bb = warp >> 12, l = warp & 4095;
    float v[8]; float s = 0.f, s2 = 0.f;
    #pragma unroll
    for (int k = 0; k < 8; k++) {
        int c = lane + 32 * k;
        float t = g_ym[(((c >> 6) * 8 + bb) * Ltot + l) * 64 + (c & 63)];
        v[k] = t; s += t; s2 += t * t;
    }
    #pragma unroll
    for (int o = 16; o; o >>= 1) {
        s  += __shfl_xor_sync(0xffffffffu, s, o);
        s2 += __shfl_xor_sync(0xffffffffu, s2, o);
    }
    float mu = s * (1.f / 256.f);
    float var = s2 * (1.f / 256.f) - mu * mu;
    float rs = rsqrtf(var + 1e-5f);
    #pragma unroll
    for (int k = 0; k < 8; k++) {
        int c = lane + 32 * k;
        g_x2[(bb * Ltot + l) * 256 + c] = (v[k] - mu) * rs * g[c] + bta[c];
    }
}

// ---------------- kernel 8: final proj GEMM + bias + transpose store ----------------
__global__ void k_final(const float* __restrict__ W,   // 256 x 256
                        const float* __restrict__ pb,  // 256
                        float* __restrict__ out) {
    __shared__ float sA[32][65];
    __shared__ float sB[32][65];
    int m0 = blockIdx.x * 64;
    int n0 = blockIdx.y * 64;
    int tid = threadIdx.x;
    int tx = tid & 15, ty = tid >> 4;
    float acc[4][4] = {};
    for (int k0 = 0; k0 < 256; k0 += 32) {
        #pragma unroll
        for (int i = 0; i < 8; i++) {
            int idx = i * 256 + tid;
            int m = idx >> 5, k = idx & 31;
            sA[k][m] = g_x2[(m0 + m) * 256 + k0 + k];
            sB[k][m] = W[(n0 + m) * 256 + k0 + k];
        }
        __syncthreads();
        #pragma unroll
        for (int k = 0; k < 32; k++) {
            float a[4], bv[4];
            #pragma unroll
            for (int i = 0; i < 4; i++) a[i] = sA[k][tx + 16 * i];
            #pragma unroll
            for (int j = 0; j < 4; j++) bv[j] = sB[k][ty + 16 * j];
            #pragma unroll
            for (int i = 0; i < 4; i++)
                #pragma unroll
                for (int j = 0; j < 4; j++) acc[i][j] += a[i] * bv[j];
        }
        __syncthreads();
    }
    #pragma unroll
    for (int i = 0; i < 4; i++) {
        int m = m0 + tx + 16 * i;          // row = b*4096 + l
        int bb = m >> 12, l = m & 4095;
        #pragma unroll
        for (int j = 0; j < 4; j++) {
            int n = n0 + ty + 16 * j;
            out[(bb * 256 + n) * Ltot + l] = acc[i][j] + pb[n];
        }
    }
}

// ---------------- launch ----------------
extern "C" void kernel_launch(void* const* d_in, const int* in_sizes, int n_in,
                              void* d_out, int out_size) {
    const float* x      = (const float*)d_in[0];
    const float* ln_g   = (const float*)d_in[1];
    const float* ln_b   = (const float*)d_in[2];
    const float* inpw   = (const float*)d_in[3];
    const float* convw  = (const float*)d_in[4];
    const float* convb  = (const float*)d_in[5];
    const float* xpw    = (const float*)d_in[6];
    const float* dtw    = (const float*)d_in[7];
    const float* dtb    = (const float*)d_in[8];
    const float* Alog   = (const float*)d_in[9];
    const float* Dp     = (const float*)d_in[10];
    const float* outw   = (const float*)d_in[11];
    const float* projw  = (const float*)d_in[12];
    const float* projb  = (const float*)d_in[13];
    const float* skip   = (const float*)d_in[14];
    float* out = (float*)d_out;

    k_prep<<<80, 256>>>(dtw, xpw);
    k_ln1<<<4096, 256>>>(x, ln_g, ln_b);
    {
        dim3 grid(Mrow / 64, 4);
        k_inproj<<<grid, 256>>>(inpw);
    }
    k_conv<<<(Nseq * Ltot * DI) / 256, 256>>>(convw, convb);
    {
        dim3 grid(Mrow / 64, 5);
        k_xproj<<<grid, 256>>>(dtb);
    }
    k_scan<<<(Nseq * DI * DS) / 256, 256>>>(Alog);
    {
        dim3 grid(Mrow / 64, 1);
        k_outproj<<<grid, 256>>>(outw, Dp, skip);
    }
    k_ln2<<<4096, 256>>>(ln_g, ln_b);
    {
        dim3 grid(M2 / 64, 4);
        k_final<<<grid, 256>>>(projw, projb, out);
    }
}

// round 2
// speedup vs baseline: 1.2496x; 1.2496x over previous
#include <cuda_runtime.h>
#include <math.h>

#define Bb    8
#define Cc    256
#define Ltot  4096
#define DS    16
#define DI    128
#define Nseq  32
#define Mrow  (Nseq*Ltot)   // 131072
#define M2    (Bb*Ltot)     // 32768

// ---------------- scratch ----------------
__device__ float g_xn   [Mrow*64];
__device__ float g_xin  [Mrow*DI];
__device__ float g_z    [Mrow*DI];
__device__ float g_xc   [Mrow*DI];
__device__ float g_delta[Mrow*DI];
__device__ float g_Bm   [Mrow*DS];
__device__ float g_Cm   [Mrow*DS];
__device__ float g_ys   [Mrow*DI];
__device__ float g_ym   [Mrow*64];
__device__ float g_x2   [M2*Cc];
__device__ float g_wx   [160*DI];

// ---------------- tf32 helpers ----------------
__device__ __forceinline__ uint2 splitf(float x) {
    unsigned hi; asm("cvt.rna.tf32.f32 %0,%1;" : "=r"(hi) : "f"(x));
    float r = x - __uint_as_float(hi);
    unsigned lo; asm("cvt.rna.tf32.f32 %0,%1;" : "=r"(lo) : "f"(r));
    return make_uint2(hi, lo);
}

#define MMA_OP(d,a0,a1,a2,a3,b0,b1) asm volatile( \
  "mma.sync.aligned.m16n8k8.row.col.f32.tf32.tf32.f32 {%0,%1,%2,%3},{%4,%5,%6,%7},{%8,%9},{%0,%1,%2,%3};" \
  : "+f"(d[0]),"+f"(d[1]),"+f"(d[2]),"+f"(d[3]) \
  : "r"(a0),"r"(a1),"r"(a2),"r"(a3),"r"(b0),"r"(b1))

#define SPAD 36
#define SB_OFF (128*SPAD)

// load A tile 128x32 from row-major src
__device__ __forceinline__ void loadA(uint2* sA, const float* __restrict__ src,
                                      int ld, int m0, int k0, int tid) {
    #pragma unroll
    for (int it = 0; it < 4; it++) {
        int idx = tid + it * 256;
        int row = idx >> 3, c4 = (idx & 7) * 4;
        float4 v = *(const float4*)(src + (size_t)(m0 + row) * ld + k0 + c4);
        uint2* p = sA + row * SPAD + c4;
        p[0] = splitf(v.x); p[1] = splitf(v.y); p[2] = splitf(v.z); p[3] = splitf(v.w);
    }
}
// load B tile 64x32 from row-major W [N][K], zero-fill rows >= nmax
__device__ __forceinline__ void loadB(uint2* sB, const float* __restrict__ W,
                                      int ld, int n0, int k0, int nmax, int tid) {
    #pragma unroll
    for (int it = 0; it < 2; it++) {
        int idx = tid + it * 256;
        int row = idx >> 3, c4 = (idx & 7) * 4;
        float4 v = make_float4(0.f, 0.f, 0.f, 0.f);
        if (n0 + row < nmax) v = *(const float4*)(W + (size_t)(n0 + row) * ld + k0 + c4);
        uint2* p = sB + row * SPAD + c4;
        p[0] = splitf(v.x); p[1] = splitf(v.y); p[2] = splitf(v.z); p[3] = splitf(v.w);
    }
}

// 3xTF32 mainloop over one BK=32 slab; warp tile 32x32 (2 m-tiles x 4 n-tiles)
__device__ __forceinline__ void mma_slab(const uint2* __restrict__ sA, const uint2* __restrict__ sB,
                                         float acc[2][4][4], int mb, int nb, int g, int t) {
    #pragma unroll
    for (int ks = 0; ks < 4; ks++) {
        int k = ks * 8 + t;
        unsigned ah[2][4], al[2][4];
        #pragma unroll
        for (int i = 0; i < 2; i++) {
            const uint2* p = sA + (mb + 16 * i + g) * SPAD + k;
            uint2 v0 = p[0], v1 = p[8 * SPAD], v2 = p[4], v3 = p[8 * SPAD + 4];
            ah[i][0] = v0.x; al[i][0] = v0.y;
            ah[i][1] = v1.x; al[i][1] = v1.y;
            ah[i][2] = v2.x; al[i][2] = v2.y;
            ah[i][3] = v3.x; al[i][3] = v3.y;
        }
        #pragma unroll
        for (int j = 0; j < 4; j++) {
            const uint2* p = sB + (nb + 8 * j + g) * SPAD + k;
            uint2 v0 = p[0], v1 = p[4];
            #pragma unroll
            for (int i = 0; i < 2; i++) {
                MMA_OP(acc[i][j], al[i][0], al[i][1], al[i][2], al[i][3], v0.x, v1.x); // lo*hi
                MMA_OP(acc[i][j], ah[i][0], ah[i][1], ah[i][2], ah[i][3], v0.y, v1.y); // hi*lo
                MMA_OP(acc[i][j], ah[i][0], ah[i][1], ah[i][2], ah[i][3], v0.x, v1.x); // hi*hi
            }
        }
    }
}

// ---------------- kernel 0: prep fused xproj weights ----------------
__global__ void k_prep(const float* __restrict__ dtw, const float* __restrict__ xpw) {
    int idx = blockIdx.x * blockDim.x + threadIdx.x;
    if (idx < 128 * 128) {
        int o = idx >> 7, k = idx & 127;
        float s = 0.f;
        #pragma unroll
        for (int r = 0; r < 4; r++) s += dtw[o * 4 + r] * xpw[r * 128 + k];
        g_wx[idx] = s;
    } else if (idx < 160 * 128) {
        int r = (idx >> 7) - 128;
        int k = idx & 127;
        g_wx[idx] = xpw[(4 + r) * 128 + k];
    }
}

// ---------------- kernel 1: LN1 + chunk rearrange ----------------
__global__ void k_ln1(const float* __restrict__ x, const float* __restrict__ g,
                      const float* __restrict__ bta) {
    int warp = (blockIdx.x * blockDim.x + threadIdx.x) >> 5;
    int lane = threadIdx.x & 31;
    int bb = warp >> 12, l = warp & 4095;
    const float* xp = x + (size_t)bb * Cc * Ltot + l;
    float v[8]; float s = 0.f, s2 = 0.f;
    #pragma unroll
    for (int k = 0; k < 8; k++) {
        float t = xp[(size_t)(lane + 32 * k) * Ltot];
        v[k] = t; s += t; s2 += t * t;
    }
    #pragma unroll
    for (int o = 16; o; o >>= 1) {
        s  += __shfl_xor_sync(0xffffffffu, s, o);
        s2 += __shfl_xor_sync(0xffffffffu, s2, o);
    }
    float mu = s * (1.f / 256.f);
    float var = s2 * (1.f / 256.f) - mu * mu;
    float rs = rsqrtf(var + 1e-5f);
    #pragma unroll
    for (int k = 0; k < 8; k++) {
        int c = lane + 32 * k;
        float xn = (v[k] - mu) * rs * g[c] + bta[c];
        int chunk = c >> 6, dm = c & 63;
        g_xn[(size_t)((chunk * 8 + bb) * Ltot + l) * 64 + dm] = xn;
    }
}

// ---------------- kernel 2: in_proj (M=131072, N=256, K=64) ----------------
__global__ void k_inproj(const float* __restrict__ W) {
    extern __shared__ uint2 sm[];
    uint2* sA = sm; uint2* sB = sm + SB_OFF;
    int tid = threadIdx.x;
    int m0 = blockIdx.x * 128, n0 = blockIdx.y * 64;
    int warp = tid >> 5, lane = tid & 31, g = lane >> 2, t = lane & 3;
    int mb = (warp & 3) * 32, nb = (warp >> 2) * 32;
    float acc[2][4][4] = {};
    for (int k0 = 0; k0 < 64; k0 += 32) {
        loadA(sA, g_xn, 64, m0, k0, tid);
        loadB(sB, W, 64, n0, k0, 256, tid);
        __syncthreads();
        mma_slab(sA, sB, acc, mb, nb, g, t);
        __syncthreads();
    }
    float* dst = (blockIdx.y < 2) ? g_xin : g_z;
    int nbase = n0 - ((blockIdx.y < 2) ? 0 : 128) + nb;
    #pragma unroll
    for (int i = 0; i < 2; i++) {
        int row = m0 + mb + 16 * i + g;
        #pragma unroll
        for (int j = 0; j < 4; j++) {
            int col = nbase + 8 * j + 2 * t;
            *(float2*)(dst + (size_t)row * 128 + col)       = make_float2(acc[i][j][0], acc[i][j][1]);
            *(float2*)(dst + (size_t)(row + 8) * 128 + col) = make_float2(acc[i][j][2], acc[i][j][3]);
        }
    }
}

// ---------------- kernel 3: depthwise causal conv + silu ----------------
__global__ void k_conv(const float* __restrict__ cw, const float* __restrict__ cb) {
    int d = threadIdx.x;                 // 0..127
    int blk = blockIdx.x;
    int n = blk >> 9;                    // 512 blocks per sequence
    int l0 = (blk & 511) * 8;
    const float* src = g_xin + (size_t)n * Ltot * DI + d;
    float w0 = cw[d*4], w1 = cw[d*4+1], w2 = cw[d*4+2], w3 = cw[d*4+3], b = cb[d];
    float x0 = (l0 >= 3) ? src[(size_t)(l0 - 3) * DI] : 0.f;
    float x1 = (l0 >= 2) ? src[(size_t)(l0 - 2) * DI] : 0.f;
    float x2 = (l0 >= 1) ? src[(size_t)(l0 - 1) * DI] : 0.f;
    float* dst = g_xc + (size_t)n * Ltot * DI + d;
    #pragma unroll
    for (int i = 0; i < 8; i++) {
        float x3 = src[(size_t)(l0 + i) * DI];
        float s = b + w0 * x0 + w1 * x1 + w2 * x2 + w3 * x3;
        float sg = 1.f / (1.f + __expf(-s));
        dst[(size_t)(l0 + i) * DI] = s * sg;
        x0 = x1; x1 = x2; x2 = x3;
    }
}

// ---------------- kernel 4: fused x_proj+dt_proj (N=160, K=128) ----------------
__global__ void k_xproj(const float* __restrict__ dtb) {
    extern __shared__ uint2 sm[];
    uint2* sA = sm; uint2* sB = sm + SB_OFF;
    int tid = threadIdx.x;
    int m0 = blockIdx.x * 128, n0 = blockIdx.y * 64;
    int warp = tid >> 5, lane = tid & 31, g = lane >> 2, t = lane & 3;
    int mb = (warp & 3) * 32, nb = (warp >> 2) * 32;
    float acc[2][4][4] = {};
    for (int k0 = 0; k0 < 128; k0 += 32) {
        loadA(sA, g_xc, 128, m0, k0, tid);
        loadB(sB, g_wx, 128, n0, k0, 160, tid);
        __syncthreads();
        mma_slab(sA, sB, acc, mb, nb, g, t);
        __syncthreads();
    }
    if (blockIdx.y < 2) {
        #pragma unroll
        for (int i = 0; i < 2; i++) {
            int row = m0 + mb + 16 * i + g;
            #pragma unroll
            for (int j = 0; j < 4; j++) {
                int col = n0 + nb + 8 * j + 2 * t;
                float b0 = dtb[col], b1 = dtb[col + 1];
                float t0 = acc[i][j][0] + b0, t1 = acc[i][j][1] + b1;
                float t2 = acc[i][j][2] + b0, t3 = acc[i][j][3] + b1;
                float s0 = (t0 > 20.f) ? t0 : log1pf(__expf(t0));
                float s1 = (t1 > 20.f) ? t1 : log1pf(__expf(t1));
                float s2 = (t2 > 20.f) ? t2 : log1pf(__expf(t2));
                float s3 = (t3 > 20.f) ? t3 : log1pf(__expf(t3));
                *(float2*)(g_delta + (size_t)row * 128 + col)       = make_float2(s0, s1);
                *(float2*)(g_delta + (size_t)(row + 8) * 128 + col) = make_float2(s2, s3);
            }
        }
    } else if (nb == 0) {
        #pragma unroll
        for (int i = 0; i < 2; i++) {
            int row = m0 + mb + 16 * i + g;
            #pragma unroll
            for (int j = 0; j < 4; j++) {
                int cl = 8 * j + 2 * t;   // 0..31
                float* dst = (cl < 16) ? g_Bm : g_Cm;
                int c = cl & 15;
                *(float2*)(dst + (size_t)row * 16 + c)       = make_float2(acc[i][j][0], acc[i][j][1]);
                *(float2*)(dst + (size_t)(row + 8) * 16 + c) = make_float2(acc[i][j][2], acc[i][j][3]);
            }
        }
    }
}

// ---------------- kernel 5: sequential selective scan ----------------
__global__ void k_scan(const float* __restrict__ Alog) {
    int tid = blockIdx.x * blockDim.x + threadIdx.x;
    int grp = tid >> 4;
    int s = tid & 15;
    int n = grp >> 7;
    int d = grp & 127;
    float a = -__expf(Alog[d * 16 + s]);
    const float* __restrict__ dptr = g_delta + (size_t)n * Ltot * DI + d;
    const float* __restrict__ uptr = g_xc    + (size_t)n * Ltot * DI + d;
    const float* __restrict__ bptr = g_Bm    + (size_t)n * Ltot * DS + s;
    const float* __restrict__ cptr = g_Cm    + (size_t)n * Ltot * DS + s;
    float* __restrict__ yptr = g_ys + (size_t)n * Ltot * DI + d;
    float h = 0.f;
    float dt = __ldg(dptr), u = __ldg(uptr), Bt = __ldg(bptr), Ct = __ldg(cptr);
    #pragma unroll 4
    for (int t = 0; t < Ltot; ++t) {
        float dt1 = 0.f, u1 = 0.f, B1 = 0.f, C1 = 0.f;
        if (t + 1 < Ltot) {
            dt1 = __ldg(dptr + DI); u1 = __ldg(uptr + DI);
            B1 = __ldg(bptr + DS);  C1 = __ldg(cptr + DS);
        }
        float dA = __expf(dt * a);
        h = dA * h + (dt * Bt) * u;
        float y = h * Ct;
        y += __shfl_xor_sync(0xffffffffu, y, 8);
        y += __shfl_xor_sync(0xffffffffu, y, 4);
        y += __shfl_xor_sync(0xffffffffu, y, 2);
        y += __shfl_xor_sync(0xffffffffu, y, 1);
        if (s == 0) *yptr = y;
        dptr += DI; uptr += DI; bptr += DS; cptr += DS; yptr += DI;
        dt = dt1; u = u1; Bt = B1; Ct = C1;
    }
}

// ---------------- kernel 6: gate + out_proj + residual (N=64, K=128) ----------------
__global__ void k_outproj(const float* __restrict__ W, const float* __restrict__ Dp,
                          const float* __restrict__ skip) {
    extern __shared__ uint2 sm[];
    uint2* sA = sm; uint2* sB = sm + SB_OFF;
    int tid = threadIdx.x;
    int m0 = blockIdx.x * 128;
    int warp = tid >> 5, lane = tid & 31, g = lane >> 2, t = lane & 3;
    int mb = (warp & 3) * 32, nb = (warp >> 2) * 32;
    float acc[2][4][4] = {};
    for (int k0 = 0; k0 < 128; k0 += 32) {
        // fused A prologue: (ys + xc*D) * silu(z)
        #pragma unroll
        for (int it = 0; it < 4; it++) {
            int idx = tid + it * 256;
            int row = idx >> 3, c4 = (idx & 7) * 4;
            size_t off = (size_t)(m0 + row) * 128 + k0 + c4;
            float4 ys = *(const float4*)(g_ys + off);
            float4 xc = *(const float4*)(g_xc + off);
            float4 zz = *(const float4*)(g_z + off);
            float4 dp = *(const float4*)(Dp + k0 + c4);
            float a0 = (ys.x + xc.x * dp.x) * (zz.x / (1.f + __expf(-zz.x)));
            float a1 = (ys.y + xc.y * dp.y) * (zz.y / (1.f + __expf(-zz.y)));
            float a2 = (ys.z + xc.z * dp.z) * (zz.z / (1.f + __expf(-zz.z)));
            float a3 = (ys.w + xc.w * dp.w) * (zz.w / (1.f + __expf(-zz.w)));
            uint2* p = sA + row * SPAD + c4;
            p[0] = splitf(a0); p[1] = splitf(a1); p[2] = splitf(a2); p[3] = splitf(a3);
        }
        loadB(sB, W, 128, 0, k0, 64, tid);
        __syncthreads();
        mma_slab(sA, sB, acc, mb, nb, g, t);
        __syncthreads();
    }
    float sk = skip[0];
    #pragma unroll
    for (int i = 0; i < 2; i++) {
        int row = m0 + mb + 16 * i + g;
        #pragma unroll
        for (int j = 0; j < 4; j++) {
            int col = nb + 8 * j + 2 * t;   // 0..63
            float2 xa = *(const float2*)(g_xn + (size_t)row * 64 + col);
            float2 xb = *(const float2*)(g_xn + (size_t)(row + 8) * 64 + col);
            *(float2*)(g_ym + (size_t)row * 64 + col) =
                make_float2(acc[i][j][0] + sk * xa.x, acc[i][j][1] + sk * xa.y);
            *(float2*)(g_ym + (size_t)(row + 8) * 64 + col) =
                make_float2(acc[i][j][2] + sk * xb.x, acc[i][j][3] + sk * xb.y);
        }
    }
}

// ---------------- kernel 7: LN2 + chunk gather ----------------
__global__ void k_ln2(const float* __restrict__ g, const float* __restrict__ bta) {
    int warp = (blockIdx.x * blockDim.x + threadIdx.x) >> 5;
    int lane = threadIdx.x & 31;
    int bb = warp >> 12, l = warp & 4095;
    float v[8]; float s = 0.f, s2 = 0.f;
    #pragma unroll
    for (int k = 0; k < 8; k++) {
        int c = lane + 32 * k;
        float t = g_ym[(size_t)(((c >> 6) * 8 + bb) * Ltot + l) * 64 + (c & 63)];
        v[k] = t; s += t; s2 += t * t;
    }
    #pragma unroll
    for (int o = 16; o; o >>= 1) {
        s  += __shfl_xor_sync(0xffffffffu, s, o);
        s2 += __shfl_xor_sync(0xffffffffu, s2, o);
    }
    float mu = s * (1.f / 256.f);
    float var = s2 * (1.f / 256.f) - mu * mu;
    float rs = rsqrtf(var + 1e-5f);
    #pragma unroll
    for (int k = 0; k < 8; k++) {
        int c = lane + 32 * k;
        g_x2[(size_t)(bb * Ltot + l) * 256 + c] = (v[k] - mu) * rs * g[c] + bta[c];
    }
}

// ---------------- kernel 8: final proj (M=32768, N=256, K=256) + transpose ----------------
__global__ void k_final(const float* __restrict__ W, const float* __restrict__ pb,
                        float* __restrict__ out) {
    extern __shared__ uint2 sm[];
    uint2* sA = sm; uint2* sB = sm + SB_OFF;
    int tid = threadIdx.x;
    int m0 = blockIdx.x * 128, n0 = blockIdx.y * 64;
    int warp = tid >> 5, lane = tid & 31, g = lane >> 2, t = lane & 3;
    int mb = (warp & 3) * 32, nb = (warp >> 2) * 32;
    float acc[2][4][4] = {};
    for (int k0 = 0; k0 < 256; k0 += 32) {
        loadA(sA, g_x2, 256, m0, k0, tid);
        loadB(sB, W, 256, n0, k0, 256, tid);
        __syncthreads();
        mma_slab(sA, sB, acc, mb, nb, g, t);
        __syncthreads();
    }
    #pragma unroll
    for (int i = 0; i < 2; i++) {
        int row = m0 + mb + 16 * i + g;
        int bbat = row >> 12, l = row & 4095;
        int row2 = row + 8;
        int l2 = row2 & 4095;
        #pragma unroll
        for (int j = 0; j < 4; j++) {
            int col = n0 + nb + 8 * j + 2 * t;
            out[(size_t)(bbat * 256 + col) * Ltot + l]      = acc[i][j][0] + pb[col];
            out[(size_t)(bbat * 256 + col + 1) * Ltot + l]  = acc[i][j][1] + pb[col + 1];
            out[(size_t)(bbat * 256 + col) * Ltot + l2]     = acc[i][j][2] + pb[col];
            out[(size_t)(bbat * 256 + col + 1) * Ltot + l2] = acc[i][j][3] + pb[col + 1];
        }
    }
}

// ---------------- launch ----------------
extern "C" void kernel_launch(void* const* d_in, const int* in_sizes, int n_in,
                              void* d_out, int out_size) {
    const float* x      = (const float*)d_in[0];
    const float* ln_g   = (const float*)d_in[1];
    const float* ln_b   = (const float*)d_in[2];
    const float* inpw   = (const float*)d_in[3];
    const float* convw  = (const float*)d_in[4];
    const float* convb  = (const float*)d_in[5];
    const float* xpw    = (const float*)d_in[6];
    const float* dtw    = (const float*)d_in[7];
    const float* dtb    = (const float*)d_in[8];
    const float* Alog   = (const float*)d_in[9];
    const float* Dp     = (const float*)d_in[10];
    const float* outw   = (const float*)d_in[11];
    const float* projw  = (const float*)d_in[12];
    const float* projb  = (const float*)d_in[13];
    const float* skip   = (const float*)d_in[14];
    float* out = (float*)d_out;

    const int SMEM_BYTES = (128 * SPAD + 64 * SPAD) * (int)sizeof(uint2);  // 55296
    cudaFuncSetAttribute(k_inproj,  cudaFuncAttributeMaxDynamicSharedMemorySize, SMEM_BYTES);
    cudaFuncSetAttribute(k_xproj,   cudaFuncAttributeMaxDynamicSharedMemorySize, SMEM_BYTES);
    cudaFuncSetAttribute(k_outproj, cudaFuncAttributeMaxDynamicSharedMemorySize, SMEM_BYTES);
    cudaFuncSetAttribute(k_final,   cudaFuncAttributeMaxDynamicSharedMemorySize, SMEM_BYTES);

    k_prep<<<80, 256>>>(dtw, xpw);
    k_ln1<<<4096, 256>>>(x, ln_g, ln_b);
    k_inproj<<<dim3(1024, 4), 256, SMEM_BYTES>>>(inpw);
    k_conv<<<16384, 128>>>(convw, convb);
    k_xproj<<<dim3(1024, 3), 256, SMEM_BYTES>>>(dtb);
    k_scan<<<(Nseq * DI * DS) / 256, 256>>>(Alog);
    k_outproj<<<dim3(1024, 1), 256, SMEM_BYTES>>>(outw, Dp, skip);
    k_ln2<<<4096, 256>>>(ln_g, ln_b);
    k_final<<<dim3(256, 4), 256, SMEM_BYTES>>>(projw, projb, out);
}

// round 3
// speedup vs baseline: 1.3272x; 1.0621x over previous
#include <cuda_runtime.h>
#include <math.h>

#define Bb    8
#define Cc    256
#define Ltot  4096
#define DS    16
#define DI    128
#define Nseq  32
#define Mrow  (Nseq*Ltot)   // 131072
#define M2    (Bb*Ltot)     // 32768

// ---------------- fp32 scratch ----------------
__device__ float g_xin  [Mrow*DI];
__device__ float g_z    [Mrow*DI];
__device__ float g_xc   [Mrow*DI];
__device__ float g_delta[Mrow*DI];
__device__ float g_Bm   [Mrow*DS];
__device__ float g_Cm   [Mrow*DS];
__device__ float g_ys   [Mrow*DI];
__device__ float g_ym   [Mrow*64];

// ---------------- bf16 hi/lo planes (1 uint = 2 bf16 along K) ----------------
__device__ unsigned g_xn_h[Mrow*32], g_xn_l[Mrow*32];
__device__ unsigned g_xc_h[Mrow*64], g_xc_l[Mrow*64];
__device__ unsigned g_x2_h[M2*128],  g_x2_l[M2*128];
__device__ unsigned g_wi_h[256*32],  g_wi_l[256*32];
__device__ unsigned g_wx_h[160*64],  g_wx_l[160*64];
__device__ unsigned g_wo_h[64*64],   g_wo_l[64*64];
__device__ unsigned g_wp_h[256*128], g_wp_l[256*128];

// ---------------- split / reconstruct helpers ----------------
__device__ __forceinline__ void split2(float x0, float x1, unsigned &h2, unsigned &l2) {
    asm("cvt.rn.bf16x2.f32 %0,%1,%2;" : "=r"(h2) : "f"(x1), "f"(x0));
    float hf0 = __uint_as_float(h2 << 16);
    float hf1 = __uint_as_float(h2 & 0xffff0000u);
    asm("cvt.rn.bf16x2.f32 %0,%1,%2;" : "=r"(l2) : "f"(x1 - hf1), "f"(x0 - hf0));
}
__device__ __forceinline__ float2 rec2(unsigned h2, unsigned l2) {
    return make_float2(__uint_as_float(h2 << 16) + __uint_as_float(l2 << 16),
                       __uint_as_float(h2 & 0xffff0000u) + __uint_as_float(l2 & 0xffff0000u));
}

#define MMA_BF16(d,a0,a1,a2,a3,b0,b1) asm volatile( \
  "mma.sync.aligned.m16n8k16.row.col.f32.bf16.bf16.f32 {%0,%1,%2,%3},{%4,%5,%6,%7},{%8,%9},{%0,%1,%2,%3};" \
  : "+f"(d[0]),"+f"(d[1]),"+f"(d[2]),"+f"(d[3]) \
  : "r"(a0),"r"(a1),"r"(a2),"r"(a3),"r"(b0),"r"(b1))

#define SPADA 20   // uint2 stride per row (16 kpairs + 4 pad) -> bank-conflict-free frags

// copy 128x32 A tile (16 kpairs) from planes into smem, interleaved {hi,lo}
__device__ __forceinline__ void loadAp(uint2* sA, const unsigned* __restrict__ hp,
                                       const unsigned* __restrict__ lp,
                                       int ldu, int m0, int kp0, int tid) {
    int row = tid >> 1, half = (tid & 1) * 8;
    const unsigned* hb = hp + (size_t)(m0 + row) * ldu + kp0 + half;
    const unsigned* lb = lp + (size_t)(m0 + row) * ldu + kp0 + half;
    uint4 h0 = *(const uint4*)hb, h1 = *(const uint4*)(hb + 4);
    uint4 l0 = *(const uint4*)lb, l1 = *(const uint4*)(lb + 4);
    uint4* p = (uint4*)(sA + row * SPADA + half);
    p[0] = make_uint4(h0.x, l0.x, h0.y, l0.y);
    p[1] = make_uint4(h0.z, l0.z, h0.w, l0.w);
    p[2] = make_uint4(h1.x, l1.x, h1.y, l1.y);
    p[3] = make_uint4(h1.z, l1.z, h1.w, l1.w);
}
// copy 64x32 B tile from weight planes; zero rows >= nmax
__device__ __forceinline__ void loadBp(uint2* sB, const unsigned* __restrict__ hp,
                                       const unsigned* __restrict__ lp,
                                       int ldu, int n0, int kp0, int nmax, int tid) {
    int row = tid >> 2, q = (tid & 3) * 4;
    uint4 h = make_uint4(0,0,0,0), l = make_uint4(0,0,0,0);
    if (n0 + row < nmax) {
        h = *(const uint4*)(hp + (size_t)(n0 + row) * ldu + kp0 + q);
        l = *(const uint4*)(lp + (size_t)(n0 + row) * ldu + kp0 + q);
    }
    uint4* p = (uint4*)(sB + row * SPADA + q);
    p[0] = make_uint4(h.x, l.x, h.y, l.y);
    p[1] = make_uint4(h.z, l.z, h.w, l.w);
}

// 3-term bf16 mainloop over one BK=32 slab; warp tile 32x32
__device__ __forceinline__ void mma_slab(const uint2* __restrict__ sA, const uint2* __restrict__ sB,
                                         float acc[2][4][4], int mb, int nb, int g, int t) {
    #pragma unroll
    for (int ks = 0; ks < 2; ks++) {
        int kp = ks * 8 + t;
        unsigned ah[2][4], al[2][4];
        #pragma unroll
        for (int i = 0; i < 2; i++) {
            const uint2* p = sA + (mb + 16 * i + g) * SPADA + kp;
            uint2 v0 = p[0], v1 = p[8 * SPADA], v2 = p[4], v3 = p[8 * SPADA + 4];
            ah[i][0] = v0.x; al[i][0] = v0.y;
            ah[i][1] = v1.x; al[i][1] = v1.y;
            ah[i][2] = v2.x; al[i][2] = v2.y;
            ah[i][3] = v3.x; al[i][3] = v3.y;
        }
        #pragma unroll
        for (int j = 0; j < 4; j++) {
            const uint2* p = sB + (nb + 8 * j + g) * SPADA + kp;
            uint2 w0 = p[0], w1 = p[4];
            #pragma unroll
            for (int i = 0; i < 2; i++) {
                MMA_BF16(acc[i][j], ah[i][0], ah[i][1], ah[i][2], ah[i][3], w0.x, w1.x);
                MMA_BF16(acc[i][j], ah[i][0], ah[i][1], ah[i][2], ah[i][3], w0.y, w1.y);
                MMA_BF16(acc[i][j], al[i][0], al[i][1], al[i][2], al[i][3], w0.x, w1.x);
            }
        }
    }
}

// ---------------- kernel 1: LN1 + chunk rearrange (+ fused weight prep blocks) ----------------
__global__ void k_ln1(const float* __restrict__ x, const float* __restrict__ g,
                      const float* __restrict__ bta,
                      const float* __restrict__ dtw, const float* __restrict__ xpw,
                      const float* __restrict__ inpw, const float* __restrict__ outw,
                      const float* __restrict__ projw) {
    if (blockIdx.x >= 4096) {
        // weight-plane prep: 55296 element-pairs over 16 blocks
        for (int idx = (blockIdx.x - 4096) * 256 + threadIdx.x; idx < 55296; idx += 16 * 256) {
            float x0, x1;
            unsigned *dh, *dl;
            if (idx < 8192) {                       // in_proj 256x64
                int r = idx >> 5, kp = idx & 31;
                x0 = inpw[r * 64 + 2 * kp]; x1 = inpw[r * 64 + 2 * kp + 1];
                dh = g_wi_h + idx; dl = g_wi_l + idx;
            } else if (idx < 18432) {               // fused xproj 160x128
                int j = idx - 8192; int r = j >> 6, kp = j & 63, k = 2 * kp;
                if (r < 128) {
                    float s0 = 0.f, s1 = 0.f;
                    #pragma unroll
                    for (int q = 0; q < 4; q++) {
                        float w = dtw[r * 4 + q];
                        s0 += w * xpw[q * 128 + k];
                        s1 += w * xpw[q * 128 + k + 1];
                    }
                    x0 = s0; x1 = s1;
                } else {
                    x0 = xpw[(4 + r - 128) * 128 + k]; x1 = xpw[(4 + r - 128) * 128 + k + 1];
                }
                dh = g_wx_h + j; dl = g_wx_l + j;
            } else if (idx < 22528) {               // out_proj 64x128
                int j = idx - 18432; int r = j >> 6, kp = j & 63;
                x0 = outw[r * 128 + 2 * kp]; x1 = outw[r * 128 + 2 * kp + 1];
                dh = g_wo_h + j; dl = g_wo_l + j;
            } else {                                // final proj 256x256
                int j = idx - 22528; int r = j >> 7, kp = j & 127;
                x0 = projw[r * 256 + 2 * kp]; x1 = projw[r * 256 + 2 * kp + 1];
                dh = g_wp_h + j; dl = g_wp_l + j;
            }
            unsigned h2, l2; split2(x0, x1, h2, l2);
            *dh = h2; *dl = l2;
        }
        return;
    }
    int warp = (blockIdx.x * blockDim.x + threadIdx.x) >> 5;
    int lane = threadIdx.x & 31;
    int bb = warp >> 12, l = warp & 4095;
    const float* xp = x + (size_t)bb * Cc * Ltot + l;
    float v[8]; float s = 0.f, s2 = 0.f;
    int c0 = lane * 8;
    #pragma unroll
    for (int k = 0; k < 8; k++) {
        float t = xp[(size_t)(c0 + k) * Ltot];
        v[k] = t; s += t; s2 += t * t;
    }
    #pragma unroll
    for (int o = 16; o; o >>= 1) {
        s  += __shfl_xor_sync(0xffffffffu, s, o);
        s2 += __shfl_xor_sync(0xffffffffu, s2, o);
    }
    float mu = s * (1.f / 256.f);
    float var = s2 * (1.f / 256.f) - mu * mu;
    float rs = rsqrtf(var + 1e-5f);
    float y[8];
    #pragma unroll
    for (int k = 0; k < 8; k++) y[k] = (v[k] - mu) * rs * g[c0 + k] + bta[c0 + k];
    int chunk = lane >> 3;
    size_t base = ((size_t)((chunk * 8 + bb) * Ltot + l)) * 32 + (lane & 7) * 4;
    unsigned h[4], lo[4];
    split2(y[0], y[1], h[0], lo[0]); split2(y[2], y[3], h[1], lo[1]);
    split2(y[4], y[5], h[2], lo[2]); split2(y[6], y[7], h[3], lo[3]);
    *(uint4*)(g_xn_h + base) = make_uint4(h[0], h[1], h[2], h[3]);
    *(uint4*)(g_xn_l + base) = make_uint4(lo[0], lo[1], lo[2], lo[3]);
}

// ---------------- kernel 2: in_proj (M=131072, N=256, K=64) ----------------
__global__ void k_inproj() {
    __shared__ uint2 sA[128 * SPADA];
    __shared__ uint2 sB[64 * SPADA];
    int tid = threadIdx.x;
    int m0 = blockIdx.x * 128, n0 = blockIdx.y * 64;
    int warp = tid >> 5, lane = tid & 31, g = lane >> 2, t = lane & 3;
    int mb = (warp & 3) * 32, nb = (warp >> 2) * 32;
    float acc[2][4][4] = {};
    #pragma unroll
    for (int sl = 0; sl < 2; sl++) {
        loadAp(sA, g_xn_h, g_xn_l, 32, m0, sl * 16, tid);
        loadBp(sB, g_wi_h, g_wi_l, 32, n0, sl * 16, 256, tid);
        __syncthreads();
        mma_slab(sA, sB, acc, mb, nb, g, t);
        __syncthreads();
    }
    float* dst = (blockIdx.y < 2) ? g_xin : g_z;
    int nbase = n0 - ((blockIdx.y < 2) ? 0 : 128) + nb;
    #pragma unroll
    for (int i = 0; i < 2; i++) {
        int row = m0 + mb + 16 * i + g;
        #pragma unroll
        for (int j = 0; j < 4; j++) {
            int col = nbase + 8 * j + 2 * t;
            *(float2*)(dst + (size_t)row * 128 + col)       = make_float2(acc[i][j][0], acc[i][j][1]);
            *(float2*)(dst + (size_t)(row + 8) * 128 + col) = make_float2(acc[i][j][2], acc[i][j][3]);
        }
    }
}

// ---------------- kernel 3: depthwise causal conv + silu (2 channels/thread) ----------------
__global__ void k_conv(const float* __restrict__ cw, const float* __restrict__ cb) {
    int tid = threadIdx.x;
    int dp = tid & 63;            // channel pair
    int lq = tid >> 6;
    int n = blockIdx.x >> 7;
    int l0 = (blockIdx.x & 127) * 32 + lq * 8;
    const float2* src = (const float2*)(g_xin + (size_t)n * Ltot * DI) + dp;
    float4 wA = *(const float4*)(cw + 8 * dp);
    float4 wB = *(const float4*)(cw + 8 * dp + 4);
    float2 bb = *(const float2*)(cb + 2 * dp);
    float2 x0 = (l0 >= 3) ? src[(size_t)(l0 - 3) * 64] : make_float2(0.f, 0.f);
    float2 x1 = (l0 >= 2) ? src[(size_t)(l0 - 2) * 64] : make_float2(0.f, 0.f);
    float2 x2 = (l0 >= 1) ? src[(size_t)(l0 - 1) * 64] : make_float2(0.f, 0.f);
    float2* dstf = (float2*)(g_xc + (size_t)n * Ltot * DI) + dp;
    unsigned* dsth = g_xc_h + (size_t)n * Ltot * 64 + dp;
    unsigned* dstl = g_xc_l + (size_t)n * Ltot * 64 + dp;
    #pragma unroll
    for (int i = 0; i < 8; i++) {
        int l = l0 + i;
        float2 x3 = src[(size_t)l * 64];
        float sa = bb.x + wA.x * x0.x + wA.y * x1.x + wA.z * x2.x + wA.w * x3.x;
        float sb = bb.y + wB.x * x0.y + wB.y * x1.y + wB.z * x2.y + wB.w * x3.y;
        sa = sa / (1.f + __expf(-sa));
        sb = sb / (1.f + __expf(-sb));
        dstf[(size_t)l * 64] = make_float2(sa, sb);
        unsigned h2, l2; split2(sa, sb, h2, l2);
        dsth[(size_t)l * 64] = h2; dstl[(size_t)l * 64] = l2;
        x0 = x1; x1 = x2; x2 = x3;
    }
}

// ---------------- kernel 4: fused x_proj+dt_proj (N=160, K=128) ----------------
__global__ void k_xproj(const float* __restrict__ dtb) {
    __shared__ uint2 sA[128 * SPADA];
    __shared__ uint2 sB[64 * SPADA];
    int tid = threadIdx.x;
    int m0 = blockIdx.x * 128, n0 = blockIdx.y * 64;
    int warp = tid >> 5, lane = tid & 31, g = lane >> 2, t = lane & 3;
    int mb = (warp & 3) * 32, nb = (warp >> 2) * 32;
    float acc[2][4][4] = {};
    #pragma unroll
    for (int sl = 0; sl < 4; sl++) {
        loadAp(sA, g_xc_h, g_xc_l, 64, m0, sl * 16, tid);
        loadBp(sB, g_wx_h, g_wx_l, 64, n0, sl * 16, 160, tid);
        __syncthreads();
        mma_slab(sA, sB, acc, mb, nb, g, t);
        __syncthreads();
    }
    if (blockIdx.y < 2) {
        #pragma unroll
        for (int i = 0; i < 2; i++) {
            int row = m0 + mb + 16 * i + g;
            #pragma unroll
            for (int j = 0; j < 4; j++) {
                int col = n0 + nb + 8 * j + 2 * t;
                float b0 = dtb[col], b1 = dtb[col + 1];
                float t0 = acc[i][j][0] + b0, t1 = acc[i][j][1] + b1;
                float t2 = acc[i][j][2] + b0, t3 = acc[i][j][3] + b1;
                float s0 = (t0 > 20.f) ? t0 : log1pf(__expf(t0));
                float s1 = (t1 > 20.f) ? t1 : log1pf(__expf(t1));
                float s2 = (t2 > 20.f) ? t2 : log1pf(__expf(t2));
                float s3 = (t3 > 20.f) ? t3 : log1pf(__expf(t3));
                *(float2*)(g_delta + (size_t)row * 128 + col)       = make_float2(s0, s1);
                *(float2*)(g_delta + (size_t)(row + 8) * 128 + col) = make_float2(s2, s3);
            }
        }
    } else if (nb == 0) {
        #pragma unroll
        for (int i = 0; i < 2; i++) {
            int row = m0 + mb + 16 * i + g;
            #pragma unroll
            for (int j = 0; j < 4; j++) {
                int cl = 8 * j + 2 * t;
                float* dst = (cl < 16) ? g_Bm : g_Cm;
                int c = cl & 15;
                *(float2*)(dst + (size_t)row * 16 + c)       = make_float2(acc[i][j][0], acc[i][j][1]);
                *(float2*)(dst + (size_t)(row + 8) * 16 + c) = make_float2(acc[i][j][2], acc[i][j][3]);
            }
        }
    }
}

// ---------------- kernel 5: sequential selective scan ----------------
__global__ void k_scan(const float* __restrict__ Alog) {
    int tid = blockIdx.x * blockDim.x + threadIdx.x;
    int grp = tid >> 4;
    int s = tid & 15;
    int n = grp >> 7;
    int d = grp & 127;
    float a = -__expf(Alog[d * 16 + s]);
    const float* __restrict__ dptr = g_delta + (size_t)n * Ltot * DI + d;
    const float* __restrict__ uptr = g_xc    + (size_t)n * Ltot * DI + d;
    const float* __restrict__ bptr = g_Bm    + (size_t)n * Ltot * DS + s;
    const float* __restrict__ cptr = g_Cm    + (size_t)n * Ltot * DS + s;
    float* __restrict__ yptr = g_ys + (size_t)n * Ltot * DI + d;
    float h = 0.f;
    float dt = __ldg(dptr), u = __ldg(uptr), Bt = __ldg(bptr), Ct = __ldg(cptr);
    #pragma unroll 4
    for (int t = 0; t < Ltot; ++t) {
        float dt1 = 0.f, u1 = 0.f, B1 = 0.f, C1 = 0.f;
        if (t + 1 < Ltot) {
            dt1 = __ldg(dptr + DI); u1 = __ldg(uptr + DI);
            B1 = __ldg(bptr + DS);  C1 = __ldg(cptr + DS);
        }
        float dA = __expf(dt * a);
        h = dA * h + (dt * Bt) * u;
        float y = h * Ct;
        y += __shfl_xor_sync(0xffffffffu, y, 8);
        y += __shfl_xor_sync(0xffffffffu, y, 4);
        y += __shfl_xor_sync(0xffffffffu, y, 2);
        y += __shfl_xor_sync(0xffffffffu, y, 1);
        if (s == 0) *yptr = y;
        dptr += DI; uptr += DI; bptr += DS; cptr += DS; yptr += DI;
        dt = dt1; u = u1; Bt = B1; Ct = C1;
    }
}

// ---------------- kernel 6: gate + out_proj + residual (N=64, K=128) ----------------
__global__ void k_outproj(const float* __restrict__ Dp, const float* __restrict__ skip) {
    __shared__ uint2 sA[128 * SPADA];
    __shared__ uint2 sB[64 * SPADA];
    int tid = threadIdx.x;
    int m0 = blockIdx.x * 128;
    int warp = tid >> 5, lane = tid & 31, g = lane >> 2, t = lane & 3;
    int mb = (warp & 3) * 32, nb = (warp >> 2) * 32;
    float acc[2][4][4] = {};
    #pragma unroll
    for (int sl = 0; sl < 4; sl++) {
        int k0 = sl * 32;
        #pragma unroll
        for (int it = 0; it < 4; it++) {
            int idx = tid + it * 256;
            int row = idx >> 3, c4 = (idx & 7) * 4;
            size_t off = (size_t)(m0 + row) * 128 + k0 + c4;
            float4 ys = *(const float4*)(g_ys + off);
            float4 xc = *(const float4*)(g_xc + off);
            float4 zz = *(const float4*)(g_z + off);
            float4 dp = *(const float4*)(Dp + k0 + c4);
            float a0 = (ys.x + xc.x * dp.x) * (zz.x / (1.f + __expf(-zz.x)));
            float a1 = (ys.y + xc.y * dp.y) * (zz.y / (1.f + __expf(-zz.y)));
            float a2 = (ys.z + xc.z * dp.z) * (zz.z / (1.f + __expf(-zz.z)));
            float a3 = (ys.w + xc.w * dp.w) * (zz.w / (1.f + __expf(-zz.w)));
            unsigned h0, l0, h1, l1;
            split2(a0, a1, h0, l0); split2(a2, a3, h1, l1);
            *(uint4*)(sA + row * SPADA + (c4 >> 1)) = make_uint4(h0, l0, h1, l1);
        }
        loadBp(sB, g_wo_h, g_wo_l, 64, 0, sl * 16, 64, tid);
        __syncthreads();
        mma_slab(sA, sB, acc, mb, nb, g, t);
        __syncthreads();
    }
    float sk = skip[0];
    #pragma unroll
    for (int i = 0; i < 2; i++) {
        int row = m0 + mb + 16 * i + g;
        #pragma unroll
        for (int j = 0; j < 4; j++) {
            int col = nb + 8 * j + 2 * t;
            float2 xa = rec2(g_xn_h[(size_t)row * 32 + (col >> 1)], g_xn_l[(size_t)row * 32 + (col >> 1)]);
            float2 xb = rec2(g_xn_h[(size_t)(row + 8) * 32 + (col >> 1)], g_xn_l[(size_t)(row + 8) * 32 + (col >> 1)]);
            *(float2*)(g_ym + (size_t)row * 64 + col) =
                make_float2(acc[i][j][0] + sk * xa.x, acc[i][j][1] + sk * xa.y);
            *(float2*)(g_ym + (size_t)(row + 8) * 64 + col) =
                make_float2(acc[i][j][2] + sk * xb.x, acc[i][j][3] + sk * xb.y);
        }
    }
}

// ---------------- kernel 7: LN2 + chunk gather -> x2 planes ----------------
__global__ void k_ln2(const float* __restrict__ g, const float* __restrict__ bta) {
    int warp = (blockIdx.x * blockDim.x + threadIdx.x) >> 5;
    int lane = threadIdx.x & 31;
    int bb = warp >> 12, l = warp & 4095;
    int c0 = lane * 8;
    int chunk = lane >> 3;
    const float4* src = (const float4*)(g_ym + ((size_t)((chunk * 8 + bb) * Ltot + l)) * 64 + (c0 & 63));
    float4 v0 = src[0], v1 = src[1];
    float s = v0.x + v0.y + v0.z + v0.w + v1.x + v1.y + v1.z + v1.w;
    float s2 = v0.x*v0.x + v0.y*v0.y + v0.z*v0.z + v0.w*v0.w
             + v1.x*v1.x + v1.y*v1.y + v1.z*v1.z + v1.w*v1.w;
    #pragma unroll
    for (int o = 16; o; o >>= 1) {
        s  += __shfl_xor_sync(0xffffffffu, s, o);
        s2 += __shfl_xor_sync(0xffffffffu, s2, o);
    }
    float mu = s * (1.f / 256.f);
    float var = s2 * (1.f / 256.f) - mu * mu;
    float rs = rsqrtf(var + 1e-5f);
    float y[8] = {v0.x, v0.y, v0.z, v0.w, v1.x, v1.y, v1.z, v1.w};
    #pragma unroll
    for (int k = 0; k < 8; k++) y[k] = (y[k] - mu) * rs * g[c0 + k] + bta[c0 + k];
    unsigned h[4], lo[4];
    split2(y[0], y[1], h[0], lo[0]); split2(y[2], y[3], h[1], lo[1]);
    split2(y[4], y[5], h[2], lo[2]); split2(y[6], y[7], h[3], lo[3]);
    size_t base = ((size_t)(bb * Ltot + l)) * 128 + lane * 4;
    *(uint4*)(g_x2_h + base) = make_uint4(h[0], h[1], h[2], h[3]);
    *(uint4*)(g_x2_l + base) = make_uint4(lo[0], lo[1], lo[2], lo[3]);
}

// ---------------- kernel 8: final proj (M=32768, N=256, K=256) + transpose ----------------
__global__ void k_final(const float* __restrict__ pb, float* __restrict__ out) {
    __shared__ uint2 sA[128 * SPADA];
    __shared__ uint2 sB[64 * SPADA];
    int tid = threadIdx.x;
    int m0 = blockIdx.x * 128, n0 = blockIdx.y * 64;
    int warp = tid >> 5, lane = tid & 31, g = lane >> 2, t = lane & 3;
    int mb = (warp & 3) * 32, nb = (warp >> 2) * 32;
    float acc[2][4][4] = {};
    #pragma unroll
    for (int sl = 0; sl < 8; sl++) {
        loadAp(sA, g_x2_h, g_x2_l, 128, m0, sl * 16, tid);
        loadBp(sB, g_wp_h, g_wp_l, 128, n0, sl * 16, 256, tid);
        __syncthreads();
        mma_slab(sA, sB, acc, mb, nb, g, t);
        __syncthreads();
    }
    #pragma unroll
    for (int i = 0; i < 2; i++) {
        int row = m0 + mb + 16 * i + g;
        int bbat = row >> 12, l = row & 4095;
        int l2 = (row + 8) & 4095;
        #pragma unroll
        for (int j = 0; j < 4; j++) {
            int col = n0 + nb + 8 * j + 2 * t;
            out[(size_t)(bbat * 256 + col) * Ltot + l]      = acc[i][j][0] + pb[col];
            out[(size_t)(bbat * 256 + col + 1) * Ltot + l]  = acc[i][j][1] + pb[col + 1];
            out[(size_t)(bbat * 256 + col) * Ltot + l2]     = acc[i][j][2] + pb[col];
            out[(size_t)(bbat * 256 + col + 1) * Ltot + l2] = acc[i][j][3] + pb[col + 1];
        }
    }
}

// ---------------- launch ----------------
extern "C" void kernel_launch(void* const* d_in, const int* in_sizes, int n_in,
                              void* d_out, int out_size) {
    const float* x      = (const float*)d_in[0];
    const float* ln_g   = (const float*)d_in[1];
    const float* ln_b   = (const float*)d_in[2];
    const float* inpw   = (const float*)d_in[3];
    const float* convw  = (const float*)d_in[4];
    const float* convb  = (const float*)d_in[5];
    const float* xpw    = (const float*)d_in[6];
    const float* dtw    = (const float*)d_in[7];
    const float* dtb    = (const float*)d_in[8];
    const float* Alog   = (const float*)d_in[9];
    const float* Dp     = (const float*)d_in[10];
    const float* outw   = (const float*)d_in[11];
    const float* projw  = (const float*)d_in[12];
    const float* projb  = (const float*)d_in[13];
    const float* skip   = (const float*)d_in[14];
    float* out = (float*)d_out;

    k_ln1<<<4096 + 16, 256>>>(x, ln_g, ln_b, dtw, xpw, inpw, outw, projw);   // (1)
    k_inproj<<<dim3(1024, 4), 256>>>();                                       // (2)
    k_conv<<<4096, 256>>>(convw, convb);                                      // (3)
    k_xproj<<<dim3(1024, 3), 256>>>(dtb);                                     // (4) <- profiled slot
    k_scan<<<512, 128>>>(Alog);                                               // (5)
    k_outproj<<<1024, 256>>>(Dp, skip);                                       // (6)
    k_ln2<<<4096, 256>>>(ln_g, ln_b);                                         // (7)
    k_final<<<dim3(256, 4), 256>>>(projb, out);                               // (8)
}

// round 4
// speedup vs baseline: 1.8268x; 1.3765x over previous
#include <cuda_runtime.h>
#include <math.h>

#define Bb    8
#define Cc    256
#define Ltot  4096
#define DS    16
#define DI    128
#define Nseq  32
#define Mrow  (Nseq*Ltot)   // 131072
#define M2    (Bb*Ltot)     // 32768
#define NCH   64            // chunks per sequence
#define CL    64            // chunk length

// ---------------- fp32 scratch ----------------
__device__ float g_xin  [Mrow*DI];
__device__ float g_z    [Mrow*DI];
__device__ float g_xc   [Mrow*DI];
__device__ float g_delta[Mrow*DI];
__device__ float g_Bm   [Mrow*DS];
__device__ float g_Cm   [Mrow*DS];
__device__ float g_ys   [Mrow*DI];
__device__ float g_ym   [Mrow*64];
// scan chunk summaries: idx = ((n*128+d)*64+c)*16+s
__device__ float g_Ac [Nseq*DI*NCH*DS];
__device__ float g_bc [Nseq*DI*NCH*DS];
__device__ float g_hin[Nseq*DI*NCH*DS];

// ---------------- bf16 hi/lo planes (1 uint = 2 bf16 along K) ----------------
__device__ unsigned g_xn_h[Mrow*32], g_xn_l[Mrow*32];
__device__ unsigned g_xc_h[Mrow*64], g_xc_l[Mrow*64];
__device__ unsigned g_x2_h[M2*128],  g_x2_l[M2*128];
__device__ unsigned g_wi_h[256*32],  g_wi_l[256*32];
__device__ unsigned g_wx_h[160*64],  g_wx_l[160*64];
__device__ unsigned g_wo_h[64*64],   g_wo_l[64*64];
__device__ unsigned g_wp_h[256*128], g_wp_l[256*128];

// ---------------- split / reconstruct helpers ----------------
__device__ __forceinline__ void split2(float x0, float x1, unsigned &h2, unsigned &l2) {
    asm("cvt.rn.bf16x2.f32 %0,%1,%2;" : "=r"(h2) : "f"(x1), "f"(x0));
    float hf0 = __uint_as_float(h2 << 16);
    float hf1 = __uint_as_float(h2 & 0xffff0000u);
    asm("cvt.rn.bf16x2.f32 %0,%1,%2;" : "=r"(l2) : "f"(x1 - hf1), "f"(x0 - hf0));
}
__device__ __forceinline__ float2 rec2(unsigned h2, unsigned l2) {
    return make_float2(__uint_as_float(h2 << 16) + __uint_as_float(l2 << 16),
                       __uint_as_float(h2 & 0xffff0000u) + __uint_as_float(l2 & 0xffff0000u));
}

#define MMA_BF16(d,a0,a1,a2,a3,b0,b1) asm volatile( \
  "mma.sync.aligned.m16n8k16.row.col.f32.bf16.bf16.f32 {%0,%1,%2,%3},{%4,%5,%6,%7},{%8,%9},{%0,%1,%2,%3};" \
  : "+f"(d[0]),"+f"(d[1]),"+f"(d[2]),"+f"(d[3]) \
  : "r"(a0),"r"(a1),"r"(a2),"r"(a3),"r"(b0),"r"(b1))

#define SPADA 20

__device__ __forceinline__ void loadAp(uint2* sA, const unsigned* __restrict__ hp,
                                       const unsigned* __restrict__ lp,
                                       int ldu, int m0, int kp0, int tid) {
    int row = tid >> 1, half = (tid & 1) * 8;
    const unsigned* hb = hp + (size_t)(m0 + row) * ldu + kp0 + half;
    const unsigned* lb = lp + (size_t)(m0 + row) * ldu + kp0 + half;
    uint4 h0 = *(const uint4*)hb, h1 = *(const uint4*)(hb + 4);
    uint4 l0 = *(const uint4*)lb, l1 = *(const uint4*)(lb + 4);
    uint4* p = (uint4*)(sA + row * SPADA + half);
    p[0] = make_uint4(h0.x, l0.x, h0.y, l0.y);
    p[1] = make_uint4(h0.z, l0.z, h0.w, l0.w);
    p[2] = make_uint4(h1.x, l1.x, h1.y, l1.y);
    p[3] = make_uint4(h1.z, l1.z, h1.w, l1.w);
}
__device__ __forceinline__ void loadBp(uint2* sB, const unsigned* __restrict__ hp,
                                       const unsigned* __restrict__ lp,
                                       int ldu, int n0, int kp0, int nmax, int tid) {
    int row = tid >> 2, q = (tid & 3) * 4;
    uint4 h = make_uint4(0,0,0,0), l = make_uint4(0,0,0,0);
    if (n0 + row < nmax) {
        h = *(const uint4*)(hp + (size_t)(n0 + row) * ldu + kp0 + q);
        l = *(const uint4*)(lp + (size_t)(n0 + row) * ldu + kp0 + q);
    }
    uint4* p = (uint4*)(sB + row * SPADA + q);
    p[0] = make_uint4(h.x, l.x, h.y, l.y);
    p[1] = make_uint4(h.z, l.z, h.w, l.w);
}

__device__ __forceinline__ void mma_slab(const uint2* __restrict__ sA, const uint2* __restrict__ sB,
                                         float acc[2][4][4], int mb, int nb, int g, int t) {
    #pragma unroll
    for (int ks = 0; ks < 2; ks++) {
        int kp = ks * 8 + t;
        unsigned ah[2][4], al[2][4];
        #pragma unroll
        for (int i = 0; i < 2; i++) {
            const uint2* p = sA + (mb + 16 * i + g) * SPADA + kp;
            uint2 v0 = p[0], v1 = p[8 * SPADA], v2 = p[4], v3 = p[8 * SPADA + 4];
            ah[i][0] = v0.x; al[i][0] = v0.y;
            ah[i][1] = v1.x; al[i][1] = v1.y;
            ah[i][2] = v2.x; al[i][2] = v2.y;
            ah[i][3] = v3.x; al[i][3] = v3.y;
        }
        #pragma unroll
        for (int j = 0; j < 4; j++) {
            const uint2* p = sB + (nb + 8 * j + g) * SPADA + kp;
            uint2 w0 = p[0], w1 = p[4];
            #pragma unroll
            for (int i = 0; i < 2; i++) {
                MMA_BF16(acc[i][j], ah[i][0], ah[i][1], ah[i][2], ah[i][3], w0.x, w1.x);
                MMA_BF16(acc[i][j], ah[i][0], ah[i][1], ah[i][2], ah[i][3], w0.y, w1.y);
                MMA_BF16(acc[i][j], al[i][0], al[i][1], al[i][2], al[i][3], w0.x, w1.x);
            }
        }
    }
}

// ---------------- kernel 1: LN1 + chunk rearrange (+ fused weight prep) ----------------
__global__ void k_ln1(const float* __restrict__ x, const float* __restrict__ g,
                      const float* __restrict__ bta,
                      const float* __restrict__ dtw, const float* __restrict__ xpw,
                      const float* __restrict__ inpw, const float* __restrict__ outw,
                      const float* __restrict__ projw) {
    if (blockIdx.x >= 4096) {
        for (int idx = (blockIdx.x - 4096) * 256 + threadIdx.x; idx < 55296; idx += 16 * 256) {
            float x0, x1;
            unsigned *dh, *dl;
            if (idx < 8192) {
                int r = idx >> 5, kp = idx & 31;
                x0 = inpw[r * 64 + 2 * kp]; x1 = inpw[r * 64 + 2 * kp + 1];
                dh = g_wi_h + idx; dl = g_wi_l + idx;
            } else if (idx < 18432) {
                int j = idx - 8192; int r = j >> 6, kp = j & 63, k = 2 * kp;
                if (r < 128) {
                    float s0 = 0.f, s1 = 0.f;
                    #pragma unroll
                    for (int q = 0; q < 4; q++) {
                        float w = dtw[r * 4 + q];
                        s0 += w * xpw[q * 128 + k];
                        s1 += w * xpw[q * 128 + k + 1];
                    }
                    x0 = s0; x1 = s1;
                } else {
                    x0 = xpw[(4 + r - 128) * 128 + k]; x1 = xpw[(4 + r - 128) * 128 + k + 1];
                }
                dh = g_wx_h + j; dl = g_wx_l + j;
            } else if (idx < 22528) {
                int j = idx - 18432; int r = j >> 6, kp = j & 63;
                x0 = outw[r * 128 + 2 * kp]; x1 = outw[r * 128 + 2 * kp + 1];
                dh = g_wo_h + j; dl = g_wo_l + j;
            } else {
                int j = idx - 22528; int r = j >> 7, kp = j & 127;
                x0 = projw[r * 256 + 2 * kp]; x1 = projw[r * 256 + 2 * kp + 1];
                dh = g_wp_h + j; dl = g_wp_l + j;
            }
            unsigned h2, l2; split2(x0, x1, h2, l2);
            *dh = h2; *dl = l2;
        }
        return;
    }
    int warp = (blockIdx.x * blockDim.x + threadIdx.x) >> 5;
    int lane = threadIdx.x & 31;
    int bb = warp >> 12, l = warp & 4095;
    const float* xp = x + (size_t)bb * Cc * Ltot + l;
    float v[8]; float s = 0.f, s2 = 0.f;
    int c0 = lane * 8;
    #pragma unroll
    for (int k = 0; k < 8; k++) {
        float t = xp[(size_t)(c0 + k) * Ltot];
        v[k] = t; s += t; s2 += t * t;
    }
    #pragma unroll
    for (int o = 16; o; o >>= 1) {
        s  += __shfl_xor_sync(0xffffffffu, s, o);
        s2 += __shfl_xor_sync(0xffffffffu, s2, o);
    }
    float mu = s * (1.f / 256.f);
    float var = s2 * (1.f / 256.f) - mu * mu;
    float rs = rsqrtf(var + 1e-5f);
    float y[8];
    #pragma unroll
    for (int k = 0; k < 8; k++) y[k] = (v[k] - mu) * rs * g[c0 + k] + bta[c0 + k];
    int chunk = lane >> 3;
    size_t base = ((size_t)((chunk * 8 + bb) * Ltot + l)) * 32 + (lane & 7) * 4;
    unsigned h[4], lo[4];
    split2(y[0], y[1], h[0], lo[0]); split2(y[2], y[3], h[1], lo[1]);
    split2(y[4], y[5], h[2], lo[2]); split2(y[6], y[7], h[3], lo[3]);
    *(uint4*)(g_xn_h + base) = make_uint4(h[0], h[1], h[2], h[3]);
    *(uint4*)(g_xn_l + base) = make_uint4(lo[0], lo[1], lo[2], lo[3]);
}

// ---------------- kernel 2: in_proj ----------------
__global__ void k_inproj() {
    __shared__ uint2 sA[128 * SPADA];
    __shared__ uint2 sB[64 * SPADA];
    int tid = threadIdx.x;
    int m0 = blockIdx.x * 128, n0 = blockIdx.y * 64;
    int warp = tid >> 5, lane = tid & 31, g = lane >> 2, t = lane & 3;
    int mb = (warp & 3) * 32, nb = (warp >> 2) * 32;
    float acc[2][4][4] = {};
    #pragma unroll
    for (int sl = 0; sl < 2; sl++) {
        loadAp(sA, g_xn_h, g_xn_l, 32, m0, sl * 16, tid);
        loadBp(sB, g_wi_h, g_wi_l, 32, n0, sl * 16, 256, tid);
        __syncthreads();
        mma_slab(sA, sB, acc, mb, nb, g, t);
        __syncthreads();
    }
    float* dst = (blockIdx.y < 2) ? g_xin : g_z;
    int nbase = n0 - ((blockIdx.y < 2) ? 0 : 128) + nb;
    #pragma unroll
    for (int i = 0; i < 2; i++) {
        int row = m0 + mb + 16 * i + g;
        #pragma unroll
        for (int j = 0; j < 4; j++) {
            int col = nbase + 8 * j + 2 * t;
            *(float2*)(dst + (size_t)row * 128 + col)       = make_float2(acc[i][j][0], acc[i][j][1]);
            *(float2*)(dst + (size_t)(row + 8) * 128 + col) = make_float2(acc[i][j][2], acc[i][j][3]);
        }
    }
}

// ---------------- kernel 3: conv + silu ----------------
__global__ void k_conv(const float* __restrict__ cw, const float* __restrict__ cb) {
    int tid = threadIdx.x;
    int dp = tid & 63;
    int lq = tid >> 6;
    int n = blockIdx.x >> 7;
    int l0 = (blockIdx.x & 127) * 32 + lq * 8;
    const float2* src = (const float2*)(g_xin + (size_t)n * Ltot * DI) + dp;
    float4 wA = *(const float4*)(cw + 8 * dp);
    float4 wB = *(const float4*)(cw + 8 * dp + 4);
    float2 bb = *(const float2*)(cb + 2 * dp);
    float2 x0 = (l0 >= 3) ? src[(size_t)(l0 - 3) * 64] : make_float2(0.f, 0.f);
    float2 x1 = (l0 >= 2) ? src[(size_t)(l0 - 2) * 64] : make_float2(0.f, 0.f);
    float2 x2 = (l0 >= 1) ? src[(size_t)(l0 - 1) * 64] : make_float2(0.f, 0.f);
    float2* dstf = (float2*)(g_xc + (size_t)n * Ltot * DI) + dp;
    unsigned* dsth = g_xc_h + (size_t)n * Ltot * 64 + dp;
    unsigned* dstl = g_xc_l + (size_t)n * Ltot * 64 + dp;
    #pragma unroll
    for (int i = 0; i < 8; i++) {
        int l = l0 + i;
        float2 x3 = src[(size_t)l * 64];
        float sa = bb.x + wA.x * x0.x + wA.y * x1.x + wA.z * x2.x + wA.w * x3.x;
        float sb = bb.y + wB.x * x0.y + wB.y * x1.y + wB.z * x2.y + wB.w * x3.y;
        sa = sa / (1.f + __expf(-sa));
        sb = sb / (1.f + __expf(-sb));
        dstf[(size_t)l * 64] = make_float2(sa, sb);
        unsigned h2, l2; split2(sa, sb, h2, l2);
        dsth[(size_t)l * 64] = h2; dstl[(size_t)l * 64] = l2;
        x0 = x1; x1 = x2; x2 = x3;
    }
}

// ---------------- kernel 4: fused x_proj+dt_proj ----------------
__global__ void k_xproj(const float* __restrict__ dtb) {
    __shared__ uint2 sA[128 * SPADA];
    __shared__ uint2 sB[64 * SPADA];
    int tid = threadIdx.x;
    int m0 = blockIdx.x * 128, n0 = blockIdx.y * 64;
    int warp = tid >> 5, lane = tid & 31, g = lane >> 2, t = lane & 3;
    int mb = (warp & 3) * 32, nb = (warp >> 2) * 32;
    float acc[2][4][4] = {};
    #pragma unroll
    for (int sl = 0; sl < 4; sl++) {
        loadAp(sA, g_xc_h, g_xc_l, 64, m0, sl * 16, tid);
        loadBp(sB, g_wx_h, g_wx_l, 64, n0, sl * 16, 160, tid);
        __syncthreads();
        mma_slab(sA, sB, acc, mb, nb, g, t);
        __syncthreads();
    }
    if (blockIdx.y < 2) {
        #pragma unroll
        for (int i = 0; i < 2; i++) {
            int row = m0 + mb + 16 * i + g;
            #pragma unroll
            for (int j = 0; j < 4; j++) {
                int col = n0 + nb + 8 * j + 2 * t;
                float b0 = dtb[col], b1 = dtb[col + 1];
                float t0 = acc[i][j][0] + b0, t1 = acc[i][j][1] + b1;
                float t2 = acc[i][j][2] + b0, t3 = acc[i][j][3] + b1;
                float s0 = (t0 > 20.f) ? t0 : log1pf(__expf(t0));
                float s1 = (t1 > 20.f) ? t1 : log1pf(__expf(t1));
                float s2 = (t2 > 20.f) ? t2 : log1pf(__expf(t2));
                float s3 = (t3 > 20.f) ? t3 : log1pf(__expf(t3));
                *(float2*)(g_delta + (size_t)row * 128 + col)       = make_float2(s0, s1);
                *(float2*)(g_delta + (size_t)(row + 8) * 128 + col) = make_float2(s2, s3);
            }
        }
    } else if (nb == 0) {
        #pragma unroll
        for (int i = 0; i < 2; i++) {
            int row = m0 + mb + 16 * i + g;
            #pragma unroll
            for (int j = 0; j < 4; j++) {
                int cl = 8 * j + 2 * t;
                float* dst = (cl < 16) ? g_Bm : g_Cm;
                int c = cl & 15;
                *(float2*)(dst + (size_t)row * 16 + c)       = make_float2(acc[i][j][0], acc[i][j][1]);
                *(float2*)(dst + (size_t)(row + 8) * 16 + c) = make_float2(acc[i][j][2], acc[i][j][3]);
            }
        }
    }
}

// ---------------- kernel 5a: chunk-local scan (pass A) ----------------
// block: 256 thr = 16 groups (d = db*16+g), lanes = s. grid: n*512 + c*8 + db
__global__ void k_scanA(const float* __restrict__ Alog) {
    int bx = blockIdx.x;
    int n = bx >> 9, c = (bx >> 3) & 63, db = bx & 7;
    int g = threadIdx.x >> 4, s = threadIdx.x & 15;
    int d = db * 16 + g;
    float a = -__expf(Alog[d * 16 + s]);
    size_t row0 = (size_t)n * Ltot + c * CL;
    const float* dp = g_delta + row0 * DI + d;
    const float* up = g_xc    + row0 * DI + d;
    const float* bp = g_Bm    + row0 * DS + s;
    float fdt[8], fu[8], fB[8];
    #pragma unroll
    for (int i = 0; i < 8; i++) {
        fdt[i] = __ldg(dp + i * DI); fu[i] = __ldg(up + i * DI); fB[i] = __ldg(bp + i * DS);
    }
    float h = 0.f, sd = 0.f;
    #pragma unroll
    for (int tt = 0; tt < CL; tt += 8) {
        #pragma unroll
        for (int i = 0; i < 8; i++) {
            float dt = fdt[i], u = fu[i], Bv = fB[i];
            int tn = tt + i + 8;
            if (tn < CL) {
                fdt[i] = __ldg(dp + tn * DI); fu[i] = __ldg(up + tn * DI); fB[i] = __ldg(bp + tn * DS);
            }
            sd += dt;
            h = __expf(dt * a) * h + (dt * Bv) * u;
        }
    }
    size_t idx = (((size_t)(n * 128 + d)) * NCH + c) * DS + s;
    g_Ac[idx] = __expf(a * sd);
    g_bc[idx] = h;
}

// ---------------- kernel 5b: combine chunk summaries (pass B) ----------------
__global__ void k_scanB() {
    int tid = blockIdx.x * blockDim.x + threadIdx.x;   // 65536 = n*d*s
    int n = tid >> 11, rem = tid & 2047;
    int d = rem >> 4, s = rem & 15;
    size_t base = ((size_t)(n * 128 + d)) * NCH * DS + s;
    float h = 0.f;
    float A0 = __ldg(g_Ac + base), b0 = __ldg(g_bc + base);
    #pragma unroll 8
    for (int c = 0; c < NCH; c++) {
        float A1 = 0.f, b1 = 0.f;
        if (c + 1 < NCH) {
            A1 = __ldg(g_Ac + base + (c + 1) * DS);
            b1 = __ldg(g_bc + base + (c + 1) * DS);
        }
        g_hin[base + c * DS] = h;
        h = A0 * h + b0;
        A0 = A1; b0 = b1;
    }
}

// ---------------- kernel 5c: replay with h_in, emit y (pass C) ----------------
__global__ void k_scanC(const float* __restrict__ Alog) {
    int bx = blockIdx.x;
    int n = bx >> 9, c = (bx >> 3) & 63, db = bx & 7;
    int g = threadIdx.x >> 4, s = threadIdx.x & 15;
    int d = db * 16 + g;
    float a = -__expf(Alog[d * 16 + s]);
    size_t row0 = (size_t)n * Ltot + c * CL;
    const float* dp = g_delta + row0 * DI + d;
    const float* up = g_xc    + row0 * DI + d;
    const float* bp = g_Bm    + row0 * DS + s;
    const float* cp = g_Cm    + row0 * DS + s;
    float* yp = g_ys + row0 * DI + d;
    float fdt[8], fu[8], fB[8], fC[8];
    #pragma unroll
    for (int i = 0; i < 8; i++) {
        fdt[i] = __ldg(dp + i * DI); fu[i] = __ldg(up + i * DI);
        fB[i] = __ldg(bp + i * DS);  fC[i] = __ldg(cp + i * DS);
    }
    float h = g_hin[(((size_t)(n * 128 + d)) * NCH + c) * DS + s];
    #pragma unroll
    for (int tt = 0; tt < CL; tt += 8) {
        #pragma unroll
        for (int i = 0; i < 8; i++) {
            float dt = fdt[i], u = fu[i], Bv = fB[i], Cv = fC[i];
            int tn = tt + i + 8;
            if (tn < CL) {
                fdt[i] = __ldg(dp + tn * DI); fu[i] = __ldg(up + tn * DI);
                fB[i] = __ldg(bp + tn * DS);  fC[i] = __ldg(cp + tn * DS);
            }
            h = __expf(dt * a) * h + (dt * Bv) * u;
            float y = h * Cv;
            y += __shfl_xor_sync(0xffffffffu, y, 8);
            y += __shfl_xor_sync(0xffffffffu, y, 4);
            y += __shfl_xor_sync(0xffffffffu, y, 2);
            y += __shfl_xor_sync(0xffffffffu, y, 1);
            if (s == 0) yp[(size_t)(tt + i) * DI] = y;
        }
    }
}

// ---------------- kernel 6: gate + out_proj + residual ----------------
__global__ void k_outproj(const float* __restrict__ Dp, const float* __restrict__ skip) {
    __shared__ uint2 sA[128 * SPADA];
    __shared__ uint2 sB[64 * SPADA];
    int tid = threadIdx.x;
    int m0 = blockIdx.x * 128;
    int warp = tid >> 5, lane = tid & 31, g = lane >> 2, t = lane & 3;
    int mb = (warp & 3) * 32, nb = (warp >> 2) * 32;
    float acc[2][4][4] = {};
    #pragma unroll
    for (int sl = 0; sl < 4; sl++) {
        int k0 = sl * 32;
        #pragma unroll
        for (int it = 0; it < 4; it++) {
            int idx = tid + it * 256;
            int row = idx >> 3, c4 = (idx & 7) * 4;
            size_t off = (size_t)(m0 + row) * 128 + k0 + c4;
            float4 ys = *(const float4*)(g_ys + off);
            float4 xc = *(const float4*)(g_xc + off);
            float4 zz = *(const float4*)(g_z + off);
            float4 dp = *(const float4*)(Dp + k0 + c4);
            float a0 = (ys.x + xc.x * dp.x) * (zz.x / (1.f + __expf(-zz.x)));
            float a1 = (ys.y + xc.y * dp.y) * (zz.y / (1.f + __expf(-zz.y)));
            float a2 = (ys.z + xc.z * dp.z) * (zz.z / (1.f + __expf(-zz.z)));
            float a3 = (ys.w + xc.w * dp.w) * (zz.w / (1.f + __expf(-zz.w)));
            unsigned h0, l0, h1, l1;
            split2(a0, a1, h0, l0); split2(a2, a3, h1, l1);
            *(uint4*)(sA + row * SPADA + (c4 >> 1)) = make_uint4(h0, l0, h1, l1);
        }
        loadBp(sB, g_wo_h, g_wo_l, 64, 0, sl * 16, 64, tid);
        __syncthreads();
        mma_slab(sA, sB, acc, mb, nb, g, t);
        __syncthreads();
    }
    float sk = skip[0];
    #pragma unroll
    for (int i = 0; i < 2; i++) {
        int row = m0 + mb + 16 * i + g;
        #pragma unroll
        for (int j = 0; j < 4; j++) {
            int col = nb + 8 * j + 2 * t;
            float2 xa = rec2(g_xn_h[(size_t)row * 32 + (col >> 1)], g_xn_l[(size_t)row * 32 + (col >> 1)]);
            float2 xb = rec2(g_xn_h[(size_t)(row + 8) * 32 + (col >> 1)], g_xn_l[(size_t)(row + 8) * 32 + (col >> 1)]);
            *(float2*)(g_ym + (size_t)row * 64 + col) =
                make_float2(acc[i][j][0] + sk * xa.x, acc[i][j][1] + sk * xa.y);
            *(float2*)(g_ym + (size_t)(row + 8) * 64 + col) =
                make_float2(acc[i][j][2] + sk * xb.x, acc[i][j][3] + sk * xb.y);
        }
    }
}

// ---------------- kernel 7: LN2 + chunk gather ----------------
__global__ void k_ln2(const float* __restrict__ g, const float* __restrict__ bta) {
    int warp = (blockIdx.x * blockDim.x + threadIdx.x) >> 5;
    int lane = threadIdx.x & 31;
    int bb = warp >> 12, l = warp & 4095;
    int c0 = lane * 8;
    int chunk = lane >> 3;
    const float4* src = (const float4*)(g_ym + ((size_t)((chunk * 8 + bb) * Ltot + l)) * 64 + (c0 & 63));
    float4 v0 = src[0], v1 = src[1];
    float s = v0.x + v0.y + v0.z + v0.w + v1.x + v1.y + v1.z + v1.w;
    float s2 = v0.x*v0.x + v0.y*v0.y + v0.z*v0.z + v0.w*v0.w
             + v1.x*v1.x + v1.y*v1.y + v1.z*v1.z + v1.w*v1.w;
    #pragma unroll
    for (int o = 16; o; o >>= 1) {
        s  += __shfl_xor_sync(0xffffffffu, s, o);
        s2 += __shfl_xor_sync(0xffffffffu, s2, o);
    }
    float mu = s * (1.f / 256.f);
    float var = s2 * (1.f / 256.f) - mu * mu;
    float rs = rsqrtf(var + 1e-5f);
    float y[8] = {v0.x, v0.y, v0.z, v0.w, v1.x, v1.y, v1.z, v1.w};
    #pragma unroll
    for (int k = 0; k < 8; k++) y[k] = (y[k] - mu) * rs * g[c0 + k] + bta[c0 + k];
    unsigned h[4], lo[4];
    split2(y[0], y[1], h[0], lo[0]); split2(y[2], y[3], h[1], lo[1]);
    split2(y[4], y[5], h[2], lo[2]); split2(y[6], y[7], h[3], lo[3]);
    size_t base = ((size_t)(bb * Ltot + l)) * 128 + lane * 4;
    *(uint4*)(g_x2_h + base) = make_uint4(h[0], h[1], h[2], h[3]);
    *(uint4*)(g_x2_l + base) = make_uint4(lo[0], lo[1], lo[2], lo[3]);
}

// ---------------- kernel 8: final proj + transpose ----------------
__global__ void k_final(const float* __restrict__ pb, float* __restrict__ out) {
    __shared__ uint2 sA[128 * SPADA];
    __shared__ uint2 sB[64 * SPADA];
    int tid = threadIdx.x;
    int m0 = blockIdx.x * 128, n0 = blockIdx.y * 64;
    int warp = tid >> 5, lane = tid & 31, g = lane >> 2, t = lane & 3;
    int mb = (warp & 3) * 32, nb = (warp >> 2) * 32;
    float acc[2][4][4] = {};
    #pragma unroll
    for (int sl = 0; sl < 8; sl++) {
        loadAp(sA, g_x2_h, g_x2_l, 128, m0, sl * 16, tid);
        loadBp(sB, g_wp_h, g_wp_l, 128, n0, sl * 16, 256, tid);
        __syncthreads();
        mma_slab(sA, sB, acc, mb, nb, g, t);
        __syncthreads();
    }
    #pragma unroll
    for (int i = 0; i < 2; i++) {
        int row = m0 + mb + 16 * i + g;
        int bbat = row >> 12, l = row & 4095;
        int l2 = (row + 8) & 4095;
        #pragma unroll
        for (int j = 0; j < 4; j++) {
            int col = n0 + nb + 8 * j + 2 * t;
            out[(size_t)(bbat * 256 + col) * Ltot + l]      = acc[i][j][0] + pb[col];
            out[(size_t)(bbat * 256 + col + 1) * Ltot + l]  = acc[i][j][1] + pb[col + 1];
            out[(size_t)(bbat * 256 + col) * Ltot + l2]     = acc[i][j][2] + pb[col];
            out[(size_t)(bbat * 256 + col + 1) * Ltot + l2] = acc[i][j][3] + pb[col + 1];
        }
    }
}

// ---------------- launch ----------------
extern "C" void kernel_launch(void* const* d_in, const int* in_sizes, int n_in,
                              void* d_out, int out_size) {
    const float* x      = (const float*)d_in[0];
    const float* ln_g   = (const float*)d_in[1];
    const float* ln_b   = (const float*)d_in[2];
    const float* inpw   = (const float*)d_in[3];
    const float* convw  = (const float*)d_in[4];
    const float* convb  = (const float*)d_in[5];
    const float* xpw    = (const float*)d_in[6];
    const float* dtw    = (const float*)d_in[7];
    const float* dtb    = (const float*)d_in[8];
    const float* Alog   = (const float*)d_in[9];
    const float* Dp     = (const float*)d_in[10];
    const float* outw   = (const float*)d_in[11];
    const float* projw  = (const float*)d_in[12];
    const float* projb  = (const float*)d_in[13];
    const float* skip   = (const float*)d_in[14];
    float* out = (float*)d_out;

    k_ln1<<<4096 + 16, 256>>>(x, ln_g, ln_b, dtw, xpw, inpw, outw, projw);   // (1)
    k_inproj<<<dim3(1024, 4), 256>>>();                                       // (2)
    k_conv<<<4096, 256>>>(convw, convb);                                      // (3)
    k_xproj<<<dim3(1024, 3), 256>>>(dtb);                                     // (4) profiled
    k_scanA<<<16384, 256>>>(Alog);                                            // (5)
    k_scanB<<<256, 256>>>();                                                  // (6)
    k_scanC<<<16384, 256>>>(Alog);                                            // (7)
    k_outproj<<<1024, 256>>>(Dp, skip);                                       // (8)
    k_ln2<<<4096, 256>>>(ln_g, ln_b);                                         // (9)
    k_final<<<dim3(256, 4), 256>>>(projb, out);                               // (10)
}

// round 5
// speedup vs baseline: 2.9223x; 1.5996x over previous
#include <cuda_runtime.h>
#include <math.h>

#define Bb    8
#define Cc    256
#define Ltot  4096
#define DS    16
#define DI    128
#define Nseq  32
#define Mrow  (Nseq*Ltot)   // 131072
#define M2    (Bb*Ltot)     // 32768
#define NCH   64
#define CL    64

// ---------------- fp32 scratch ----------------
__device__ __align__(16) float g_xin [Mrow*DI];
__device__ __align__(16) float g_z   [Mrow*DI];
__device__ __align__(16) float g_xc  [Mrow*DI];
__device__ __align__(16) float g_ym  [Mrow*64];
// transposed scan operands
__device__ __align__(16) float g_dtT [Nseq*DI*Ltot];   // [n][d][t]
__device__ __align__(16) float g_PT  [Nseq*DI*Ltot];   // [n][d][t]  (dt*u)
__device__ __align__(16) float g_BmT [Nseq*DS*Ltot];   // [n][s][t]
__device__ __align__(16) float g_CmT [Nseq*DS*Ltot];   // [n][s][t]
__device__ __align__(16) float g_ysT [Nseq*DI*Ltot];   // [n][d][t]
// chunk summaries: [n][d][c][s]
__device__ __align__(16) float g_Ac [Nseq*DI*NCH*DS];
__device__ __align__(16) float g_bc [Nseq*DI*NCH*DS];
__device__ __align__(16) float g_hin[Nseq*DI*NCH*DS];

// ---------------- bf16 hi/lo planes ----------------
__device__ __align__(16) unsigned g_xn_h[Mrow*32], g_xn_l[Mrow*32];
__device__ __align__(16) unsigned g_xc_h[Mrow*64], g_xc_l[Mrow*64];
__device__ __align__(16) unsigned g_x2_h[M2*128],  g_x2_l[M2*128];
__device__ __align__(16) unsigned g_wi_h[256*32],  g_wi_l[256*32];
__device__ __align__(16) unsigned g_wx_h[160*64],  g_wx_l[160*64];
__device__ __align__(16) unsigned g_wo_h[64*64],   g_wo_l[64*64];
__device__ __align__(16) unsigned g_wp_h[256*128], g_wp_l[256*128];

__device__ __forceinline__ void split2(float x0, float x1, unsigned &h2, unsigned &l2) {
    asm("cvt.rn.bf16x2.f32 %0,%1,%2;" : "=r"(h2) : "f"(x1), "f"(x0));
    float hf0 = __uint_as_float(h2 << 16);
    float hf1 = __uint_as_float(h2 & 0xffff0000u);
    asm("cvt.rn.bf16x2.f32 %0,%1,%2;" : "=r"(l2) : "f"(x1 - hf1), "f"(x0 - hf0));
}
__device__ __forceinline__ float2 rec2(unsigned h2, unsigned l2) {
    return make_float2(__uint_as_float(h2 << 16) + __uint_as_float(l2 << 16),
                       __uint_as_float(h2 & 0xffff0000u) + __uint_as_float(l2 & 0xffff0000u));
}

#define MMA_BF16(d,a0,a1,a2,a3,b0,b1) asm volatile( \
  "mma.sync.aligned.m16n8k16.row.col.f32.bf16.bf16.f32 {%0,%1,%2,%3},{%4,%5,%6,%7},{%8,%9},{%0,%1,%2,%3};" \
  : "+f"(d[0]),"+f"(d[1]),"+f"(d[2]),"+f"(d[3]) \
  : "r"(a0),"r"(a1),"r"(a2),"r"(a3),"r"(b0),"r"(b1))

#define SPADA 20

__device__ __forceinline__ void loadAp(uint2* sA, const unsigned* __restrict__ hp,
                                       const unsigned* __restrict__ lp,
                                       int ldu, int m0, int kp0, int tid) {
    int row = tid >> 1, half = (tid & 1) * 8;
    const unsigned* hb = hp + (size_t)(m0 + row) * ldu + kp0 + half;
    const unsigned* lb = lp + (size_t)(m0 + row) * ldu + kp0 + half;
    uint4 h0 = *(const uint4*)hb, h1 = *(const uint4*)(hb + 4);
    uint4 l0 = *(const uint4*)lb, l1 = *(const uint4*)(lb + 4);
    uint4* p = (uint4*)(sA + row * SPADA + half);
    p[0] = make_uint4(h0.x, l0.x, h0.y, l0.y);
    p[1] = make_uint4(h0.z, l0.z, h0.w, l0.w);
    p[2] = make_uint4(h1.x, l1.x, h1.y, l1.y);
    p[3] = make_uint4(h1.z, l1.z, h1.w, l1.w);
}
__device__ __forceinline__ void loadBp(uint2* sB, const unsigned* __restrict__ hp,
                                       const unsigned* __restrict__ lp,
                                       int ldu, int n0, int kp0, int nmax, int tid) {
    int row = tid >> 2, q = (tid & 3) * 4;
    uint4 h = make_uint4(0,0,0,0), l = make_uint4(0,0,0,0);
    if (n0 + row < nmax) {
        h = *(const uint4*)(hp + (size_t)(n0 + row) * ldu + kp0 + q);
        l = *(const uint4*)(lp + (size_t)(n0 + row) * ldu + kp0 + q);
    }
    uint4* p = (uint4*)(sB + row * SPADA + q);
    p[0] = make_uint4(h.x, l.x, h.y, l.y);
    p[1] = make_uint4(h.z, l.z, h.w, l.w);
}

__device__ __forceinline__ void mma_slab(const uint2* __restrict__ sA, const uint2* __restrict__ sB,
                                         float acc[2][4][4], int mb, int nb, int g, int t) {
    #pragma unroll
    for (int ks = 0; ks < 2; ks++) {
        int kp = ks * 8 + t;
        unsigned ah[2][4], al[2][4];
        #pragma unroll
        for (int i = 0; i < 2; i++) {
            const uint2* p = sA + (mb + 16 * i + g) * SPADA + kp;
            uint2 v0 = p[0], v1 = p[8 * SPADA], v2 = p[4], v3 = p[8 * SPADA + 4];
            ah[i][0] = v0.x; al[i][0] = v0.y;
            ah[i][1] = v1.x; al[i][1] = v1.y;
            ah[i][2] = v2.x; al[i][2] = v2.y;
            ah[i][3] = v3.x; al[i][3] = v3.y;
        }
        #pragma unroll
        for (int j = 0; j < 4; j++) {
            const uint2* p = sB + (nb + 8 * j + g) * SPADA + kp;
            uint2 w0 = p[0], w1 = p[4];
            #pragma unroll
            for (int i = 0; i < 2; i++) {
                MMA_BF16(acc[i][j], ah[i][0], ah[i][1], ah[i][2], ah[i][3], w0.x, w1.x);
                MMA_BF16(acc[i][j], ah[i][0], ah[i][1], ah[i][2], ah[i][3], w0.y, w1.y);
                MMA_BF16(acc[i][j], al[i][0], al[i][1], al[i][2], al[i][3], w0.x, w1.x);
            }
        }
    }
}

// ---------------- kernel 1: LN1 + chunk rearrange (+ fused weight prep) ----------------
__global__ void k_ln1(const float* __restrict__ x, const float* __restrict__ g,
                      const float* __restrict__ bta,
                      const float* __restrict__ dtw, const float* __restrict__ xpw,
                      const float* __restrict__ inpw, const float* __restrict__ outw,
                      const float* __restrict__ projw) {
    if (blockIdx.x >= 4096) {
        for (int idx = (blockIdx.x - 4096) * 256 + threadIdx.x; idx < 55296; idx += 16 * 256) {
            float x0, x1;
            unsigned *dh, *dl;
            if (idx < 8192) {
                int r = idx >> 5, kp = idx & 31;
                x0 = inpw[r * 64 + 2 * kp]; x1 = inpw[r * 64 + 2 * kp + 1];
                dh = g_wi_h + idx; dl = g_wi_l + idx;
            } else if (idx < 18432) {
                int j = idx - 8192; int r = j >> 6, kp = j & 63, k = 2 * kp;
                if (r < 128) {
                    float s0 = 0.f, s1 = 0.f;
                    #pragma unroll
                    for (int q = 0; q < 4; q++) {
                        float w = dtw[r * 4 + q];
                        s0 += w * xpw[q * 128 + k];
                        s1 += w * xpw[q * 128 + k + 1];
                    }
                    x0 = s0; x1 = s1;
                } else {
                    x0 = xpw[(4 + r - 128) * 128 + k]; x1 = xpw[(4 + r - 128) * 128 + k + 1];
                }
                dh = g_wx_h + j; dl = g_wx_l + j;
            } else if (idx < 22528) {
                int j = idx - 18432; int r = j >> 6, kp = j & 63;
                x0 = outw[r * 128 + 2 * kp]; x1 = outw[r * 128 + 2 * kp + 1];
                dh = g_wo_h + j; dl = g_wo_l + j;
            } else {
                int j = idx - 22528; int r = j >> 7, kp = j & 127;
                x0 = projw[r * 256 + 2 * kp]; x1 = projw[r * 256 + 2 * kp + 1];
                dh = g_wp_h + j; dl = g_wp_l + j;
            }
            unsigned h2, l2; split2(x0, x1, h2, l2);
            *dh = h2; *dl = l2;
        }
        return;
    }
    int warp = (blockIdx.x * blockDim.x + threadIdx.x) >> 5;
    int lane = threadIdx.x & 31;
    int bb = warp >> 12, l = warp & 4095;
    const float* xp = x + (size_t)bb * Cc * Ltot + l;
    float v[8]; float s = 0.f, s2 = 0.f;
    int c0 = lane * 8;
    #pragma unroll
    for (int k = 0; k < 8; k++) {
        float t = xp[(size_t)(c0 + k) * Ltot];
        v[k] = t; s += t; s2 += t * t;
    }
    #pragma unroll
    for (int o = 16; o; o >>= 1) {
        s  += __shfl_xor_sync(0xffffffffu, s, o);
        s2 += __shfl_xor_sync(0xffffffffu, s2, o);
    }
    float mu = s * (1.f / 256.f);
    float var = s2 * (1.f / 256.f) - mu * mu;
    float rs = rsqrtf(var + 1e-5f);
    float y[8];
    #pragma unroll
    for (int k = 0; k < 8; k++) y[k] = (v[k] - mu) * rs * g[c0 + k] + bta[c0 + k];
    int chunk = lane >> 3;
    size_t base = ((size_t)((chunk * 8 + bb) * Ltot + l)) * 32 + (lane & 7) * 4;
    unsigned h[4], lo[4];
    split2(y[0], y[1], h[0], lo[0]); split2(y[2], y[3], h[1], lo[1]);
    split2(y[4], y[5], h[2], lo[2]); split2(y[6], y[7], h[3], lo[3]);
    *(uint4*)(g_xn_h + base) = make_uint4(h[0], h[1], h[2], h[3]);
    *(uint4*)(g_xn_l + base) = make_uint4(lo[0], lo[1], lo[2], lo[3]);
}

// ---------------- kernel 2: in_proj ----------------
__global__ void k_inproj() {
    __shared__ uint2 sA[128 * SPADA];
    __shared__ uint2 sB[64 * SPADA];
    int tid = threadIdx.x;
    int m0 = blockIdx.x * 128, n0 = blockIdx.y * 64;
    int warp = tid >> 5, lane = tid & 31, g = lane >> 2, t = lane & 3;
    int mb = (warp & 3) * 32, nb = (warp >> 2) * 32;
    float acc[2][4][4] = {};
    #pragma unroll
    for (int sl = 0; sl < 2; sl++) {
        loadAp(sA, g_xn_h, g_xn_l, 32, m0, sl * 16, tid);
        loadBp(sB, g_wi_h, g_wi_l, 32, n0, sl * 16, 256, tid);
        __syncthreads();
        mma_slab(sA, sB, acc, mb, nb, g, t);
        __syncthreads();
    }
    float* dst = (blockIdx.y < 2) ? g_xin : g_z;
    int nbase = n0 - ((blockIdx.y < 2) ? 0 : 128) + nb;
    #pragma unroll
    for (int i = 0; i < 2; i++) {
        int row = m0 + mb + 16 * i + g;
        #pragma unroll
        for (int j = 0; j < 4; j++) {
            int col = nbase + 8 * j + 2 * t;
            *(float2*)(dst + (size_t)row * 128 + col)       = make_float2(acc[i][j][0], acc[i][j][1]);
            *(float2*)(dst + (size_t)(row + 8) * 128 + col) = make_float2(acc[i][j][2], acc[i][j][3]);
        }
    }
}

// ---------------- kernel 3: conv + silu ----------------
__global__ void k_conv(const float* __restrict__ cw, const float* __restrict__ cb) {
    int tid = threadIdx.x;
    int dp = tid & 63;
    int lq = tid >> 6;
    int n = blockIdx.x >> 7;
    int l0 = (blockIdx.x & 127) * 32 + lq * 8;
    const float2* src = (const float2*)(g_xin + (size_t)n * Ltot * DI) + dp;
    float4 wA = *(const float4*)(cw + 8 * dp);
    float4 wB = *(const float4*)(cw + 8 * dp + 4);
    float2 bb = *(const float2*)(cb + 2 * dp);
    float2 x0 = (l0 >= 3) ? src[(size_t)(l0 - 3) * 64] : make_float2(0.f, 0.f);
    float2 x1 = (l0 >= 2) ? src[(size_t)(l0 - 2) * 64] : make_float2(0.f, 0.f);
    float2 x2 = (l0 >= 1) ? src[(size_t)(l0 - 1) * 64] : make_float2(0.f, 0.f);
    float2* dstf = (float2*)(g_xc + (size_t)n * Ltot * DI) + dp;
    unsigned* dsth = g_xc_h + (size_t)n * Ltot * 64 + dp;
    unsigned* dstl = g_xc_l + (size_t)n * Ltot * 64 + dp;
    #pragma unroll
    for (int i = 0; i < 8; i++) {
        int l = l0 + i;
        float2 x3 = src[(size_t)l * 64];
        float sa = bb.x + wA.x * x0.x + wA.y * x1.x + wA.z * x2.x + wA.w * x3.x;
        float sb = bb.y + wB.x * x0.y + wB.y * x1.y + wB.z * x2.y + wB.w * x3.y;
        sa = sa / (1.f + __expf(-sa));
        sb = sb / (1.f + __expf(-sb));
        dstf[(size_t)l * 64] = make_float2(sa, sb);
        unsigned h2, l2; split2(sa, sb, h2, l2);
        dsth[(size_t)l * 64] = h2; dstl[(size_t)l * 64] = l2;
        x0 = x1; x1 = x2; x2 = x3;
    }
}

// ---------------- kernel 4: fused x_proj+dt_proj + transposed epilogue ----------------
__global__ void k_xproj(const float* __restrict__ dtb) {
    __shared__ __align__(16) char smraw[64 * 132 * 4];   // 33792 B, unioned
    uint2* sA = (uint2*)smraw;
    uint2* sB = sA + 128 * SPADA;
    float* smT = (float*)smraw;
    int tid = threadIdx.x;
    int m0 = blockIdx.x * 128, n0 = blockIdx.y * 64;
    int warp = tid >> 5, lane = tid & 31, g = lane >> 2, t = lane & 3;
    int mb = (warp & 3) * 32, nb = (warp >> 2) * 32;
    float acc[2][4][4] = {};
    #pragma unroll
    for (int sl = 0; sl < 4; sl++) {
        loadAp(sA, g_xc_h, g_xc_l, 64, m0, sl * 16, tid);
        loadBp(sB, g_wx_h, g_wx_l, 64, n0, sl * 16, 160, tid);
        __syncthreads();
        mma_slab(sA, sB, acc, mb, nb, g, t);
        __syncthreads();
    }
    int n = m0 >> 12, l0 = m0 & 4095;
    if (blockIdx.y < 2) {
        // phase 1: softplus(delta) -> smem transposed tile [64 d][128 t]
        #pragma unroll
        for (int i = 0; i < 2; i++) {
            int rowL = mb + 16 * i + g;
            #pragma unroll
            for (int j = 0; j < 4; j++) {
                int colL = nb + 8 * j + 2 * t;
                float b0 = dtb[n0 + colL], b1 = dtb[n0 + colL + 1];
                float t0 = acc[i][j][0] + b0, t1 = acc[i][j][1] + b1;
                float t2 = acc[i][j][2] + b0, t3 = acc[i][j][3] + b1;
                acc[i][j][0] = (t0 > 20.f) ? t0 : log1pf(__expf(t0));
                acc[i][j][1] = (t1 > 20.f) ? t1 : log1pf(__expf(t1));
                acc[i][j][2] = (t2 > 20.f) ? t2 : log1pf(__expf(t2));
                acc[i][j][3] = (t3 > 20.f) ? t3 : log1pf(__expf(t3));
                smT[colL * 132 + rowL]           = acc[i][j][0];
                smT[(colL + 1) * 132 + rowL]     = acc[i][j][1];
                smT[colL * 132 + rowL + 8]       = acc[i][j][2];
                smT[(colL + 1) * 132 + rowL + 8] = acc[i][j][3];
            }
        }
        __syncthreads();
        #pragma unroll
        for (int k = 0; k < 8; k++) {
            int dL = warp * 8 + k;
            float4 v = *(float4*)&smT[dL * 132 + 4 * lane];
            *(float4*)(g_dtT + ((size_t)(n * 128 + n0 + dL)) * 4096 + l0 + 4 * lane) = v;
        }
        __syncthreads();
        // phase 2: P = sp * u
        #pragma unroll
        for (int i = 0; i < 2; i++) {
            int rowL = mb + 16 * i + g;
            #pragma unroll
            for (int j = 0; j < 4; j++) {
                int colL = nb + 8 * j + 2 * t;
                float2 u0 = *(const float2*)(g_xc + (size_t)(m0 + rowL) * 128 + n0 + colL);
                float2 u1 = *(const float2*)(g_xc + (size_t)(m0 + rowL + 8) * 128 + n0 + colL);
                smT[colL * 132 + rowL]           = acc[i][j][0] * u0.x;
                smT[(colL + 1) * 132 + rowL]     = acc[i][j][1] * u0.y;
                smT[colL * 132 + rowL + 8]       = acc[i][j][2] * u1.x;
                smT[(colL + 1) * 132 + rowL + 8] = acc[i][j][3] * u1.y;
            }
        }
        __syncthreads();
        #pragma unroll
        for (int k = 0; k < 8; k++) {
            int dL = warp * 8 + k;
            float4 v = *(float4*)&smT[dL * 132 + 4 * lane];
            *(float4*)(g_PT + ((size_t)(n * 128 + n0 + dL)) * 4096 + l0 + 4 * lane) = v;
        }
    } else {
        // B/C tile: cols 128..159 live in nb==0 warps
        if (nb == 0) {
            #pragma unroll
            for (int i = 0; i < 2; i++) {
                int rowL = mb + 16 * i + g;
                #pragma unroll
                for (int j = 0; j < 4; j++) {
                    int colL = 8 * j + 2 * t;   // 0..31
                    smT[colL * 132 + rowL]           = acc[i][j][0];
                    smT[(colL + 1) * 132 + rowL]     = acc[i][j][1];
                    smT[colL * 132 + rowL + 8]       = acc[i][j][2];
                    smT[(colL + 1) * 132 + rowL + 8] = acc[i][j][3];
                }
            }
        }
        __syncthreads();
        #pragma unroll
        for (int k = 0; k < 4; k++) {
            int sRow = warp * 4 + k;   // 0..31
            float4 v = *(float4*)&smT[sRow * 132 + 4 * lane];
            if (sRow < 16)
                *(float4*)(g_BmT + ((size_t)(n * 16 + sRow)) * 4096 + l0 + 4 * lane) = v;
            else
                *(float4*)(g_CmT + ((size_t)(n * 16 + sRow - 16)) * 4096 + l0 + 4 * lane) = v;
        }
    }
}

// ---------------- kernel 5a: chunk-local scan, thread owns 16 states ----------------
__global__ void k_scanA(const float* __restrict__ Alog) {
    int c = blockIdx.x, n = blockIdx.y, d = threadIdx.x;
    __shared__ float sBt[16 * 64];
    #pragma unroll
    for (int k = 0; k < 2; k++) {
        int f = threadIdx.x + k * 128, s = f >> 4, tq = f & 15;
        *(float4*)&sBt[s * 64 + 4 * tq] =
            __ldg((const float4*)(g_BmT + ((size_t)(n * 16 + s)) * 4096 + c * 64 + 4 * tq));
    }
    __syncthreads();
    float a[16], h[16];
    #pragma unroll
    for (int s = 0; s < 16; s++) { a[s] = -__expf(__ldg(Alog + d * 16 + s)); h[s] = 0.f; }
    float sd = 0.f;
    const float4* dt4 = (const float4*)(g_dtT + ((size_t)(n * 128 + d)) * 4096 + c * 64);
    const float4* P4  = (const float4*)(g_PT  + ((size_t)(n * 128 + d)) * 4096 + c * 64);
    for (int q = 0; q < 16; q++) {
        float4 dtv = __ldg(dt4 + q), Pv = __ldg(P4 + q);
        float dts[4] = {dtv.x, dtv.y, dtv.z, dtv.w};
        float Ps[4]  = {Pv.x,  Pv.y,  Pv.z,  Pv.w};
        #pragma unroll
        for (int e = 0; e < 4; e++) {
            float dt = dts[e], P = Ps[e];
            sd += dt;
            const float* Bp = &sBt[4 * q + e];
            #pragma unroll
            for (int s = 0; s < 16; s++)
                h[s] = __expf(dt * a[s]) * h[s] + P * Bp[s * 64];
        }
    }
    float* oA = g_Ac + (((size_t)(n * 128 + d)) * 64 + c) * 16;
    float* oB = g_bc + (((size_t)(n * 128 + d)) * 64 + c) * 16;
    #pragma unroll
    for (int q = 0; q < 4; q++) {
        *(float4*)(oA + 4 * q) = make_float4(__expf(a[4*q] * sd), __expf(a[4*q+1] * sd),
                                             __expf(a[4*q+2] * sd), __expf(a[4*q+3] * sd));
        *(float4*)(oB + 4 * q) = make_float4(h[4*q], h[4*q+1], h[4*q+2], h[4*q+3]);
    }
}

// ---------------- kernel 5b: combine chunk summaries ----------------
__global__ void k_scanB() {
    int tid = blockIdx.x * blockDim.x + threadIdx.x;
    int n = tid >> 11, rem = tid & 2047;
    int d = rem >> 4, s = rem & 15;
    size_t base = ((size_t)(n * 128 + d)) * NCH * DS + s;
    float h = 0.f;
    float A0 = __ldg(g_Ac + base), b0 = __ldg(g_bc + base);
    #pragma unroll 8
    for (int c = 0; c < NCH; c++) {
        float A1 = 0.f, b1 = 0.f;
        if (c + 1 < NCH) {
            A1 = __ldg(g_Ac + base + (c + 1) * DS);
            b1 = __ldg(g_bc + base + (c + 1) * DS);
        }
        g_hin[base + c * DS] = h;
        h = A0 * h + b0;
        A0 = A1; b0 = b1;
    }
}

// ---------------- kernel 5c: replay with h_in, emit y^T ----------------
__global__ void k_scanC(const float* __restrict__ Alog) {
    int c = blockIdx.x, n = blockIdx.y, d = threadIdx.x;
    __shared__ float sBt[16 * 64];
    __shared__ float sCt[16 * 64];
    #pragma unroll
    for (int k = 0; k < 2; k++) {
        int f = threadIdx.x + k * 128, s = f >> 4, tq = f & 15;
        *(float4*)&sBt[s * 64 + 4 * tq] =
            __ldg((const float4*)(g_BmT + ((size_t)(n * 16 + s)) * 4096 + c * 64 + 4 * tq));
        *(float4*)&sCt[s * 64 + 4 * tq] =
            __ldg((const float4*)(g_CmT + ((size_t)(n * 16 + s)) * 4096 + c * 64 + 4 * tq));
    }
    __syncthreads();
    float a[16], h[16];
    #pragma unroll
    for (int s = 0; s < 16; s++) a[s] = -__expf(__ldg(Alog + d * 16 + s));
    const float* hi = g_hin + (((size_t)(n * 128 + d)) * 64 + c) * 16;
    #pragma unroll
    for (int q = 0; q < 4; q++) {
        float4 v = __ldg((const float4*)(hi + 4 * q));
        h[4*q] = v.x; h[4*q+1] = v.y; h[4*q+2] = v.z; h[4*q+3] = v.w;
    }
    const float4* dt4 = (const float4*)(g_dtT + ((size_t)(n * 128 + d)) * 4096 + c * 64);
    const float4* P4  = (const float4*)(g_PT  + ((size_t)(n * 128 + d)) * 4096 + c * 64);
    float4* yp = (float4*)(g_ysT + ((size_t)(n * 128 + d)) * 4096 + c * 64);
    for (int q = 0; q < 16; q++) {
        float4 dtv = __ldg(dt4 + q), Pv = __ldg(P4 + q);
        float dts[4] = {dtv.x, dtv.y, dtv.z, dtv.w};
        float Ps[4]  = {Pv.x,  Pv.y,  Pv.z,  Pv.w};
        float yv[4];
        #pragma unroll
        for (int e = 0; e < 4; e++) {
            float dt = dts[e], P = Ps[e];
            const float* Bp = &sBt[4 * q + e];
            const float* Cp = &sCt[4 * q + e];
            float y = 0.f;
            #pragma unroll
            for (int s = 0; s < 16; s++) {
                h[s] = __expf(dt * a[s]) * h[s] + P * Bp[s * 64];
                y += h[s] * Cp[s * 64];
            }
            yv[e] = y;
        }
        yp[q] = make_float4(yv[0], yv[1], yv[2], yv[3]);
    }
}

// ---------------- kernel 6: gate + out_proj + residual ----------------
__global__ void k_outproj(const float* __restrict__ Dp, const float* __restrict__ skip) {
    __shared__ uint2 sA[128 * SPADA];
    __shared__ uint2 sB[64 * SPADA];
    int tid = threadIdx.x;
    int m0 = blockIdx.x * 128;
    int nn = m0 >> 12, l0 = m0 & 4095;
    int warp = tid >> 5, lane = tid & 31, g = lane >> 2, t = lane & 3;
    int mb = (warp & 3) * 32, nb = (warp >> 2) * 32;
    float acc[2][4][4] = {};
    #pragma unroll
    for (int sl = 0; sl < 4; sl++) {
        int k0 = sl * 32;
        #pragma unroll
        for (int it = 0; it < 4; it++) {
            int idx = tid + it * 256;
            int row = idx >> 3, c4 = (idx & 7) * 4;
            size_t off = (size_t)(m0 + row) * 128 + k0 + c4;
            float ys0 = __ldg(g_ysT + ((size_t)(nn * 128 + k0 + c4 + 0)) * 4096 + l0 + row);
            float ys1 = __ldg(g_ysT + ((size_t)(nn * 128 + k0 + c4 + 1)) * 4096 + l0 + row);
            float ys2 = __ldg(g_ysT + ((size_t)(nn * 128 + k0 + c4 + 2)) * 4096 + l0 + row);
            float ys3 = __ldg(g_ysT + ((size_t)(nn * 128 + k0 + c4 + 3)) * 4096 + l0 + row);
            float4 xc = *(const float4*)(g_xc + off);
            float4 zz = *(const float4*)(g_z + off);
            float4 dp = *(const float4*)(Dp + k0 + c4);
            float a0 = (ys0 + xc.x * dp.x) * (zz.x / (1.f + __expf(-zz.x)));
            float a1 = (ys1 + xc.y * dp.y) * (zz.y / (1.f + __expf(-zz.y)));
            float a2 = (ys2 + xc.z * dp.z) * (zz.z / (1.f + __expf(-zz.z)));
            float a3 = (ys3 + xc.w * dp.w) * (zz.w / (1.f + __expf(-zz.w)));
            unsigned h0, lo0, h1, lo1;
            split2(a0, a1, h0, lo0); split2(a2, a3, h1, lo1);
            *(uint4*)(sA + row * SPADA + (c4 >> 1)) = make_uint4(h0, lo0, h1, lo1);
        }
        loadBp(sB, g_wo_h, g_wo_l, 64, 0, sl * 16, 64, tid);
        __syncthreads();
        mma_slab(sA, sB, acc, mb, nb, g, t);
        __syncthreads();
    }
    float sk = skip[0];
    #pragma unroll
    for (int i = 0; i < 2; i++) {
        int row = m0 + mb + 16 * i + g;
        #pragma unroll
        for (int j = 0; j < 4; j++) {
            int col = nb + 8 * j + 2 * t;
            float2 xa = rec2(g_xn_h[(size_t)row * 32 + (col >> 1)], g_xn_l[(size_t)row * 32 + (col >> 1)]);
            float2 xb = rec2(g_xn_h[(size_t)(row + 8) * 32 + (col >> 1)], g_xn_l[(size_t)(row + 8) * 32 + (col >> 1)]);
            *(float2*)(g_ym + (size_t)row * 64 + col) =
                make_float2(acc[i][j][0] + sk * xa.x, acc[i][j][1] + sk * xa.y);
            *(float2*)(g_ym + (size_t)(row + 8) * 64 + col) =
                make_float2(acc[i][j][2] + sk * xb.x, acc[i][j][3] + sk * xb.y);
        }
    }
}

// ---------------- kernel 7: LN2 + chunk gather ----------------
__global__ void k_ln2(const float* __restrict__ g, const float* __restrict__ bta) {
    int warp = (blockIdx.x * blockDim.x + threadIdx.x) >> 5;
    int lane = threadIdx.x & 31;
    int bb = warp >> 12, l = warp & 4095;
    int c0 = lane * 8;
    int chunk = lane >> 3;
    const float4* src = (const float4*)(g_ym + ((size_t)((chunk * 8 + bb) * Ltot + l)) * 64 + (c0 & 63));
    float4 v0 = src[0], v1 = src[1];
    float s = v0.x + v0.y + v0.z + v0.w + v1.x + v1.y + v1.z + v1.w;
    float s2 = v0.x*v0.x + v0.y*v0.y + v0.z*v0.z + v0.w*v0.w
             + v1.x*v1.x + v1.y*v1.y + v1.z*v1.z + v1.w*v1.w;
    #pragma unroll
    for (int o = 16; o; o >>= 1) {
        s  += __shfl_xor_sync(0xffffffffu, s, o);
        s2 += __shfl_xor_sync(0xffffffffu, s2, o);
    }
    float mu = s * (1.f / 256.f);
    float var = s2 * (1.f / 256.f) - mu * mu;
    float rs = rsqrtf(var + 1e-5f);
    float y[8] = {v0.x, v0.y, v0.z, v0.w, v1.x, v1.y, v1.z, v1.w};
    #pragma unroll
    for (int k = 0; k < 8; k++) y[k] = (y[k] - mu) * rs * g[c0 + k] + bta[c0 + k];
    unsigned h[4], lo[4];
    split2(y[0], y[1], h[0], lo[0]); split2(y[2], y[3], h[1], lo[1]);
    split2(y[4], y[5], h[2], lo[2]); split2(y[6], y[7], h[3], lo[3]);
    size_t base = ((size_t)(bb * Ltot + l)) * 128 + lane * 4;
    *(uint4*)(g_x2_h + base) = make_uint4(h[0], h[1], h[2], h[3]);
    *(uint4*)(g_x2_l + base) = make_uint4(lo[0], lo[1], lo[2], lo[3]);
}

// ---------------- kernel 8: final proj + transpose ----------------
__global__ void k_final(const float* __restrict__ pb, float* __restrict__ out) {
    __shared__ uint2 sA[128 * SPADA];
    __shared__ uint2 sB[64 * SPADA];
    int tid = threadIdx.x;
    int m0 = blockIdx.x * 128, n0 = blockIdx.y * 64;
    int warp = tid >> 5, lane = tid & 31, g = lane >> 2, t = lane & 3;
    int mb = (warp & 3) * 32, nb = (warp >> 2) * 32;
    float acc[2][4][4] = {};
    #pragma unroll
    for (int sl = 0; sl < 8; sl++) {
        loadAp(sA, g_x2_h, g_x2_l, 128, m0, sl * 16, tid);
        loadBp(sB, g_wp_h, g_wp_l, 128, n0, sl * 16, 256, tid);
        __syncthreads();
        mma_slab(sA, sB, acc, mb, nb, g, t);
        __syncthreads();
    }
    #pragma unroll
    for (int i = 0; i < 2; i++) {
        int row = m0 + mb + 16 * i + g;
        int bbat = row >> 12, l = row & 4095;
        int l2 = (row + 8) & 4095;
        #pragma unroll
        for (int j = 0; j < 4; j++) {
            int col = n0 + nb + 8 * j + 2 * t;
            out[(size_t)(bbat * 256 + col) * Ltot + l]      = acc[i][j][0] + pb[col];
            out[(size_t)(bbat * 256 + col + 1) * Ltot + l]  = acc[i][j][1] + pb[col + 1];
            out[(size_t)(bbat * 256 + col) * Ltot + l2]     = acc[i][j][2] + pb[col];
            out[(size_t)(bbat * 256 + col + 1) * Ltot + l2] = acc[i][j][3] + pb[col + 1];
        }
    }
}

// ---------------- launch ----------------
extern "C" void kernel_launch(void* const* d_in, const int* in_sizes, int n_in,
                              void* d_out, int out_size) {
    const float* x      = (const float*)d_in[0];
    const float* ln_g   = (const float*)d_in[1];
    const float* ln_b   = (const float*)d_in[2];
    const float* inpw   = (const float*)d_in[3];
    const float* convw  = (const float*)d_in[4];
    const float* convb  = (const float*)d_in[5];
    const float* xpw    = (const float*)d_in[6];
    const float* dtw    = (const float*)d_in[7];
    const float* dtb    = (const float*)d_in[8];
    const float* Alog   = (const float*)d_in[9];
    const float* Dp     = (const float*)d_in[10];
    const float* outw   = (const float*)d_in[11];
    const float* projw  = (const float*)d_in[12];
    const float* projb  = (const float*)d_in[13];
    const float* skip   = (const float*)d_in[14];
    float* out = (float*)d_out;

    k_ln1<<<4096 + 16, 256>>>(x, ln_g, ln_b, dtw, xpw, inpw, outw, projw);   // (1)
    k_inproj<<<dim3(1024, 4), 256>>>();                                       // (2)
    k_conv<<<4096, 256>>>(convw, convb);                                      // (3)
    k_xproj<<<dim3(1024, 3), 256>>>(dtb);                                     // (4) profiled
    k_scanA<<<dim3(NCH, Nseq), 128>>>(Alog);                                  // (5)
    k_scanB<<<256, 256>>>();                                                  // (6)
    k_scanC<<<dim3(NCH, Nseq), 128>>>(Alog);                                  // (7)
    k_outproj<<<1024, 256>>>(Dp, skip);                                       // (8)
    k_ln2<<<4096, 256>>>(ln_g, ln_b);                                         // (9)
    k_final<<<dim3(256, 4), 256>>>(projb, out);                               // (10)
}

// round 6
// speedup vs baseline: 3.0539x; 1.0450x over previous
#include <cuda_runtime.h>
#include <math.h>

#define Bb    8
#define Cc    256
#define Ltot  4096
#define DS    16
#define DI    128
#define Nseq  32
#define Mrow  (Nseq*Ltot)   // 131072
#define M2    (Bb*Ltot)     // 32768
#define NCH   64
#define CL    64

// ---------------- fp32 scratch ----------------
__device__ __align__(16) float g_xin [Mrow*DI];
__device__ __align__(16) float g_z   [Mrow*DI];
__device__ __align__(16) float g_xc  [Mrow*DI];
__device__ __align__(16) float g_ym  [Mrow*64];
__device__ __align__(16) float g_dtT [Nseq*DI*Ltot];
__device__ __align__(16) float g_PT  [Nseq*DI*Ltot];
__device__ __align__(16) float g_BmT [Nseq*DS*Ltot];
__device__ __align__(16) float g_CmT [Nseq*DS*Ltot];
__device__ __align__(16) float g_ysT [Nseq*DI*Ltot];
__device__ __align__(16) float g_Ac [Nseq*DI*NCH*DS];
__device__ __align__(16) float g_bc [Nseq*DI*NCH*DS];
__device__ __align__(16) float g_hin[Nseq*DI*NCH*DS];

// ---------------- interleaved bf16 hi/lo planes: uint2{h2,l2} per k-pair ----------------
__device__ __align__(16) uint2 g_xn_i[Mrow*32];
__device__ __align__(16) uint2 g_xc_i[Mrow*64];
__device__ __align__(16) uint2 g_x2_i[M2*128];
__device__ __align__(16) uint2 g_wi_i[256*32];
__device__ __align__(16) uint2 g_wx_i[160*64];
__device__ __align__(16) uint2 g_wo_i[64*64];
__device__ __align__(16) uint2 g_wp_i[256*128];

__device__ __forceinline__ void split2(float x0, float x1, unsigned &h2, unsigned &l2) {
    asm("cvt.rn.bf16x2.f32 %0,%1,%2;" : "=r"(h2) : "f"(x1), "f"(x0));
    float hf0 = __uint_as_float(h2 << 16);
    float hf1 = __uint_as_float(h2 & 0xffff0000u);
    asm("cvt.rn.bf16x2.f32 %0,%1,%2;" : "=r"(l2) : "f"(x1 - hf1), "f"(x0 - hf0));
}
__device__ __forceinline__ float2 rec2(uint2 v) {
    return make_float2(__uint_as_float(v.x << 16) + __uint_as_float(v.y << 16),
                       __uint_as_float(v.x & 0xffff0000u) + __uint_as_float(v.y & 0xffff0000u));
}

#define MMA_BF16(d,a0,a1,a2,a3,b0,b1) asm volatile( \
  "mma.sync.aligned.m16n8k16.row.col.f32.bf16.bf16.f32 {%0,%1,%2,%3},{%4,%5,%6,%7},{%8,%9},{%0,%1,%2,%3};" \
  : "+f"(d[0]),"+f"(d[1]),"+f"(d[2]),"+f"(d[3]) \
  : "r"(a0),"r"(a1),"r"(a2),"r"(a3),"r"(b0),"r"(b1))

#define SPADA 20
#define STAGE_BYTES ((128 + 64) * SPADA * 8)   // 30720
#define ABUF_BYTES  (128 * SPADA * 8)          // 20480

#define CPA(dst,src,sz) asm volatile("cp.async.cg.shared.global [%0],[%1],16,%2;"::"r"(dst),"l"(src),"r"(sz))
#define CPCOMMIT()      asm volatile("cp.async.commit_group;")
#define CPWAIT(n)       asm volatile("cp.async.wait_group %0;"::"n"(n))

// issue A tile: 128 rows x 16 kpairs, 16B per thread x 4 iters
__device__ __forceinline__ void issueA(unsigned sb, const uint2* __restrict__ plane,
                                       int ldu, int m0, int kp0, int tid) {
    #pragma unroll
    for (int it = 0; it < 4; it++) {
        int idx = it * 256 + tid;
        int row = idx >> 3, ch = idx & 7;
        unsigned dst = sb + (row * SPADA + ch * 2) * 8;
        const uint2* src = plane + (size_t)(m0 + row) * ldu + kp0 + ch * 2;
        CPA(dst, src, 16);
    }
}
// issue B tile: 64 rows x 16 kpairs; rows >= nmax zero-filled
__device__ __forceinline__ void issueB(unsigned sb, const uint2* __restrict__ plane,
                                       int ldu, int n0, int kp0, int nmax, int tid) {
    #pragma unroll
    for (int it = 0; it < 2; it++) {
        int idx = it * 256 + tid;
        int row = idx >> 3, ch = idx & 7;
        unsigned dst = sb + (row * SPADA + ch * 2) * 8;
        const uint2* src = plane + (size_t)(n0 + row) * ldu + kp0 + ch * 2;
        int sz = (n0 + row < nmax) ? 16 : 0;
        CPA(dst, src, sz);
    }
}

__device__ __forceinline__ void mma_slab(const uint2* __restrict__ sA, const uint2* __restrict__ sB,
                                         float acc[2][4][4], int mb, int nb, int g, int t) {
    #pragma unroll
    for (int ks = 0; ks < 2; ks++) {
        int kp = ks * 8 + t;
        unsigned ah[2][4], al[2][4];
        #pragma unroll
        for (int i = 0; i < 2; i++) {
            const uint2* p = sA + (mb + 16 * i + g) * SPADA + kp;
            uint2 v0 = p[0], v1 = p[8 * SPADA], v2 = p[4], v3 = p[8 * SPADA + 4];
            ah[i][0] = v0.x; al[i][0] = v0.y;
            ah[i][1] = v1.x; al[i][1] = v1.y;
            ah[i][2] = v2.x; al[i][2] = v2.y;
            ah[i][3] = v3.x; al[i][3] = v3.y;
        }
        #pragma unroll
        for (int j = 0; j < 4; j++) {
            const uint2* p = sB + (nb + 8 * j + g) * SPADA + kp;
            uint2 w0 = p[0], w1 = p[4];
            #pragma unroll
            for (int i = 0; i < 2; i++) {
                MMA_BF16(acc[i][j], ah[i][0], ah[i][1], ah[i][2], ah[i][3], w0.x, w1.x);
                MMA_BF16(acc[i][j], ah[i][0], ah[i][1], ah[i][2], ah[i][3], w0.y, w1.y);
                MMA_BF16(acc[i][j], al[i][0], al[i][1], al[i][2], al[i][3], w0.x, w1.x);
            }
        }
    }
}

// ---------------- kernel 1: LN1 + chunk rearrange (+ fused weight prep) ----------------
__global__ void k_ln1(const float* __restrict__ x, const float* __restrict__ g,
                      const float* __restrict__ bta,
                      const float* __restrict__ dtw, const float* __restrict__ xpw,
                      const float* __restrict__ inpw, const float* __restrict__ outw,
                      const float* __restrict__ projw) {
    if (blockIdx.x >= 4096) {
        for (int idx = (blockIdx.x - 4096) * 256 + threadIdx.x; idx < 55296; idx += 16 * 256) {
            float x0, x1;
            uint2* dst;
            if (idx < 8192) {
                int r = idx >> 5, kp = idx & 31;
                x0 = inpw[r * 64 + 2 * kp]; x1 = inpw[r * 64 + 2 * kp + 1];
                dst = g_wi_i + idx;
            } else if (idx < 18432) {
                int j = idx - 8192; int r = j >> 6, kp = j & 63, k = 2 * kp;
                if (r < 128) {
                    float s0 = 0.f, s1 = 0.f;
                    #pragma unroll
                    for (int q = 0; q < 4; q++) {
                        float w = dtw[r * 4 + q];
                        s0 += w * xpw[q * 128 + k];
                        s1 += w * xpw[q * 128 + k + 1];
                    }
                    x0 = s0; x1 = s1;
                } else {
                    x0 = xpw[(4 + r - 128) * 128 + k]; x1 = xpw[(4 + r - 128) * 128 + k + 1];
                }
                dst = g_wx_i + j;
            } else if (idx < 22528) {
                int j = idx - 18432; int r = j >> 6, kp = j & 63;
                x0 = outw[r * 128 + 2 * kp]; x1 = outw[r * 128 + 2 * kp + 1];
                dst = g_wo_i + j;
            } else {
                int j = idx - 22528; int r = j >> 7, kp = j & 127;
                x0 = projw[r * 256 + 2 * kp]; x1 = projw[r * 256 + 2 * kp + 1];
                dst = g_wp_i + j;
            }
            unsigned h2, l2; split2(x0, x1, h2, l2);
            *dst = make_uint2(h2, l2);
        }
        return;
    }
    int warp = (blockIdx.x * blockDim.x + threadIdx.x) >> 5;
    int lane = threadIdx.x & 31;
    int bb = warp >> 12, l = warp & 4095;
    const float* xp = x + (size_t)bb * Cc * Ltot + l;
    float v[8]; float s = 0.f, s2 = 0.f;
    int c0 = lane * 8;
    #pragma unroll
    for (int k = 0; k < 8; k++) {
        float t = xp[(size_t)(c0 + k) * Ltot];
        v[k] = t; s += t; s2 += t * t;
    }
    #pragma unroll
    for (int o = 16; o; o >>= 1) {
        s  += __shfl_xor_sync(0xffffffffu, s, o);
        s2 += __shfl_xor_sync(0xffffffffu, s2, o);
    }
    float mu = s * (1.f / 256.f);
    float var = s2 * (1.f / 256.f) - mu * mu;
    float rs = rsqrtf(var + 1e-5f);
    float y[8];
    #pragma unroll
    for (int k = 0; k < 8; k++) y[k] = (v[k] - mu) * rs * g[c0 + k] + bta[c0 + k];
    int chunk = lane >> 3;
    size_t base = ((size_t)((chunk * 8 + bb) * Ltot + l)) * 32 + (lane & 7) * 4;
    unsigned h[4], lo[4];
    split2(y[0], y[1], h[0], lo[0]); split2(y[2], y[3], h[1], lo[1]);
    split2(y[4], y[5], h[2], lo[2]); split2(y[6], y[7], h[3], lo[3]);
    *(uint4*)(g_xn_i + base)     = make_uint4(h[0], lo[0], h[1], lo[1]);
    *(uint4*)(g_xn_i + base + 2) = make_uint4(h[2], lo[2], h[3], lo[3]);
}

// ---------------- kernel 2: in_proj (double-buffered, 2 slabs) ----------------
__global__ void k_inproj() {
    extern __shared__ __align__(16) char smem[];
    unsigned sb = (unsigned)__cvta_generic_to_shared(smem);
    int tid = threadIdx.x;
    int m0 = blockIdx.x * 128, n0 = blockIdx.y * 64;
    int warp = tid >> 5, lane = tid & 31, g = lane >> 2, t = lane & 3;
    int mb = (warp & 3) * 32, nb = (warp >> 2) * 32;
    float acc[2][4][4] = {};
    issueA(sb, g_xn_i, 32, m0, 0, tid);
    issueB(sb + ABUF_BYTES, g_wi_i, 32, n0, 0, 256, tid);
    CPCOMMIT();
    #pragma unroll
    for (int sl = 0; sl < 2; sl++) {
        unsigned buf = (sl & 1) * STAGE_BYTES;
        if (sl + 1 < 2) {
            unsigned nbuf = ((sl + 1) & 1) * STAGE_BYTES;
            issueA(sb + nbuf, g_xn_i, 32, m0, (sl + 1) * 16, tid);
            issueB(sb + nbuf + ABUF_BYTES, g_wi_i, 32, n0, (sl + 1) * 16, 256, tid);
            CPCOMMIT();
            CPWAIT(1);
        } else {
            CPWAIT(0);
        }
        __syncthreads();
        mma_slab((uint2*)(smem + buf), (uint2*)(smem + buf + ABUF_BYTES), acc, mb, nb, g, t);
        __syncthreads();
    }
    float* dst = (blockIdx.y < 2) ? g_xin : g_z;
    int nbase = n0 - ((blockIdx.y < 2) ? 0 : 128) + nb;
    #pragma unroll
    for (int i = 0; i < 2; i++) {
        int row = m0 + mb + 16 * i + g;
        #pragma unroll
        for (int j = 0; j < 4; j++) {
            int col = nbase + 8 * j + 2 * t;
            *(float2*)(dst + (size_t)row * 128 + col)       = make_float2(acc[i][j][0], acc[i][j][1]);
            *(float2*)(dst + (size_t)(row + 8) * 128 + col) = make_float2(acc[i][j][2], acc[i][j][3]);
        }
    }
}

// ---------------- kernel 3: conv + silu ----------------
__global__ void k_conv(const float* __restrict__ cw, const float* __restrict__ cb) {
    int tid = threadIdx.x;
    int dp = tid & 63;
    int lq = tid >> 6;
    int n = blockIdx.x >> 7;
    int l0 = (blockIdx.x & 127) * 32 + lq * 8;
    const float2* src = (const float2*)(g_xin + (size_t)n * Ltot * DI) + dp;
    float4 wA = *(const float4*)(cw + 8 * dp);
    float4 wB = *(const float4*)(cw + 8 * dp + 4);
    float2 bb = *(const float2*)(cb + 2 * dp);
    float2 x0 = (l0 >= 3) ? src[(size_t)(l0 - 3) * 64] : make_float2(0.f, 0.f);
    float2 x1 = (l0 >= 2) ? src[(size_t)(l0 - 2) * 64] : make_float2(0.f, 0.f);
    float2 x2 = (l0 >= 1) ? src[(size_t)(l0 - 1) * 64] : make_float2(0.f, 0.f);
    float2* dstf = (float2*)(g_xc + (size_t)n * Ltot * DI) + dp;
    uint2* dsti = g_xc_i + (size_t)n * Ltot * 64 + dp;
    #pragma unroll
    for (int i = 0; i < 8; i++) {
        int l = l0 + i;
        float2 x3 = src[(size_t)l * 64];
        float sa = bb.x + wA.x * x0.x + wA.y * x1.x + wA.z * x2.x + wA.w * x3.x;
        float sb2 = bb.y + wB.x * x0.y + wB.y * x1.y + wB.z * x2.y + wB.w * x3.y;
        sa = sa / (1.f + __expf(-sa));
        sb2 = sb2 / (1.f + __expf(-sb2));
        dstf[(size_t)l * 64] = make_float2(sa, sb2);
        unsigned h2, l2; split2(sa, sb2, h2, l2);
        dsti[(size_t)l * 64] = make_uint2(h2, l2);
        x0 = x1; x1 = x2; x2 = x3;
    }
}

// ---------------- kernel 4: fused x_proj+dt_proj (double-buffered) + transposed epilogue ----------------
__global__ void k_xproj(const float* __restrict__ dtb) {
    extern __shared__ __align__(16) char smem[];
    unsigned sb = (unsigned)__cvta_generic_to_shared(smem);
    float* smT = (float*)smem;
    int tid = threadIdx.x;
    int m0 = blockIdx.x * 128, n0 = blockIdx.y * 64;
    int warp = tid >> 5, lane = tid & 31, g = lane >> 2, t = lane & 3;
    int mb = (warp & 3) * 32, nb = (warp >> 2) * 32;
    float acc[2][4][4] = {};
    issueA(sb, g_xc_i, 64, m0, 0, tid);
    issueB(sb + ABUF_BYTES, g_wx_i, 64, n0, 0, 160, tid);
    CPCOMMIT();
    #pragma unroll
    for (int sl = 0; sl < 4; sl++) {
        unsigned buf = (sl & 1) * STAGE_BYTES;
        if (sl + 1 < 4) {
            unsigned nbuf = ((sl + 1) & 1) * STAGE_BYTES;
            issueA(sb + nbuf, g_xc_i, 64, m0, (sl + 1) * 16, tid);
            issueB(sb + nbuf + ABUF_BYTES, g_wx_i, 64, n0, (sl + 1) * 16, 160, tid);
            CPCOMMIT();
            CPWAIT(1);
        } else {
            CPWAIT(0);
        }
        __syncthreads();
        mma_slab((uint2*)(smem + buf), (uint2*)(smem + buf + ABUF_BYTES), acc, mb, nb, g, t);
        __syncthreads();
    }
    int n = m0 >> 12, l0 = m0 & 4095;
    if (blockIdx.y < 2) {
        #pragma unroll
        for (int i = 0; i < 2; i++) {
            int rowL = mb + 16 * i + g;
            #pragma unroll
            for (int j = 0; j < 4; j++) {
                int colL = nb + 8 * j + 2 * t;
                float b0 = dtb[n0 + colL], b1 = dtb[n0 + colL + 1];
                float t0 = acc[i][j][0] + b0, t1 = acc[i][j][1] + b1;
                float t2 = acc[i][j][2] + b0, t3 = acc[i][j][3] + b1;
                acc[i][j][0] = (t0 > 20.f) ? t0 : log1pf(__expf(t0));
                acc[i][j][1] = (t1 > 20.f) ? t1 : log1pf(__expf(t1));
                acc[i][j][2] = (t2 > 20.f) ? t2 : log1pf(__expf(t2));
                acc[i][j][3] = (t3 > 20.f) ? t3 : log1pf(__expf(t3));
                smT[colL * 132 + rowL]           = acc[i][j][0];
                smT[(colL + 1) * 132 + rowL]     = acc[i][j][1];
                smT[colL * 132 + rowL + 8]       = acc[i][j][2];
                smT[(colL + 1) * 132 + rowL + 8] = acc[i][j][3];
            }
        }
        __syncthreads();
        #pragma unroll
        for (int k = 0; k < 8; k++) {
            int dL = warp * 8 + k;
            float4 v = *(float4*)&smT[dL * 132 + 4 * lane];
            *(float4*)(g_dtT + ((size_t)(n * 128 + n0 + dL)) * 4096 + l0 + 4 * lane) = v;
        }
        __syncthreads();
        #pragma unroll
        for (int i = 0; i < 2; i++) {
            int rowL = mb + 16 * i + g;
            #pragma unroll
            for (int j = 0; j < 4; j++) {
                int colL = nb + 8 * j + 2 * t;
                float2 u0 = *(const float2*)(g_xc + (size_t)(m0 + rowL) * 128 + n0 + colL);
                float2 u1 = *(const float2*)(g_xc + (size_t)(m0 + rowL + 8) * 128 + n0 + colL);
                smT[colL * 132 + rowL]           = acc[i][j][0] * u0.x;
                smT[(colL + 1) * 132 + rowL]     = acc[i][j][1] * u0.y;
                smT[colL * 132 + rowL + 8]       = acc[i][j][2] * u1.x;
                smT[(colL + 1) * 132 + rowL + 8] = acc[i][j][3] * u1.y;
            }
        }
        __syncthreads();
        #pragma unroll
        for (int k = 0; k < 8; k++) {
            int dL = warp * 8 + k;
            float4 v = *(float4*)&smT[dL * 132 + 4 * lane];
            *(float4*)(g_PT + ((size_t)(n * 128 + n0 + dL)) * 4096 + l0 + 4 * lane) = v;
        }
    } else {
        if (nb == 0) {
            #pragma unroll
            for (int i = 0; i < 2; i++) {
                int rowL = mb + 16 * i + g;
                #pragma unroll
                for (int j = 0; j < 4; j++) {
                    int colL = 8 * j + 2 * t;
                    smT[colL * 132 + rowL]           = acc[i][j][0];
                    smT[(colL + 1) * 132 + rowL]     = acc[i][j][1];
                    smT[colL * 132 + rowL + 8]       = acc[i][j][2];
                    smT[(colL + 1) * 132 + rowL + 8] = acc[i][j][3];
                }
            }
        }
        __syncthreads();
        #pragma unroll
        for (int k = 0; k < 4; k++) {
            int sRow = warp * 4 + k;
            float4 v = *(float4*)&smT[sRow * 132 + 4 * lane];
            if (sRow < 16)
                *(float4*)(g_BmT + ((size_t)(n * 16 + sRow)) * 4096 + l0 + 4 * lane) = v;
            else
                *(float4*)(g_CmT + ((size_t)(n * 16 + sRow - 16)) * 4096 + l0 + 4 * lane) = v;
        }
    }
}

// ---------------- kernel 5a: chunk-local scan ----------------
__global__ void k_scanA(const float* __restrict__ Alog) {
    int c = blockIdx.x, n = blockIdx.y, d = threadIdx.x;
    __shared__ float sBt[16 * 64];
    #pragma unroll
    for (int k = 0; k < 2; k++) {
        int f = threadIdx.x + k * 128, s = f >> 4, tq = f & 15;
        *(float4*)&sBt[s * 64 + 4 * tq] =
            __ldg((const float4*)(g_BmT + ((size_t)(n * 16 + s)) * 4096 + c * 64 + 4 * tq));
    }
    __syncthreads();
    float a[16], h[16];
    #pragma unroll
    for (int s = 0; s < 16; s++) { a[s] = -__expf(__ldg(Alog + d * 16 + s)); h[s] = 0.f; }
    float sd = 0.f;
    const float4* dt4 = (const float4*)(g_dtT + ((size_t)(n * 128 + d)) * 4096 + c * 64);
    const float4* P4  = (const float4*)(g_PT  + ((size_t)(n * 128 + d)) * 4096 + c * 64);
    for (int q = 0; q < 16; q++) {
        float4 dtv = __ldg(dt4 + q), Pv = __ldg(P4 + q);
        float dts[4] = {dtv.x, dtv.y, dtv.z, dtv.w};
        float Ps[4]  = {Pv.x,  Pv.y,  Pv.z,  Pv.w};
        #pragma unroll
        for (int e = 0; e < 4; e++) {
            float dt = dts[e], P = Ps[e];
            sd += dt;
            const float* Bp = &sBt[4 * q + e];
            #pragma unroll
            for (int s = 0; s < 16; s++)
                h[s] = __expf(dt * a[s]) * h[s] + P * Bp[s * 64];
        }
    }
    float* oA = g_Ac + (((size_t)(n * 128 + d)) * 64 + c) * 16;
    float* oB = g_bc + (((size_t)(n * 128 + d)) * 64 + c) * 16;
    #pragma unroll
    for (int q = 0; q < 4; q++) {
        *(float4*)(oA + 4 * q) = make_float4(__expf(a[4*q] * sd), __expf(a[4*q+1] * sd),
                                             __expf(a[4*q+2] * sd), __expf(a[4*q+3] * sd));
        *(float4*)(oB + 4 * q) = make_float4(h[4*q], h[4*q+1], h[4*q+2], h[4*q+3]);
    }
}

// ---------------- kernel 5b: combine chunk summaries ----------------
__global__ void k_scanB() {
    int tid = blockIdx.x * blockDim.x + threadIdx.x;
    int n = tid >> 11, rem = tid & 2047;
    int d = rem >> 4, s = rem & 15;
    size_t base = ((size_t)(n * 128 + d)) * NCH * DS + s;
    float h = 0.f;
    float A0 = __ldg(g_Ac + base), b0 = __ldg(g_bc + base);
    #pragma unroll 8
    for (int c = 0; c < NCH; c++) {
        float A1 = 0.f, b1 = 0.f;
        if (c + 1 < NCH) {
            A1 = __ldg(g_Ac + base + (c + 1) * DS);
            b1 = __ldg(g_bc + base + (c + 1) * DS);
        }
        g_hin[base + c * DS] = h;
        h = A0 * h + b0;
        A0 = A1; b0 = b1;
    }
}

// ---------------- kernel 5c: replay with h_in, emit y^T ----------------
__global__ void k_scanC(const float* __restrict__ Alog) {
    int c = blockIdx.x, n = blockIdx.y, d = threadIdx.x;
    __shared__ float sBt[16 * 64];
    __shared__ float sCt[16 * 64];
    #pragma unroll
    for (int k = 0; k < 2; k++) {
        int f = threadIdx.x + k * 128, s = f >> 4, tq = f & 15;
        *(float4*)&sBt[s * 64 + 4 * tq] =
            __ldg((const float4*)(g_BmT + ((size_t)(n * 16 + s)) * 4096 + c * 64 + 4 * tq));
        *(float4*)&sCt[s * 64 + 4 * tq] =
            __ldg((const float4*)(g_CmT + ((size_t)(n * 16 + s)) * 4096 + c * 64 + 4 * tq));
    }
    __syncthreads();
    float a[16], h[16];
    #pragma unroll
    for (int s = 0; s < 16; s++) a[s] = -__expf(__ldg(Alog + d * 16 + s));
    const float* hi = g_hin + (((size_t)(n * 128 + d)) * 64 + c) * 16;
    #pragma unroll
    for (int q = 0; q < 4; q++) {
        float4 v = __ldg((const float4*)(hi + 4 * q));
        h[4*q] = v.x; h[4*q+1] = v.y; h[4*q+2] = v.z; h[4*q+3] = v.w;
    }
    const float4* dt4 = (const float4*)(g_dtT + ((size_t)(n * 128 + d)) * 4096 + c * 64);
    const float4* P4  = (const float4*)(g_PT  + ((size_t)(n * 128 + d)) * 4096 + c * 64);
    float4* yp = (float4*)(g_ysT + ((size_t)(n * 128 + d)) * 4096 + c * 64);
    for (int q = 0; q < 16; q++) {
        float4 dtv = __ldg(dt4 + q), Pv = __ldg(P4 + q);
        float dts[4] = {dtv.x, dtv.y, dtv.z, dtv.w};
        float Ps[4]  = {Pv.x,  Pv.y,  Pv.z,  Pv.w};
        float yv[4];
        #pragma unroll
        for (int e = 0; e < 4; e++) {
            float dt = dts[e], P = Ps[e];
            const float* Bp = &sBt[4 * q + e];
            const float* Cp = &sCt[4 * q + e];
            float y = 0.f;
            #pragma unroll
            for (int s = 0; s < 16; s++) {
                h[s] = __expf(dt * a[s]) * h[s] + P * Bp[s * 64];
                y += h[s] * Cp[s * 64];
            }
            yv[e] = y;
        }
        yp[q] = make_float4(yv[0], yv[1], yv[2], yv[3]);
    }
}

// ---------------- kernel 6: gate + out_proj + residual ----------------
__global__ void k_outproj(const float* __restrict__ Dp, const float* __restrict__ skip) {
    __shared__ uint2 sA[128 * SPADA];
    __shared__ uint2 sB[64 * SPADA];
    int tid = threadIdx.x;
    int m0 = blockIdx.x * 128;
    int nn = m0 >> 12, l0 = m0 & 4095;
    int warp = tid >> 5, lane = tid & 31, g = lane >> 2, t = lane & 3;
    int mb = (warp & 3) * 32, nb = (warp >> 2) * 32;
    float acc[2][4][4] = {};
    #pragma unroll
    for (int sl = 0; sl < 4; sl++) {
        int k0 = sl * 32;
        #pragma unroll
        for (int it = 0; it < 4; it++) {
            int idx = tid + it * 256;
            int row = idx >> 3, c4 = (idx & 7) * 4;
            size_t off = (size_t)(m0 + row) * 128 + k0 + c4;
            float ys0 = __ldg(g_ysT + ((size_t)(nn * 128 + k0 + c4 + 0)) * 4096 + l0 + row);
            float ys1 = __ldg(g_ysT + ((size_t)(nn * 128 + k0 + c4 + 1)) * 4096 + l0 + row);
            float ys2 = __ldg(g_ysT + ((size_t)(nn * 128 + k0 + c4 + 2)) * 4096 + l0 + row);
            float ys3 = __ldg(g_ysT + ((size_t)(nn * 128 + k0 + c4 + 3)) * 4096 + l0 + row);
            float4 xc = *(const float4*)(g_xc + off);
            float4 zz = *(const float4*)(g_z + off);
            float4 dp = *(const float4*)(Dp + k0 + c4);
            float a0 = (ys0 + xc.x * dp.x) * (zz.x / (1.f + __expf(-zz.x)));
            float a1 = (ys1 + xc.y * dp.y) * (zz.y / (1.f + __expf(-zz.y)));
            float a2 = (ys2 + xc.z * dp.z) * (zz.z / (1.f + __expf(-zz.z)));
            float a3 = (ys3 + xc.w * dp.w) * (zz.w / (1.f + __expf(-zz.w)));
            unsigned h0, lo0, h1, lo1;
            split2(a0, a1, h0, lo0); split2(a2, a3, h1, lo1);
            *(uint4*)(sA + row * SPADA + (c4 >> 1)) = make_uint4(h0, lo0, h1, lo1);
        }
        // B tile from interleaved weights
        {
            int row = tid >> 2, q = (tid & 3) * 4;
            const uint2* src = g_wo_i + (size_t)row * 64 + sl * 16 + q;
            uint4 v0 = *(const uint4*)src;
            uint4 v1 = *(const uint4*)(src + 2);
            *(uint4*)(sB + row * SPADA + q)     = v0;
            *(uint4*)(sB + row * SPADA + q + 2) = v1;
        }
        __syncthreads();
        mma_slab(sA, sB, acc, mb, nb, g, t);
        __syncthreads();
    }
    float sk = skip[0];
    #pragma unroll
    for (int i = 0; i < 2; i++) {
        int row = m0 + mb + 16 * i + g;
        #pragma unroll
        for (int j = 0; j < 4; j++) {
            int col = nb + 8 * j + 2 * t;
            float2 xa = rec2(g_xn_i[(size_t)row * 32 + (col >> 1)]);
            float2 xb = rec2(g_xn_i[(size_t)(row + 8) * 32 + (col >> 1)]);
            *(float2*)(g_ym + (size_t)row * 64 + col) =
                make_float2(acc[i][j][0] + sk * xa.x, acc[i][j][1] + sk * xa.y);
            *(float2*)(g_ym + (size_t)(row + 8) * 64 + col) =
                make_float2(acc[i][j][2] + sk * xb.x, acc[i][j][3] + sk * xb.y);
        }
    }
}

// ---------------- kernel 7: LN2 + chunk gather ----------------
__global__ void k_ln2(const float* __restrict__ g, const float* __restrict__ bta) {
    int warp = (blockIdx.x * blockDim.x + threadIdx.x) >> 5;
    int lane = threadIdx.x & 31;
    int bb = warp >> 12, l = warp & 4095;
    int c0 = lane * 8;
    int chunk = lane >> 3;
    const float4* src = (const float4*)(g_ym + ((size_t)((chunk * 8 + bb) * Ltot + l)) * 64 + (c0 & 63));
    float4 v0 = src[0], v1 = src[1];
    float s = v0.x + v0.y + v0.z + v0.w + v1.x + v1.y + v1.z + v1.w;
    float s2 = v0.x*v0.x + v0.y*v0.y + v0.z*v0.z + v0.w*v0.w
             + v1.x*v1.x + v1.y*v1.y + v1.z*v1.z + v1.w*v1.w;
    #pragma unroll
    for (int o = 16; o; o >>= 1) {
        s  += __shfl_xor_sync(0xffffffffu, s, o);
        s2 += __shfl_xor_sync(0xffffffffu, s2, o);
    }
    float mu = s * (1.f / 256.f);
    float var = s2 * (1.f / 256.f) - mu * mu;
    float rs = rsqrtf(var + 1e-5f);
    float y[8] = {v0.x, v0.y, v0.z, v0.w, v1.x, v1.y, v1.z, v1.w};
    #pragma unroll
    for (int k = 0; k < 8; k++) y[k] = (y[k] - mu) * rs * g[c0 + k] + bta[c0 + k];
    unsigned h[4], lo[4];
    split2(y[0], y[1], h[0], lo[0]); split2(y[2], y[3], h[1], lo[1]);
    split2(y[4], y[5], h[2], lo[2]); split2(y[6], y[7], h[3], lo[3]);
    size_t base = ((size_t)(bb * Ltot + l)) * 128 + lane * 4;
    *(uint4*)(g_x2_i + base)     = make_uint4(h[0], lo[0], h[1], lo[1]);
    *(uint4*)(g_x2_i + base + 2) = make_uint4(h[2], lo[2], h[3], lo[3]);
}

// ---------------- kernel 8: final proj (double-buffered, 8 slabs) ----------------
__global__ void k_final(const float* __restrict__ pb, float* __restrict__ out) {
    extern __shared__ __align__(16) char smem[];
    unsigned sb = (unsigned)__cvta_generic_to_shared(smem);
    int tid = threadIdx.x;
    int m0 = blockIdx.x * 128, n0 = blockIdx.y * 64;
    int warp = tid >> 5, lane = tid & 31, g = lane >> 2, t = lane & 3;
    int mb = (warp & 3) * 32, nb = (warp >> 2) * 32;
    float acc[2][4][4] = {};
    issueA(sb, g_x2_i, 128, m0, 0, tid);
    issueB(sb + ABUF_BYTES, g_wp_i, 128, n0, 0, 256, tid);
    CPCOMMIT();
    #pragma unroll
    for (int sl = 0; sl < 8; sl++) {
        unsigned buf = (sl & 1) * STAGE_BYTES;
        if (sl + 1 < 8) {
            unsigned nbuf = ((sl + 1) & 1) * STAGE_BYTES;
            issueA(sb + nbuf, g_x2_i, 128, m0, (sl + 1) * 16, tid);
            issueB(sb + nbuf + ABUF_BYTES, g_wp_i, 128, n0, (sl + 1) * 16, 256, tid);
            CPCOMMIT();
            CPWAIT(1);
        } else {
            CPWAIT(0);
        }
        __syncthreads();
        mma_slab((uint2*)(smem + buf), (uint2*)(smem + buf + ABUF_BYTES), acc, mb, nb, g, t);
        __syncthreads();
    }
    #pragma unroll
    for (int i = 0; i < 2; i++) {
        int row = m0 + mb + 16 * i + g;
        int bbat = row >> 12, l = row & 4095;
        int l2 = (row + 8) & 4095;
        #pragma unroll
        for (int j = 0; j < 4; j++) {
            int col = n0 + nb + 8 * j + 2 * t;
            out[(size_t)(bbat * 256 + col) * Ltot + l]      = acc[i][j][0] + pb[col];
            out[(size_t)(bbat * 256 + col + 1) * Ltot + l]  = acc[i][j][1] + pb[col + 1];
            out[(size_t)(bbat * 256 + col) * Ltot + l2]     = acc[i][j][2] + pb[col];
            out[(size_t)(bbat * 256 + col + 1) * Ltot + l2] = acc[i][j][3] + pb[col + 1];
        }
    }
}

// ---------------- launch ----------------
extern "C" void kernel_launch(void* const* d_in, const int* in_sizes, int n_in,
                              void* d_out, int out_size) {
    const float* x      = (const float*)d_in[0];
    const float* ln_g   = (const float*)d_in[1];
    const float* ln_b   = (const float*)d_in[2];
    const float* inpw   = (const float*)d_in[3];
    const float* convw  = (const float*)d_in[4];
    const float* convb  = (const float*)d_in[5];
    const float* xpw    = (const float*)d_in[6];
    const float* dtw    = (const float*)d_in[7];
    const float* dtb    = (const float*)d_in[8];
    const float* Alog   = (const float*)d_in[9];
    const float* Dp     = (const float*)d_in[10];
    const float* outw   = (const float*)d_in[11];
    const float* projw  = (const float*)d_in[12];
    const float* projb  = (const float*)d_in[13];
    const float* skip   = (const float*)d_in[14];
    float* out = (float*)d_out;

    const int DBUF = 2 * STAGE_BYTES;   // 61440
    cudaFuncSetAttribute(k_inproj, cudaFuncAttributeMaxDynamicSharedMemorySize, DBUF);
    cudaFuncSetAttribute(k_xproj,  cudaFuncAttributeMaxDynamicSharedMemorySize, DBUF);
    cudaFuncSetAttribute(k_final,  cudaFuncAttributeMaxDynamicSharedMemorySize, DBUF);

    k_ln1<<<4096 + 16, 256>>>(x, ln_g, ln_b, dtw, xpw, inpw, outw, projw);   // (1)
    k_inproj<<<dim3(1024, 4), 256, DBUF>>>();                                 // (2)
    k_conv<<<4096, 256>>>(convw, convb);                                      // (3)
    k_xproj<<<dim3(1024, 3), 256, DBUF>>>(dtb);                               // (4) profiled
    k_scanA<<<dim3(NCH, Nseq), 128>>>(Alog);                                  // (5)
    k_scanB<<<256, 256>>>();                                                  // (6)
    k_scanC<<<dim3(NCH, Nseq), 128>>>(Alog);                                  // (7)
    k_outproj<<<1024, 256>>>(Dp, skip);                                       // (8)
    k_ln2<<<4096, 256>>>(ln_g, ln_b);                                         // (9)
    k_final<<<dim3(256, 4), 256, DBUF>>>(projb, out);                         // (10)
}

// round 7
// speedup vs baseline: 3.3578x; 1.0995x over previous
#include <cuda_runtime.h>
#include <math.h>

#define Bb    8
#define Cc    256
#define Ltot  4096
#define DS    16
#define DI    128
#define Nseq  32
#define Mrow  (Nseq*Ltot)   // 131072
#define M2    (Bb*Ltot)     // 32768
#define NCH   64
#define CL    64

// ---------------- fp32 scratch ----------------
__device__ __align__(16) float g_xin [Mrow*DI];
__device__ __align__(16) float g_z   [Mrow*DI];
__device__ __align__(16) float g_xc  [Mrow*DI];
__device__ __align__(16) float g_ym  [Mrow*64];
__device__ __align__(16) float g_dtT [Nseq*DI*Ltot];
__device__ __align__(16) float g_PT  [Nseq*DI*Ltot];
__device__ __align__(16) float g_BmT [Nseq*DS*Ltot];
__device__ __align__(16) float g_CmT [Nseq*DS*Ltot];
__device__ __align__(16) float g_ysT [Nseq*DI*Ltot];
__device__ __align__(16) float g_Ac [Nseq*DI*NCH*DS];
__device__ __align__(16) float g_bc [Nseq*DI*NCH*DS];
__device__ __align__(16) float g_hin[Nseq*DI*NCH*DS];

// ---------------- interleaved bf16 hi/lo planes: uint2{h2,l2} per k-pair ----------------
__device__ __align__(16) uint2 g_xn_i[Mrow*32];
__device__ __align__(16) uint2 g_xc_i[Mrow*64];
__device__ __align__(16) uint2 g_x2_i[M2*128];
__device__ __align__(16) uint2 g_wi_i[256*32];
__device__ __align__(16) uint2 g_wx_i[160*64];
__device__ __align__(16) uint2 g_wo_i[64*64];
__device__ __align__(16) uint2 g_wp_i[256*128];

__device__ __forceinline__ void split2(float x0, float x1, unsigned &h2, unsigned &l2) {
    asm("cvt.rn.bf16x2.f32 %0,%1,%2;" : "=r"(h2) : "f"(x1), "f"(x0));
    float hf0 = __uint_as_float(h2 << 16);
    float hf1 = __uint_as_float(h2 & 0xffff0000u);
    asm("cvt.rn.bf16x2.f32 %0,%1,%2;" : "=r"(l2) : "f"(x1 - hf1), "f"(x0 - hf0));
}
__device__ __forceinline__ float2 rec2(uint2 v) {
    return make_float2(__uint_as_float(v.x << 16) + __uint_as_float(v.y << 16),
                       __uint_as_float(v.x & 0xffff0000u) + __uint_as_float(v.y & 0xffff0000u));
}

#define MMA_BF16(d,a0,a1,a2,a3,b0,b1) asm volatile( \
  "mma.sync.aligned.m16n8k16.row.col.f32.bf16.bf16.f32 {%0,%1,%2,%3},{%4,%5,%6,%7},{%8,%9},{%0,%1,%2,%3};" \
  : "+f"(d[0]),"+f"(d[1]),"+f"(d[2]),"+f"(d[3]) \
  : "r"(a0),"r"(a1),"r"(a2),"r"(a3),"r"(b0),"r"(b1))

#define SPADA 20
#define STAGE_BYTES ((128 + 64) * SPADA * 8)   // 30720
#define ABUF_BYTES  (128 * SPADA * 8)          // 20480

#define CPA(dst,src,sz) asm volatile("cp.async.cg.shared.global [%0],[%1],16,%2;"::"r"(dst),"l"(src),"r"(sz))
#define CPCOMMIT()      asm volatile("cp.async.commit_group;")
#define CPWAIT(n)       asm volatile("cp.async.wait_group %0;"::"n"(n))

__device__ __forceinline__ void issueA(unsigned sb, const uint2* __restrict__ plane,
                                       int ldu, int m0, int kp0, int tid) {
    #pragma unroll
    for (int it = 0; it < 4; it++) {
        int idx = it * 256 + tid;
        int row = idx >> 3, ch = idx & 7;
        unsigned dst = sb + (row * SPADA + ch * 2) * 8;
        const uint2* src = plane + (size_t)(m0 + row) * ldu + kp0 + ch * 2;
        CPA(dst, src, 16);
    }
}
__device__ __forceinline__ void issueB(unsigned sb, const uint2* __restrict__ plane,
                                       int ldu, int n0, int kp0, int nmax, int tid) {
    #pragma unroll
    for (int it = 0; it < 2; it++) {
        int idx = it * 256 + tid;
        int row = idx >> 3, ch = idx & 7;
        unsigned dst = sb + (row * SPADA + ch * 2) * 8;
        const uint2* src = plane + (size_t)(n0 + row) * ldu + kp0 + ch * 2;
        int sz = (n0 + row < nmax) ? 16 : 0;
        CPA(dst, src, sz);
    }
}

// 3-term bf16 mainloop, term-major MMA issue (breaks acc RAW chains)
__device__ __forceinline__ void mma_slab(const uint2* __restrict__ sA, const uint2* __restrict__ sB,
                                         float acc[2][4][4], int mb, int nb, int g, int t) {
    #pragma unroll
    for (int ks = 0; ks < 2; ks++) {
        int kp = ks * 8 + t;
        unsigned ah[2][4], al[2][4];
        #pragma unroll
        for (int i = 0; i < 2; i++) {
            const uint2* p = sA + (mb + 16 * i + g) * SPADA + kp;
            uint2 v0 = p[0], v1 = p[8 * SPADA], v2 = p[4], v3 = p[8 * SPADA + 4];
            ah[i][0] = v0.x; al[i][0] = v0.y;
            ah[i][1] = v1.x; al[i][1] = v1.y;
            ah[i][2] = v2.x; al[i][2] = v2.y;
            ah[i][3] = v3.x; al[i][3] = v3.y;
        }
        unsigned bh[4][2], bl[4][2];
        #pragma unroll
        for (int j = 0; j < 4; j++) {
            const uint2* p = sB + (nb + 8 * j + g) * SPADA + kp;
            uint2 w0 = p[0], w1 = p[4];
            bh[j][0] = w0.x; bh[j][1] = w1.x;
            bl[j][0] = w0.y; bl[j][1] = w1.y;
        }
        #pragma unroll
        for (int j = 0; j < 4; j++)
            #pragma unroll
            for (int i = 0; i < 2; i++)
                MMA_BF16(acc[i][j], ah[i][0], ah[i][1], ah[i][2], ah[i][3], bh[j][0], bh[j][1]);
        #pragma unroll
        for (int j = 0; j < 4; j++)
            #pragma unroll
            for (int i = 0; i < 2; i++)
                MMA_BF16(acc[i][j], ah[i][0], ah[i][1], ah[i][2], ah[i][3], bl[j][0], bl[j][1]);
        #pragma unroll
        for (int j = 0; j < 4; j++)
            #pragma unroll
            for (int i = 0; i < 2; i++)
                MMA_BF16(acc[i][j], al[i][0], al[i][1], al[i][2], al[i][3], bh[j][0], bh[j][1]);
    }
}

// ---------------- kernel 1: LN1 + chunk rearrange (+ fused weight prep) ----------------
__global__ void k_ln1(const float* __restrict__ x, const float* __restrict__ g,
                      const float* __restrict__ bta,
                      const float* __restrict__ dtw, const float* __restrict__ xpw,
                      const float* __restrict__ inpw, const float* __restrict__ outw,
                      const float* __restrict__ projw) {
    if (blockIdx.x >= 4096) {
        for (int idx = (blockIdx.x - 4096) * 256 + threadIdx.x; idx < 55296; idx += 16 * 256) {
            float x0, x1;
            uint2* dst;
            if (idx < 8192) {
                int r = idx >> 5, kp = idx & 31;
                x0 = inpw[r * 64 + 2 * kp]; x1 = inpw[r * 64 + 2 * kp + 1];
                dst = g_wi_i + idx;
            } else if (idx < 18432) {
                int j = idx - 8192; int r = j >> 6, kp = j & 63, k = 2 * kp;
                if (r < 128) {
                    float s0 = 0.f, s1 = 0.f;
                    #pragma unroll
                    for (int q = 0; q < 4; q++) {
                        float w = dtw[r * 4 + q];
                        s0 += w * xpw[q * 128 + k];
                        s1 += w * xpw[q * 128 + k + 1];
                    }
                    x0 = s0; x1 = s1;
                } else {
                    x0 = xpw[(4 + r - 128) * 128 + k]; x1 = xpw[(4 + r - 128) * 128 + k + 1];
                }
                dst = g_wx_i + j;
            } else if (idx < 22528) {
                int j = idx - 18432; int r = j >> 6, kp = j & 63;
                x0 = outw[r * 128 + 2 * kp]; x1 = outw[r * 128 + 2 * kp + 1];
                dst = g_wo_i + j;
            } else {
                int j = idx - 22528; int r = j >> 7, kp = j & 127;
                x0 = projw[r * 256 + 2 * kp]; x1 = projw[r * 256 + 2 * kp + 1];
                dst = g_wp_i + j;
            }
            unsigned h2, l2; split2(x0, x1, h2, l2);
            *dst = make_uint2(h2, l2);
        }
        return;
    }
    int warp = (blockIdx.x * blockDim.x + threadIdx.x) >> 5;
    int lane = threadIdx.x & 31;
    int bb = warp >> 12, l = warp & 4095;
    const float* xp = x + (size_t)bb * Cc * Ltot + l;
    float v[8]; float s = 0.f, s2 = 0.f;
    int c0 = lane * 8;
    #pragma unroll
    for (int k = 0; k < 8; k++) {
        float t = xp[(size_t)(c0 + k) * Ltot];
        v[k] = t; s += t; s2 += t * t;
    }
    #pragma unroll
    for (int o = 16; o; o >>= 1) {
        s  += __shfl_xor_sync(0xffffffffu, s, o);
        s2 += __shfl_xor_sync(0xffffffffu, s2, o);
    }
    float mu = s * (1.f / 256.f);
    float var = s2 * (1.f / 256.f) - mu * mu;
    float rs = rsqrtf(var + 1e-5f);
    float y[8];
    #pragma unroll
    for (int k = 0; k < 8; k++) y[k] = (v[k] - mu) * rs * g[c0 + k] + bta[c0 + k];
    int chunk = lane >> 3;
    size_t base = ((size_t)((chunk * 8 + bb) * Ltot + l)) * 32 + (lane & 7) * 4;
    unsigned h[4], lo[4];
    split2(y[0], y[1], h[0], lo[0]); split2(y[2], y[3], h[1], lo[1]);
    split2(y[4], y[5], h[2], lo[2]); split2(y[6], y[7], h[3], lo[3]);
    *(uint4*)(g_xn_i + base)     = make_uint4(h[0], lo[0], h[1], lo[1]);
    *(uint4*)(g_xn_i + base + 2) = make_uint4(h[2], lo[2], h[3], lo[3]);
}

// ---------------- kernel 2: in_proj (grid = (ntile, mtile)) ----------------
__global__ void __launch_bounds__(256, 3) k_inproj() {
    extern __shared__ __align__(16) char smem[];
    unsigned sb = (unsigned)__cvta_generic_to_shared(smem);
    int tid = threadIdx.x;
    int m0 = blockIdx.y * 128, n0 = blockIdx.x * 64;
    int warp = tid >> 5, lane = tid & 31, g = lane >> 2, t = lane & 3;
    int mb = (warp & 3) * 32, nb = (warp >> 2) * 32;
    float acc[2][4][4] = {};
    issueA(sb, g_xn_i, 32, m0, 0, tid);
    issueB(sb + ABUF_BYTES, g_wi_i, 32, n0, 0, 256, tid);
    CPCOMMIT();
    #pragma unroll
    for (int sl = 0; sl < 2; sl++) {
        unsigned buf = (sl & 1) * STAGE_BYTES;
        if (sl + 1 < 2) {
            unsigned nbuf = ((sl + 1) & 1) * STAGE_BYTES;
            issueA(sb + nbuf, g_xn_i, 32, m0, (sl + 1) * 16, tid);
            issueB(sb + nbuf + ABUF_BYTES, g_wi_i, 32, n0, (sl + 1) * 16, 256, tid);
            CPCOMMIT();
            CPWAIT(1);
        } else {
            CPWAIT(0);
        }
        __syncthreads();
        mma_slab((uint2*)(smem + buf), (uint2*)(smem + buf + ABUF_BYTES), acc, mb, nb, g, t);
        __syncthreads();
    }
    float* dst = (blockIdx.x < 2) ? g_xin : g_z;
    int nbase = n0 - ((blockIdx.x < 2) ? 0 : 128) + nb;
    #pragma unroll
    for (int i = 0; i < 2; i++) {
        int row = m0 + mb + 16 * i + g;
        #pragma unroll
        for (int j = 0; j < 4; j++) {
            int col = nbase + 8 * j + 2 * t;
            *(float2*)(dst + (size_t)row * 128 + col)       = make_float2(acc[i][j][0], acc[i][j][1]);
            *(float2*)(dst + (size_t)(row + 8) * 128 + col) = make_float2(acc[i][j][2], acc[i][j][3]);
        }
    }
}

// ---------------- kernel 3: conv + silu ----------------
__global__ void k_conv(const float* __restrict__ cw, const float* __restrict__ cb) {
    int tid = threadIdx.x;
    int dp = tid & 63;
    int lq = tid >> 6;
    int n = blockIdx.x >> 7;
    int l0 = (blockIdx.x & 127) * 32 + lq * 8;
    const float2* src = (const float2*)(g_xin + (size_t)n * Ltot * DI) + dp;
    float4 wA = *(const float4*)(cw + 8 * dp);
    float4 wB = *(const float4*)(cw + 8 * dp + 4);
    float2 bb = *(const float2*)(cb + 2 * dp);
    float2 x0 = (l0 >= 3) ? src[(size_t)(l0 - 3) * 64] : make_float2(0.f, 0.f);
    float2 x1 = (l0 >= 2) ? src[(size_t)(l0 - 2) * 64] : make_float2(0.f, 0.f);
    float2 x2 = (l0 >= 1) ? src[(size_t)(l0 - 1) * 64] : make_float2(0.f, 0.f);
    float2* dstf = (float2*)(g_xc + (size_t)n * Ltot * DI) + dp;
    uint2* dsti = g_xc_i + (size_t)n * Ltot * 64 + dp;
    #pragma unroll
    for (int i = 0; i < 8; i++) {
        int l = l0 + i;
        float2 x3 = src[(size_t)l * 64];
        float sa = bb.x + wA.x * x0.x + wA.y * x1.x + wA.z * x2.x + wA.w * x3.x;
        float sb2 = bb.y + wB.x * x0.y + wB.y * x1.y + wB.z * x2.y + wB.w * x3.y;
        sa = sa / (1.f + __expf(-sa));
        sb2 = sb2 / (1.f + __expf(-sb2));
        dstf[(size_t)l * 64] = make_float2(sa, sb2);
        unsigned h2, l2; split2(sa, sb2, h2, l2);
        dsti[(size_t)l * 64] = make_uint2(h2, l2);
        x0 = x1; x1 = x2; x2 = x3;
    }
}

// ---------------- kernel 4: fused x_proj+dt_proj (grid=(3,1024)) + transposed epilogue ----------------
__global__ void __launch_bounds__(256, 3) k_xproj(const float* __restrict__ dtb) {
    extern __shared__ __align__(16) char smem[];
    unsigned sb = (unsigned)__cvta_generic_to_shared(smem);
    float* smT = (float*)smem;
    int tid = threadIdx.x;
    int m0 = blockIdx.y * 128, n0 = blockIdx.x * 64;
    int warp = tid >> 5, lane = tid & 31, g = lane >> 2, t = lane & 3;
    int mb = (warp & 3) * 32, nb = (warp >> 2) * 32;
    float acc[2][4][4] = {};
    issueA(sb, g_xc_i, 64, m0, 0, tid);
    issueB(sb + ABUF_BYTES, g_wx_i, 64, n0, 0, 160, tid);
    CPCOMMIT();
    #pragma unroll
    for (int sl = 0; sl < 4; sl++) {
        unsigned buf = (sl & 1) * STAGE_BYTES;
        if (sl + 1 < 4) {
            unsigned nbuf = ((sl + 1) & 1) * STAGE_BYTES;
            issueA(sb + nbuf, g_xc_i, 64, m0, (sl + 1) * 16, tid);
            issueB(sb + nbuf + ABUF_BYTES, g_wx_i, 64, n0, (sl + 1) * 16, 160, tid);
            CPCOMMIT();
            CPWAIT(1);
        } else {
            CPWAIT(0);
        }
        __syncthreads();
        mma_slab((uint2*)(smem + buf), (uint2*)(smem + buf + ABUF_BYTES), acc, mb, nb, g, t);
        __syncthreads();
    }
    int n = m0 >> 12, l0 = m0 & 4095;
    if (blockIdx.x < 2) {
        #pragma unroll
        for (int i = 0; i < 2; i++) {
            int rowL = mb + 16 * i + g;
            #pragma unroll
            for (int j = 0; j < 4; j++) {
                int colL = nb + 8 * j + 2 * t;
                float b0 = dtb[n0 + colL], b1 = dtb[n0 + colL + 1];
                float t0 = acc[i][j][0] + b0, t1 = acc[i][j][1] + b1;
                float t2 = acc[i][j][2] + b0, t3 = acc[i][j][3] + b1;
                acc[i][j][0] = (t0 > 20.f) ? t0 : log1pf(__expf(t0));
                acc[i][j][1] = (t1 > 20.f) ? t1 : log1pf(__expf(t1));
                acc[i][j][2] = (t2 > 20.f) ? t2 : log1pf(__expf(t2));
                acc[i][j][3] = (t3 > 20.f) ? t3 : log1pf(__expf(t3));
                smT[colL * 132 + rowL]           = acc[i][j][0];
                smT[(colL + 1) * 132 + rowL]     = acc[i][j][1];
                smT[colL * 132 + rowL + 8]       = acc[i][j][2];
                smT[(colL + 1) * 132 + rowL + 8] = acc[i][j][3];
            }
        }
        __syncthreads();
        #pragma unroll
        for (int k = 0; k < 8; k++) {
            int dL = warp * 8 + k;
            float4 v = *(float4*)&smT[dL * 132 + 4 * lane];
            *(float4*)(g_dtT + ((size_t)(n * 128 + n0 + dL)) * 4096 + l0 + 4 * lane) = v;
        }
        __syncthreads();
        #pragma unroll
        for (int i = 0; i < 2; i++) {
            int rowL = mb + 16 * i + g;
            #pragma unroll
            for (int j = 0; j < 4; j++) {
                int colL = nb + 8 * j + 2 * t;
                float2 u0 = *(const float2*)(g_xc + (size_t)(m0 + rowL) * 128 + n0 + colL);
                float2 u1 = *(const float2*)(g_xc + (size_t)(m0 + rowL + 8) * 128 + n0 + colL);
                smT[colL * 132 + rowL]           = acc[i][j][0] * u0.x;
                smT[(colL + 1) * 132 + rowL]     = acc[i][j][1] * u0.y;
                smT[colL * 132 + rowL + 8]       = acc[i][j][2] * u1.x;
                smT[(colL + 1) * 132 + rowL + 8] = acc[i][j][3] * u1.y;
            }
        }
        __syncthreads();
        #pragma unroll
        for (int k = 0; k < 8; k++) {
            int dL = warp * 8 + k;
            float4 v = *(float4*)&smT[dL * 132 + 4 * lane];
            *(float4*)(g_PT + ((size_t)(n * 128 + n0 + dL)) * 4096 + l0 + 4 * lane) = v;
        }
    } else {
        if (nb == 0) {
            #pragma unroll
            for (int i = 0; i < 2; i++) {
                int rowL = mb + 16 * i + g;
                #pragma unroll
                for (int j = 0; j < 4; j++) {
                    int colL = 8 * j + 2 * t;
                    smT[colL * 132 + rowL]           = acc[i][j][0];
                    smT[(colL + 1) * 132 + rowL]     = acc[i][j][1];
                    smT[colL * 132 + rowL + 8]       = acc[i][j][2];
                    smT[(colL + 1) * 132 + rowL + 8] = acc[i][j][3];
                }
            }
        }
        __syncthreads();
        #pragma unroll
        for (int k = 0; k < 4; k++) {
            int sRow = warp * 4 + k;
            float4 v = *(float4*)&smT[sRow * 132 + 4 * lane];
            if (sRow < 16)
                *(float4*)(g_BmT + ((size_t)(n * 16 + sRow)) * 4096 + l0 + 4 * lane) = v;
            else
                *(float4*)(g_CmT + ((size_t)(n * 16 + sRow - 16)) * 4096 + l0 + 4 * lane) = v;
        }
    }
}

// ---------------- kernel 5a: chunk-local scan ----------------
__global__ void k_scanA(const float* __restrict__ Alog) {
    int c = blockIdx.x, n = blockIdx.y, d = threadIdx.x;
    __shared__ float sBt[16 * 64];
    #pragma unroll
    for (int k = 0; k < 2; k++) {
        int f = threadIdx.x + k * 128, s = f >> 4, tq = f & 15;
        *(float4*)&sBt[s * 64 + 4 * tq] =
            __ldg((const float4*)(g_BmT + ((size_t)(n * 16 + s)) * 4096 + c * 64 + 4 * tq));
    }
    __syncthreads();
    float a[16], h[16];
    #pragma unroll
    for (int s = 0; s < 16; s++) { a[s] = -__expf(__ldg(Alog + d * 16 + s)); h[s] = 0.f; }
    float sd = 0.f;
    const float4* dt4 = (const float4*)(g_dtT + ((size_t)(n * 128 + d)) * 4096 + c * 64);
    const float4* P4  = (const float4*)(g_PT  + ((size_t)(n * 128 + d)) * 4096 + c * 64);
    for (int q = 0; q < 16; q++) {
        float4 dtv = __ldg(dt4 + q), Pv = __ldg(P4 + q);
        float dts[4] = {dtv.x, dtv.y, dtv.z, dtv.w};
        float Ps[4]  = {Pv.x,  Pv.y,  Pv.z,  Pv.w};
        #pragma unroll
        for (int e = 0; e < 4; e++) {
            float dt = dts[e], P = Ps[e];
            sd += dt;
            const float* Bp = &sBt[4 * q + e];
            #pragma unroll
            for (int s = 0; s < 16; s++)
                h[s] = __expf(dt * a[s]) * h[s] + P * Bp[s * 64];
        }
    }
    float* oA = g_Ac + (((size_t)(n * 128 + d)) * 64 + c) * 16;
    float* oB = g_bc + (((size_t)(n * 128 + d)) * 64 + c) * 16;
    #pragma unroll
    for (int q = 0; q < 4; q++) {
        *(float4*)(oA + 4 * q) = make_float4(__expf(a[4*q] * sd), __expf(a[4*q+1] * sd),
                                             __expf(a[4*q+2] * sd), __expf(a[4*q+3] * sd));
        *(float4*)(oB + 4 * q) = make_float4(h[4*q], h[4*q+1], h[4*q+2], h[4*q+3]);
    }
}

// ---------------- kernel 5b: combine chunk summaries ----------------
__global__ void k_scanB() {
    int tid = blockIdx.x * blockDim.x + threadIdx.x;
    int n = tid >> 11, rem = tid & 2047;
    int d = rem >> 4, s = rem & 15;
    size_t base = ((size_t)(n * 128 + d)) * NCH * DS + s;
    float h = 0.f;
    float A0 = __ldg(g_Ac + base), b0 = __ldg(g_bc + base);
    #pragma unroll 8
    for (int c = 0; c < NCH; c++) {
        float A1 = 0.f, b1 = 0.f;
        if (c + 1 < NCH) {
            A1 = __ldg(g_Ac + base + (c + 1) * DS);
            b1 = __ldg(g_bc + base + (c + 1) * DS);
        }
        g_hin[base + c * DS] = h;
        h = A0 * h + b0;
        A0 = A1; b0 = b1;
    }
}

// ---------------- kernel 5c: replay with h_in, emit y^T ----------------
__global__ void k_scanC(const float* __restrict__ Alog) {
    int c = blockIdx.x, n = blockIdx.y, d = threadIdx.x;
    __shared__ float sBt[16 * 64];
    __shared__ float sCt[16 * 64];
    #pragma unroll
    for (int k = 0; k < 2; k++) {
        int f = threadIdx.x + k * 128, s = f >> 4, tq = f & 15;
        *(float4*)&sBt[s * 64 + 4 * tq] =
            __ldg((const float4*)(g_BmT + ((size_t)(n * 16 + s)) * 4096 + c * 64 + 4 * tq));
        *(float4*)&sCt[s * 64 + 4 * tq] =
            __ldg((const float4*)(g_CmT + ((size_t)(n * 16 + s)) * 4096 + c * 64 + 4 * tq));
    }
    __syncthreads();
    float a[16], h[16];
    #pragma unroll
    for (int s = 0; s < 16; s++) a[s] = -__expf(__ldg(Alog + d * 16 + s));
    const float* hi = g_hin + (((size_t)(n * 128 + d)) * 64 + c) * 16;
    #pragma unroll
    for (int q = 0; q < 4; q++) {
        float4 v = __ldg((const float4*)(hi + 4 * q));
        h[4*q] = v.x; h[4*q+1] = v.y; h[4*q+2] = v.z; h[4*q+3] = v.w;
    }
    const float4* dt4 = (const float4*)(g_dtT + ((size_t)(n * 128 + d)) * 4096 + c * 64);
    const float4* P4  = (const float4*)(g_PT  + ((size_t)(n * 128 + d)) * 4096 + c * 64);
    float4* yp = (float4*)(g_ysT + ((size_t)(n * 128 + d)) * 4096 + c * 64);
    for (int q = 0; q < 16; q++) {
        float4 dtv = __ldg(dt4 + q), Pv = __ldg(P4 + q);
        float dts[4] = {dtv.x, dtv.y, dtv.z, dtv.w};
        float Ps[4]  = {Pv.x,  Pv.y,  Pv.z,  Pv.w};
        float yv[4];
        #pragma unroll
        for (int e = 0; e < 4; e++) {
            float dt = dts[e], P = Ps[e];
            const float* Bp = &sBt[4 * q + e];
            const float* Cp = &sCt[4 * q + e];
            float y = 0.f;
            #pragma unroll
            for (int s = 0; s < 16; s++) {
                h[s] = __expf(dt * a[s]) * h[s] + P * Bp[s * 64];
                y += h[s] * Cp[s * 64];
            }
            yv[e] = y;
        }
        yp[q] = make_float4(yv[0], yv[1], yv[2], yv[3]);
    }
}

// ---------------- kernel 6: gate + out_proj + residual ----------------
__global__ void __launch_bounds__(256, 3) k_outproj(const float* __restrict__ Dp, const float* __restrict__ skip) {
    __shared__ uint2 sA[128 * SPADA];
    __shared__ uint2 sB[64 * SPADA];
    int tid = threadIdx.x;
    int m0 = blockIdx.x * 128;
    int nn = m0 >> 12, l0 = m0 & 4095;
    int warp = tid >> 5, lane = tid & 31, g = lane >> 2, t = lane & 3;
    int mb = (warp & 3) * 32, nb = (warp >> 2) * 32;
    float acc[2][4][4] = {};
    #pragma unroll
    for (int sl = 0; sl < 4; sl++) {
        int k0 = sl * 32;
        #pragma unroll
        for (int it = 0; it < 4; it++) {
            int idx = tid + it * 256;
            int row = idx >> 3, c4 = (idx & 7) * 4;
            size_t off = (size_t)(m0 + row) * 128 + k0 + c4;
            float ys0 = __ldg(g_ysT + ((size_t)(nn * 128 + k0 + c4 + 0)) * 4096 + l0 + row);
            float ys1 = __ldg(g_ysT + ((size_t)(nn * 128 + k0 + c4 + 1)) * 4096 + l0 + row);
            float ys2 = __ldg(g_ysT + ((size_t)(nn * 128 + k0 + c4 + 2)) * 4096 + l0 + row);
            float ys3 = __ldg(g_ysT + ((size_t)(nn * 128 + k0 + c4 + 3)) * 4096 + l0 + row);
            float4 xc = *(const float4*)(g_xc + off);
            float4 zz = *(const float4*)(g_z + off);
            float4 dp = *(const float4*)(Dp + k0 + c4);
            float a0 = (ys0 + xc.x * dp.x) * (zz.x / (1.f + __expf(-zz.x)));
            float a1 = (ys1 + xc.y * dp.y) * (zz.y / (1.f + __expf(-zz.y)));
            float a2 = (ys2 + xc.z * dp.z) * (zz.z / (1.f + __expf(-zz.z)));
            float a3 = (ys3 + xc.w * dp.w) * (zz.w / (1.f + __expf(-zz.w)));
            unsigned h0, lo0, h1, lo1;
            split2(a0, a1, h0, lo0); split2(a2, a3, h1, lo1);
            *(uint4*)(sA + row * SPADA + (c4 >> 1)) = make_uint4(h0, lo0, h1, lo1);
        }
        {
            int row = tid >> 2, q = (tid & 3) * 4;
            const uint2* src = g_wo_i + (size_t)row * 64 + sl * 16 + q;
            uint4 v0 = *(const uint4*)src;
            uint4 v1 = *(const uint4*)(src + 2);
            *(uint4*)(sB + row * SPADA + q)     = v0;
            *(uint4*)(sB + row * SPADA + q + 2) = v1;
        }
        __syncthreads();
        mma_slab(sA, sB, acc, mb, nb, g, t);
        __syncthreads();
    }
    float sk = skip[0];
    #pragma unroll
    for (int i = 0; i < 2; i++) {
        int row = m0 + mb + 16 * i + g;
        #pragma unroll
        for (int j = 0; j < 4; j++) {
            int col = nb + 8 * j + 2 * t;
            float2 xa = rec2(g_xn_i[(size_t)row * 32 + (col >> 1)]);
            float2 xb = rec2(g_xn_i[(size_t)(row + 8) * 32 + (col >> 1)]);
            *(float2*)(g_ym + (size_t)row * 64 + col) =
                make_float2(acc[i][j][0] + sk * xa.x, acc[i][j][1] + sk * xa.y);
            *(float2*)(g_ym + (size_t)(row + 8) * 64 + col) =
                make_float2(acc[i][j][2] + sk * xb.x, acc[i][j][3] + sk * xb.y);
        }
    }
}

// ---------------- kernel 7: LN2 + chunk gather ----------------
__global__ void k_ln2(const float* __restrict__ g, const float* __restrict__ bta) {
    int warp = (blockIdx.x * blockDim.x + threadIdx.x) >> 5;
    int lane = threadIdx.x & 31;
    int bb = warp >> 12, l = warp & 4095;
    int c0 = lane * 8;
    int chunk = lane >> 3;
    const float4* src = (const float4*)(g_ym + ((size_t)((chunk * 8 + bb) * Ltot + l)) * 64 + (c0 & 63));
    float4 v0 = src[0], v1 = src[1];
    float s = v0.x + v0.y + v0.z + v0.w + v1.x + v1.y + v1.z + v1.w;
    float s2 = v0.x*v0.x + v0.y*v0.y + v0.z*v0.z + v0.w*v0.w
             + v1.x*v1.x + v1.y*v1.y + v1.z*v1.z + v1.w*v1.w;
    #pragma unroll
    for (int o = 16; o; o >>= 1) {
        s  += __shfl_xor_sync(0xffffffffu, s, o);
        s2 += __shfl_xor_sync(0xffffffffu, s2, o);
    }
    float mu = s * (1.f / 256.f);
    float var = s2 * (1.f / 256.f) - mu * mu;
    float rs = rsqrtf(var + 1e-5f);
    float y[8] = {v0.x, v0.y, v0.z, v0.w, v1.x, v1.y, v1.z, v1.w};
    #pragma unroll
    for (int k = 0; k < 8; k++) y[k] = (y[k] - mu) * rs * g[c0 + k] + bta[c0 + k];
    unsigned h[4], lo[4];
    split2(y[0], y[1], h[0], lo[0]); split2(y[2], y[3], h[1], lo[1]);
    split2(y[4], y[5], h[2], lo[2]); split2(y[6], y[7], h[3], lo[3]);
    size_t base = ((size_t)(bb * Ltot + l)) * 128 + lane * 4;
    *(uint4*)(g_x2_i + base)     = make_uint4(h[0], lo[0], h[1], lo[1]);
    *(uint4*)(g_x2_i + base + 2) = make_uint4(h[2], lo[2], h[3], lo[3]);
}

// ---------------- kernel 8: final proj (grid=(4,256)) ----------------
__global__ void __launch_bounds__(256, 3) k_final(const float* __restrict__ pb, float* __restrict__ out) {
    extern __shared__ __align__(16) char smem[];
    unsigned sb = (unsigned)__cvta_generic_to_shared(smem);
    int tid = threadIdx.x;
    int m0 = blockIdx.y * 128, n0 = blockIdx.x * 64;
    int warp = tid >> 5, lane = tid & 31, g = lane >> 2, t = lane & 3;
    int mb = (warp & 3) * 32, nb = (warp >> 2) * 32;
    float acc[2][4][4] = {};
    issueA(sb, g_x2_i, 128, m0, 0, tid);
    issueB(sb + ABUF_BYTES, g_wp_i, 128, n0, 0, 256, tid);
    CPCOMMIT();
    #pragma unroll
    for (int sl = 0; sl < 8; sl++) {
        unsigned buf = (sl & 1) * STAGE_BYTES;
        if (sl + 1 < 8) {
            unsigned nbuf = ((sl + 1) & 1) * STAGE_BYTES;
            issueA(sb + nbuf, g_x2_i, 128, m0, (sl + 1) * 16, tid);
            issueB(sb + nbuf + ABUF_BYTES, g_wp_i, 128, n0, (sl + 1) * 16, 256, tid);
            CPCOMMIT();
            CPWAIT(1);
        } else {
            CPWAIT(0);
        }
        __syncthreads();
        mma_slab((uint2*)(smem + buf), (uint2*)(smem + buf + ABUF_BYTES), acc, mb, nb, g, t);
        __syncthreads();
    }
    #pragma unroll
    for (int i = 0; i < 2; i++) {
        int row = m0 + mb + 16 * i + g;
        int bbat = row >> 12, l = row & 4095;
        int l2 = (row + 8) & 4095;
        #pragma unroll
        for (int j = 0; j < 4; j++) {
            int col = n0 + nb + 8 * j + 2 * t;
            out[(size_t)(bbat * 256 + col) * Ltot + l]      = acc[i][j][0] + pb[col];
            out[(size_t)(bbat * 256 + col + 1) * Ltot + l]  = acc[i][j][1] + pb[col + 1];
            out[(size_t)(bbat * 256 + col) * Ltot + l2]     = acc[i][j][2] + pb[col];
            out[(size_t)(bbat * 256 + col + 1) * Ltot + l2] = acc[i][j][3] + pb[col + 1];
        }
    }
}

// ---------------- launch ----------------
extern "C" void kernel_launch(void* const* d_in, const int* in_sizes, int n_in,
                              void* d_out, int out_size) {
    const float* x      = (const float*)d_in[0];
    const float* ln_g   = (const float*)d_in[1];
    const float* ln_b   = (const float*)d_in[2];
    const float* inpw   = (const float*)d_in[3];
    const float* convw  = (const float*)d_in[4];
    const float* convb  = (const float*)d_in[5];
    const float* xpw    = (const float*)d_in[6];
    const float* dtw    = (const float*)d_in[7];
    const float* dtb    = (const float*)d_in[8];
    const float* Alog   = (const float*)d_in[9];
    const float* Dp     = (const float*)d_in[10];
    const float* outw   = (const float*)d_in[11];
    const float* projw  = (const float*)d_in[12];
    const float* projb  = (const float*)d_in[13];
    const float* skip   = (const float*)d_in[14];
    float* out = (float*)d_out;

    const int DBUF = 2 * STAGE_BYTES;   // 61440
    cudaFuncSetAttribute(k_inproj, cudaFuncAttributeMaxDynamicSharedMemorySize, DBUF);
    cudaFuncSetAttribute(k_xproj,  cudaFuncAttributeMaxDynamicSharedMemorySize, DBUF);
    cudaFuncSetAttribute(k_final,  cudaFuncAttributeMaxDynamicSharedMemorySize, DBUF);

    k_ln1<<<4096 + 16, 256>>>(x, ln_g, ln_b, dtw, xpw, inpw, outw, projw);   // (1)
    k_inproj<<<dim3(4, 1024), 256, DBUF>>>();                                 // (2)
    k_conv<<<4096, 256>>>(convw, convb);                                      // (3)
    k_xproj<<<dim3(3, 1024), 256, DBUF>>>(dtb);                               // (4) profiled
    k_scanA<<<dim3(NCH, Nseq), 128>>>(Alog);                                  // (5)
    k_scanB<<<256, 256>>>();                                                  // (6)
    k_scanC<<<dim3(NCH, Nseq), 128>>>(Alog);                                  // (7)
    k_outproj<<<1024, 256>>>(Dp, skip);                                       // (8)
    k_ln2<<<4096, 256>>>(ln_g, ln_b);                                         // (9)
    k_final<<<dim3(4, 256), 256, DBUF>>>(projb, out);                         // (10)
}